// round 2
// baseline (speedup 1.0000x reference)
#include <cuda_runtime.h>
#include <cuda_bf16.h>

namespace {
constexpr int Bn = 4, Tn = 2048, Cn = 1024, Hn = 16, Dn = 64;
constexpr int BM = 128, BN = 128, BK = 16;
}

// Scratch (device globals — no allocation allowed)
__device__ __align__(16) float g_q[Bn * Hn * Tn * Dn];   // [B,H,T,D], pre-scaled by D^-0.5
__device__ __align__(16) float g_k[Bn * Hn * Tn * Dn];
__device__ __align__(16) float g_v[Bn * Hn * Tn * Dn];
__device__ __align__(16) float g_ao[Bn * Tn * Cn];       // [B,T,C]

// ---------------------------------------------------------------------------
// Packed f32x2 helpers (sm_100+). ptxas never auto-fuses these from C++.
// ---------------------------------------------------------------------------
__device__ __forceinline__ unsigned long long pack2(float lo, float hi) {
    unsigned long long r;
    asm("mov.b64 %0, {%1, %2};" : "=l"(r) : "f"(lo), "f"(hi));
    return r;
}
__device__ __forceinline__ float2 unpack2(unsigned long long v) {
    float2 r;
    asm("mov.b64 {%0, %1}, %2;" : "=f"(r.x), "=f"(r.y) : "l"(v));
    return r;
}
__device__ __forceinline__ void ffma2(unsigned long long& d,
                                      unsigned long long a, unsigned long long b) {
    asm("fma.rn.f32x2 %0, %1, %2, %0;" : "+l"(d) : "l"(a), "l"(b));
}
__device__ __forceinline__ void fmul2(unsigned long long& d, unsigned long long a) {
    asm("mul.rn.f32x2 %0, %0, %1;" : "+l"(d) : "l"(a));
}

// ---------------------------------------------------------------------------
// NT GEMM: C[m,n] = sum_k A[m,k] * Bm[n,k].  BM=BN=128, BK=16, 256 threads,
// 8x8 microtile, double-buffered SMEM, f32x2 inner product.
// MODE 0: A=x, Bm=w_qkv -> scatter q/k/v [B,H,T,D], q scaled by D^-0.5.
// MODE 1: A=g_ao, Bm=w_out -> Cout = A*Bm^T + bias.
// ---------------------------------------------------------------------------
template <int MODE>
__global__ __launch_bounds__(256) void gemm_nt(
    const float* __restrict__ Ain, const float* __restrict__ Bm,
    const float* __restrict__ bias, float* __restrict__ Cout,
    int M, int N, int K)
{
    const float* A = (MODE == 1) ? (const float*)g_ao : Ain;
    __shared__ __align__(16) float As[2][BK][BM];
    __shared__ __align__(16) float Bs[2][BK][BN];

    const int tid = threadIdx.x;
    const int tx = tid & 15;              // n microtile (8 cols)
    const int ty = tid >> 4;              // m microtile (8 rows)
    const int m0 = blockIdx.y * BM;
    const int n0 = blockIdx.x * BN;

    // Global->shared mapping: thread loads 2 float4 (8 k-values) of one row.
    const int lr = tid >> 1;              // 0..127
    const int lk = (tid & 1) * 8;         // 0 or 8

    const float* aptr = A  + (size_t)(m0 + lr) * K + lk;
    const float* bptr = Bm + (size_t)(n0 + lr) * K + lk;

    unsigned long long acc[8][4];
#pragma unroll
    for (int i = 0; i < 8; i++)
#pragma unroll
        for (int j = 0; j < 4; j++) acc[i][j] = 0ull;

    // Prologue: tile 0 -> buffer 0
    {
        float4 a0 = *(const float4*)(aptr);
        float4 a1 = *(const float4*)(aptr + 4);
        float4 b0 = *(const float4*)(bptr);
        float4 b1 = *(const float4*)(bptr + 4);
        As[0][lk + 0][lr] = a0.x; As[0][lk + 1][lr] = a0.y;
        As[0][lk + 2][lr] = a0.z; As[0][lk + 3][lr] = a0.w;
        As[0][lk + 4][lr] = a1.x; As[0][lk + 5][lr] = a1.y;
        As[0][lk + 6][lr] = a1.z; As[0][lk + 7][lr] = a1.w;
        Bs[0][lk + 0][lr] = b0.x; Bs[0][lk + 1][lr] = b0.y;
        Bs[0][lk + 2][lr] = b0.z; Bs[0][lk + 3][lr] = b0.w;
        Bs[0][lk + 4][lr] = b1.x; Bs[0][lk + 5][lr] = b1.y;
        Bs[0][lk + 6][lr] = b1.z; Bs[0][lk + 7][lr] = b1.w;
    }
    __syncthreads();

    const int ntiles = K / BK;
    int buf = 0;
    for (int t = 0; t < ntiles; t++) {
        float4 a0, a1, b0, b1;
        const bool has_next = (t + 1 < ntiles);
        if (has_next) {
            const int k0 = (t + 1) * BK;
            a0 = *(const float4*)(aptr + k0);
            a1 = *(const float4*)(aptr + k0 + 4);
            b0 = *(const float4*)(bptr + k0);
            b1 = *(const float4*)(bptr + k0 + 4);
        }

#pragma unroll
        for (int k = 0; k < BK; k++) {
            const float4 av0 = *(const float4*)&As[buf][k][ty * 8];
            const float4 av1 = *(const float4*)&As[buf][k][ty * 8 + 4];
            const ulonglong2 bq0 = *(const ulonglong2*)&Bs[buf][k][tx * 8];
            const ulonglong2 bq1 = *(const ulonglong2*)&Bs[buf][k][tx * 8 + 4];
            unsigned long long bp[4] = {bq0.x, bq0.y, bq1.x, bq1.y};
            const float aa[8] = {av0.x, av0.y, av0.z, av0.w,
                                 av1.x, av1.y, av1.z, av1.w};
#pragma unroll
            for (int i = 0; i < 8; i++) {
                const unsigned long long ap = pack2(aa[i], aa[i]);
#pragma unroll
                for (int j = 0; j < 4; j++) ffma2(acc[i][j], ap, bp[j]);
            }
        }

        if (has_next) {
            const int nb = buf ^ 1;
            As[nb][lk + 0][lr] = a0.x; As[nb][lk + 1][lr] = a0.y;
            As[nb][lk + 2][lr] = a0.z; As[nb][lk + 3][lr] = a0.w;
            As[nb][lk + 4][lr] = a1.x; As[nb][lk + 5][lr] = a1.y;
            As[nb][lk + 6][lr] = a1.z; As[nb][lk + 7][lr] = a1.w;
            Bs[nb][lk + 0][lr] = b0.x; Bs[nb][lk + 1][lr] = b0.y;
            Bs[nb][lk + 2][lr] = b0.z; Bs[nb][lk + 3][lr] = b0.w;
            Bs[nb][lk + 4][lr] = b1.x; Bs[nb][lk + 5][lr] = b1.y;
            Bs[nb][lk + 6][lr] = b1.z; Bs[nb][lk + 7][lr] = b1.w;
        }
        __syncthreads();
        buf ^= 1;
    }

    // Unpack accumulators
    float c[8][8];
#pragma unroll
    for (int i = 0; i < 8; i++)
#pragma unroll
        for (int j = 0; j < 4; j++) {
            float2 f = unpack2(acc[i][j]);
            c[i][2 * j] = f.x; c[i][2 * j + 1] = f.y;
        }

    if (MODE == 0) {
        const int sec = n0 / Cn;                      // 0=q,1=k,2=v (128|1024)
        const int nloc = (n0 % Cn) + tx * 8;          // col within section
        const int h = nloc / Dn;
        const int d0 = nloc % Dn;                     // 8 cols stay in one head
        const float scale = (sec == 0) ? 0.125f : 1.0f;
        float* dst = (sec == 0) ? g_q : (sec == 1) ? g_k : g_v;
#pragma unroll
        for (int i = 0; i < 8; i++) {
            const int m = m0 + ty * 8 + i;
            const int b = m >> 11, tpos = m & 2047;
            float* row = dst + (size_t)((b * Hn + h) * Tn + tpos) * Dn + d0;
            float4 o0 = {c[i][0] * scale, c[i][1] * scale, c[i][2] * scale, c[i][3] * scale};
            float4 o1 = {c[i][4] * scale, c[i][5] * scale, c[i][6] * scale, c[i][7] * scale};
            *(float4*)(row) = o0;
            *(float4*)(row + 4) = o1;
        }
    } else {
        const int cb = n0 + tx * 8;
        const float4 bb0 = *(const float4*)(bias + cb);
        const float4 bb1 = *(const float4*)(bias + cb + 4);
#pragma unroll
        for (int i = 0; i < 8; i++) {
            const int m = m0 + ty * 8 + i;
            float* row = Cout + (size_t)m * N + cb;
            float4 o0 = {c[i][0] + bb0.x, c[i][1] + bb0.y, c[i][2] + bb0.z, c[i][3] + bb0.w};
            float4 o1 = {c[i][4] + bb1.x, c[i][5] + bb1.y, c[i][6] + bb1.z, c[i][7] + bb1.w};
            *(float4*)(row) = o0;
            *(float4*)(row + 4) = o1;
        }
    }
}

// ---------------------------------------------------------------------------
// Causal flash attention, fp32 with f32x2 math.
// Grid: (Tn/128, Bn*Hn). Block: 128 threads; thread t owns query row
// qi = blockIdx.x*128 + t. K/V tiles of 32 rows staged in SMEM.
// ---------------------------------------------------------------------------
__global__ __launch_bounds__(128) void attn_fwd()
{
    __shared__ __align__(16) float Ks[32 * 64];
    __shared__ __align__(16) float Vs[32 * 64];

    const int tid = threadIdx.x;
    const int bh = blockIdx.y;
    const float* qb = g_q + (size_t)bh * Tn * Dn;
    const float4* kb4 = (const float4*)(g_k + (size_t)bh * Tn * Dn);
    const float4* vb4 = (const float4*)(g_v + (size_t)bh * Tn * Dn);

    const int qi = blockIdx.x * 128 + tid;

    // q row as 32 packed pairs (loaded directly as 64-bit lanes)
    unsigned long long qp[32];
    {
        const ulonglong2* q2 = (const ulonglong2*)(qb + (size_t)qi * Dn);
#pragma unroll
        for (int c = 0; c < 16; c++) {
            ulonglong2 u = q2[c];
            qp[2 * c] = u.x; qp[2 * c + 1] = u.y;
        }
    }

    unsigned long long acc[32];
#pragma unroll
    for (int c = 0; c < 32; c++) acc[c] = 0ull;
    float mrun = -1e30f, lrun = 0.0f;

    const int nkt = blockIdx.x * 4 + 4;   // 32-key tiles covering [0, qtile_end)

    for (int kt = 0; kt < nkt; kt++) {
        const int k0 = kt * 32;
        __syncthreads();
#pragma unroll 4
        for (int i = tid; i < 512; i += 128) {
            ((float4*)Ks)[i] = kb4[k0 * 16 + i];
            ((float4*)Vs)[i] = vb4[k0 * 16 + i];
        }
        __syncthreads();

        float s[32];
        const ulonglong2* Ks2 = (const ulonglong2*)Ks;
#pragma unroll
        for (int r = 0; r < 32; r++) {
            unsigned long long sa = 0ull, sb = 0ull;
#pragma unroll
            for (int c = 0; c < 16; c += 2) {
                ulonglong2 k0v = Ks2[r * 16 + c];
                ulonglong2 k1v = Ks2[r * 16 + c + 1];
                ffma2(sa, qp[2 * c], k0v.x);
                ffma2(sb, qp[2 * c + 1], k0v.y);
                ffma2(sa, qp[2 * c + 2], k1v.x);
                ffma2(sb, qp[2 * c + 3], k1v.y);
            }
            float2 fa = unpack2(sa), fb = unpack2(sb);
            float sum = (fa.x + fa.y) + (fb.x + fb.y);
            s[r] = (k0 + r <= qi) ? sum : -1e30f;
        }

        float tm = -1e30f;
#pragma unroll
        for (int r = 0; r < 32; r++) tm = fmaxf(tm, s[r]);
        const float newm = fmaxf(mrun, tm);
        const float corr = __expf(mrun - newm);
        lrun *= corr;
        const unsigned long long cp = pack2(corr, corr);
#pragma unroll
        for (int c = 0; c < 32; c++) fmul2(acc[c], cp);

        const ulonglong2* Vs2 = (const ulonglong2*)Vs;
#pragma unroll
        for (int r = 0; r < 32; r++) {
            const float p = __expf(s[r] - newm);
            lrun += p;
            const unsigned long long pp = pack2(p, p);
#pragma unroll
            for (int c = 0; c < 16; c++) {
                ulonglong2 vv = Vs2[r * 16 + c];
                ffma2(acc[2 * c], pp, vv.x);
                ffma2(acc[2 * c + 1], pp, vv.y);
            }
        }
        mrun = newm;
    }

    const float inv = 1.0f / lrun;
    const int b = bh >> 4, h = bh & 15;
    float* dst = g_ao + (size_t)(b * Tn + qi) * Cn + h * Dn;
#pragma unroll
    for (int c = 0; c < 16; c++) {
        float2 f0 = unpack2(acc[2 * c]);
        float2 f1 = unpack2(acc[2 * c + 1]);
        float4 o = {f0.x * inv, f0.y * inv, f1.x * inv, f1.y * inv};
        *(float4*)(dst + 4 * c) = o;
    }
}

// ---------------------------------------------------------------------------
// Launch: inputs: x, w_qkv, w_out, b_out. Output fp32 [4,2048,1024].
// ---------------------------------------------------------------------------
extern "C" void kernel_launch(void* const* d_in, const int* in_sizes, int n_in,
                              void* d_out, int out_size)
{
    const float* x     = (const float*)d_in[0];
    const float* w_qkv = (const float*)d_in[1];
    const float* w_out = (const float*)d_in[2];
    const float* b_out = (const float*)d_in[3];
    float* out = (float*)d_out;

    const int M = Bn * Tn;   // 8192

    gemm_nt<0><<<dim3((3 * Cn) / BN, M / BM), 256>>>(x, w_qkv, nullptr, nullptr,
                                                     M, 3 * Cn, Cn);
    attn_fwd<<<dim3(Tn / 128, Bn * Hn), 128>>>();
    gemm_nt<1><<<dim3(Cn / BN, M / BM), 256>>>(nullptr, w_out, b_out, out,
                                               M, Cn, Cn);
}

// round 4
// speedup vs baseline: 1.5861x; 1.5861x over previous
#include <cuda_runtime.h>
#include <cuda_bf16.h>

namespace {
constexpr int Bn = 4, Tn = 2048, Cn = 1024, Hn = 16, Dn = 64;
constexpr int Kp = 3072;     // split-K concat: A=[h|l|h], B=[h|h|l]
constexpr int LDS = 40;      // padded SMEM row stride (elements): 80B, conflict-free
}

// ---------------- scratch (device globals; no allocs allowed) ----------------
__device__ __align__(16) __nv_bfloat16 g_A[(size_t)Bn * Tn * Kp];   // 48 MB
__device__ __align__(16) __nv_bfloat16 g_B1[(size_t)3 * Cn * Kp];   // 18 MB
__device__ __align__(16) __nv_bfloat16 g_B3[(size_t)Cn * Kp];       //  6 MB
__device__ __align__(16) float g_q[(size_t)Bn * Hn * Tn * Dn];      // pre-scaled by D^-0.5
__device__ __align__(16) float g_k[(size_t)Bn * Hn * Tn * Dn];
__device__ __align__(16) float g_v[(size_t)Bn * Hn * Tn * Dn];
__device__ __align__(16) float g_ao[(size_t)Bn * Tn * Cn];

// ---------------- warp MMA helpers (arch-portable, sm_80+) ----------------
__device__ __forceinline__ unsigned smem_u32(const void* p) {
    unsigned a;
    asm("{ .reg .u64 t; cvta.to.shared.u64 t, %1; cvt.u32.u64 %0, t; }" : "=r"(a) : "l"(p));
    return a;
}
__device__ __forceinline__ void ldsm4(unsigned* r, unsigned addr) {
    asm volatile("ldmatrix.sync.aligned.m8n8.x4.shared.b16 {%0,%1,%2,%3}, [%4];"
        : "=r"(r[0]), "=r"(r[1]), "=r"(r[2]), "=r"(r[3]) : "r"(addr));
}
__device__ __forceinline__ void mma16816(float* c, const unsigned* a, const unsigned* b) {
    asm volatile("mma.sync.aligned.m16n8k16.row.col.f32.bf16.bf16.f32 "
        "{%0,%1,%2,%3}, {%4,%5,%6,%7}, {%8,%9}, {%0,%1,%2,%3};"
        : "+f"(c[0]), "+f"(c[1]), "+f"(c[2]), "+f"(c[3])
        : "r"(a[0]), "r"(a[1]), "r"(a[2]), "r"(a[3]), "r"(b[0]), "r"(b[1]));
}

// ---------------- fp32 -> split-bf16 converters ----------------
// mode 0: x->g_A (h,l,h)  1: w_qkv->g_B1 (h,h,l)  2: g_ao->g_A (h,l,h)  3: w_out->g_B3 (h,h,l)
__global__ __launch_bounds__(256) void split_k(const float* __restrict__ srcIn, int mode)
{
    const float* src = (mode == 2) ? (const float*)g_ao : srcIn;
    __nv_bfloat16* dst = (mode == 0 || mode == 2) ? g_A : (mode == 1) ? g_B1 : g_B3;
    const bool apat = (mode == 0 || mode == 2);
    const size_t idx = (size_t)blockIdx.x * 256 + threadIdx.x;
    const size_t row = idx >> 10;
    const int k = (int)(idx & 1023);
    const float v = src[idx];
    const __nv_bfloat16 h = __float2bfloat16(v);
    const __nv_bfloat16 l = __float2bfloat16(v - __bfloat162float(h));
    const size_t base = row * Kp;
    dst[base + k] = h;
    dst[base + 1024 + k] = apat ? l : h;
    dst[base + 2048 + k] = apat ? h : l;
}

// ---------------- HMMA GEMM: C[m,n] = sum_k A[m,k] * B[n,k] ----------------
// 128x128 CTA tile, 8 warps (warp tile 32x64), BK=32, double-buffered SMEM.
// MODE 0: B=g_B1 -> scatter q/k/v [B,H,T,D] (q scaled 0.125). MODE 1: B=g_B3 -> out+bias.
template <int MODE>
__global__ __launch_bounds__(256) void gemm_mma(
    const float* __restrict__ bias, float* __restrict__ out)
{
    const __nv_bfloat16* __restrict__ A = g_A;
    const __nv_bfloat16* __restrict__ Bw = (MODE == 0) ? g_B1 : g_B3;

    __shared__ __align__(16) __nv_bfloat16 sA[2][128 * LDS];
    __shared__ __align__(16) __nv_bfloat16 sB[2][128 * LDS];

    const int tid = threadIdx.x, lane = tid & 31, wid = tid >> 5;
    const int wm = wid & 3, wn = wid >> 2;          // warp grid 4(m) x 2(n)
    const int m0 = blockIdx.y * 128, n0 = blockIdx.x * 128;

    // global->smem: thread loads 16 bf16 (32B) of one row per stage
    const int grow = tid >> 1;                      // 0..127
    const int gcol = (tid & 1) * 16;                // 0 or 16
    const __nv_bfloat16* ag = A  + (size_t)(m0 + grow) * Kp + gcol;
    const __nv_bfloat16* bg = Bw + (size_t)(n0 + grow) * Kp + gcol;

    // ldmatrix base addresses (per-thread row within warp tile)
    const unsigned sAu = smem_u32(sA), sBu = smem_u32(sB);
    const unsigned a_base = sAu + ((wm * 32 + (lane & 15)) * LDS + (lane >> 4) * 8) * 2;
    const unsigned b_base = sBu + ((wn * 64 + (lane & 7) + ((lane >> 4) << 3)) * LDS
                                   + ((lane >> 3) & 1) * 8) * 2;
    constexpr unsigned STG = 128 * LDS * 2;         // stage stride (bytes)

    float acc[2][8][4];
#pragma unroll
    for (int i = 0; i < 2; i++)
#pragma unroll
        for (int j = 0; j < 8; j++)
#pragma unroll
            for (int q = 0; q < 4; q++) acc[i][j][q] = 0.0f;

    // prologue: stage 0
    {
        uint4 a0 = *(const uint4*)ag,        a1 = *(const uint4*)(ag + 8);
        uint4 b0 = *(const uint4*)bg,        b1 = *(const uint4*)(bg + 8);
        uint4* pa = (uint4*)&sA[0][grow * LDS + gcol];
        uint4* pb = (uint4*)&sB[0][grow * LDS + gcol];
        pa[0] = a0; pa[1] = a1; pb[0] = b0; pb[1] = b1;
    }
    __syncthreads();

    const int nst = Kp / 32;                        // 96
    for (int st = 0; st < nst; st++) {
        const int cur = st & 1;
        const bool has_next = (st + 1 < nst);
        uint4 a0, a1, b0, b1;
        if (has_next) {
            const int kc = (st + 1) * 32;
            a0 = *(const uint4*)(ag + kc); a1 = *(const uint4*)(ag + kc + 8);
            b0 = *(const uint4*)(bg + kc); b1 = *(const uint4*)(bg + kc + 8);
        }

#pragma unroll
        for (int ks = 0; ks < 2; ks++) {            // two k16 steps
            unsigned afr[2][4], bfr[4][4];
#pragma unroll
            for (int mi = 0; mi < 2; mi++)
                ldsm4(afr[mi], a_base + cur * STG + mi * 16 * LDS * 2 + ks * 32);
#pragma unroll
            for (int nb = 0; nb < 4; nb++)
                ldsm4(bfr[nb], b_base + cur * STG + nb * 16 * LDS * 2 + ks * 32);
#pragma unroll
            for (int mi = 0; mi < 2; mi++)
#pragma unroll
                for (int nb = 0; nb < 4; nb++) {
                    mma16816(acc[mi][2 * nb],     afr[mi], &bfr[nb][0]);
                    mma16816(acc[mi][2 * nb + 1], afr[mi], &bfr[nb][2]);
                }
        }

        if (has_next) {
            const int nxt = cur ^ 1;
            uint4* pa = (uint4*)&sA[nxt][grow * LDS + gcol];
            uint4* pb = (uint4*)&sB[nxt][grow * LDS + gcol];
            pa[0] = a0; pa[1] = a1; pb[0] = b0; pb[1] = b1;
        }
        __syncthreads();
    }

    // epilogue
    const int g = lane >> 2, tig = lane & 3;
    if (MODE == 0) {
        const int nblock = n0 + wn * 64;            // 64-aligned -> single head
        const int sec = nblock >> 10;
        const int h = (nblock & 1023) >> 6;
        const float scale = (sec == 0) ? 0.125f : 1.0f;
        float* dstb = (sec == 0) ? g_q : (sec == 1) ? g_k : g_v;
#pragma unroll
        for (int mi = 0; mi < 2; mi++) {
            const int m1 = m0 + wm * 32 + mi * 16 + g;
            const int b = m1 >> 11, t = m1 & 2047;
            float* rbase = dstb + (size_t)((b * Hn + h) * Tn + t) * Dn;
#pragma unroll
            for (int ni = 0; ni < 8; ni++) {
                const int d = ni * 8 + 2 * tig;
                float2 lo = {acc[mi][ni][0] * scale, acc[mi][ni][1] * scale};
                float2 hi = {acc[mi][ni][2] * scale, acc[mi][ni][3] * scale};
                *(float2*)(rbase + d) = lo;
                *(float2*)(rbase + 8 * (size_t)Dn + d) = hi;   // row m1+8
            }
        }
    } else {
#pragma unroll
        for (int mi = 0; mi < 2; mi++) {
            const int m1 = m0 + wm * 32 + mi * 16 + g;
#pragma unroll
            for (int ni = 0; ni < 8; ni++) {
                const int n = n0 + wn * 64 + ni * 8 + 2 * tig;
                const float2 bb = *(const float2*)(bias + n);
                float2 lo = {acc[mi][ni][0] + bb.x, acc[mi][ni][1] + bb.y};
                float2 hi = {acc[mi][ni][2] + bb.x, acc[mi][ni][3] + bb.y};
                *(float2*)(out + (size_t)m1 * Cn + n) = lo;
                *(float2*)(out + (size_t)(m1 + 8) * Cn + n) = hi;
            }
        }
    }
}

// ---------------- causal flash attention (fp32, proven Round-1 kernel) ------
__global__ __launch_bounds__(64) void attn_fwd()
{
    __shared__ float4 Ks[32 * 16];
    __shared__ float4 Vs[32 * 16];

    const int tid = threadIdx.x;
    const int bh = blockIdx.y;
    const float4* qb = (const float4*)(g_q + (size_t)bh * Tn * Dn);
    const float4* kb = (const float4*)(g_k + (size_t)bh * Tn * Dn);
    const float4* vb = (const float4*)(g_v + (size_t)bh * Tn * Dn);

    const int qi = blockIdx.x * 64 + tid;

    float4 qr[16];
#pragma unroll
    for (int c = 0; c < 16; c++) qr[c] = qb[qi * 16 + c];

    float4 acc[16] = {};
    float mrun = -1e30f, lrun = 0.0f;

    const int nkt = blockIdx.x * 2 + 2;

    for (int kt = 0; kt < nkt; kt++) {
        const int k0 = kt * 32;
        __syncthreads();
#pragma unroll 4
        for (int i = tid; i < 512; i += 64) {
            Ks[i] = kb[k0 * 16 + i];
            Vs[i] = vb[k0 * 16 + i];
        }
        __syncthreads();

        float s[32];
#pragma unroll
        for (int r = 0; r < 32; r++) {
            float sum = 0.0f;
#pragma unroll
            for (int c = 0; c < 16; c++) {
                float4 kk = Ks[r * 16 + c];
                sum = fmaf(qr[c].x, kk.x, sum);
                sum = fmaf(qr[c].y, kk.y, sum);
                sum = fmaf(qr[c].z, kk.z, sum);
                sum = fmaf(qr[c].w, kk.w, sum);
            }
            s[r] = (k0 + r <= qi) ? sum : -1e30f;
        }

        float tm = -1e30f;
#pragma unroll
        for (int r = 0; r < 32; r++) tm = fmaxf(tm, s[r]);
        const float newm = fmaxf(mrun, tm);
        const float corr = __expf(mrun - newm);
        lrun *= corr;
#pragma unroll
        for (int c = 0; c < 16; c++) {
            acc[c].x *= corr; acc[c].y *= corr;
            acc[c].z *= corr; acc[c].w *= corr;
        }
#pragma unroll
        for (int r = 0; r < 32; r++) {
            const float p = __expf(s[r] - newm);
            lrun += p;
#pragma unroll
            for (int c = 0; c < 16; c++) {
                float4 vv = Vs[r * 16 + c];
                acc[c].x = fmaf(p, vv.x, acc[c].x);
                acc[c].y = fmaf(p, vv.y, acc[c].y);
                acc[c].z = fmaf(p, vv.z, acc[c].z);
                acc[c].w = fmaf(p, vv.w, acc[c].w);
            }
        }
        mrun = newm;
    }

    const float inv = 1.0f / lrun;
    const int b = bh >> 4, h = bh & 15;
    float4* dst = (float4*)(g_ao + (size_t)(b * Tn + qi) * Cn + h * Dn);
#pragma unroll
    for (int c = 0; c < 16; c++) {
        float4 o;
        o.x = acc[c].x * inv; o.y = acc[c].y * inv;
        o.z = acc[c].z * inv; o.w = acc[c].w * inv;
        dst[c] = o;
    }
}

// ---------------- launch ----------------
extern "C" void kernel_launch(void* const* d_in, const int* in_sizes, int n_in,
                              void* d_out, int out_size)
{
    const float* x     = (const float*)d_in[0];  // [4,2048,1024]
    const float* w_qkv = (const float*)d_in[1];  // [3072,1024]
    const float* w_out = (const float*)d_in[2];  // [1024,1024]
    const float* b_out = (const float*)d_in[3];  // [1024]
    float* out = (float*)d_out;

    const int M = Bn * Tn;                               // 8192
    split_k<<<(M * Cn) / 256, 256>>>(x, 0);              // x -> g_A
    split_k<<<(3 * Cn * Cn) / 256, 256>>>(w_qkv, 1);     // w_qkv -> g_B1
    gemm_mma<0><<<dim3(3 * Cn / 128, M / 128), 256>>>(nullptr, nullptr);
    attn_fwd<<<dim3(Tn / 64, Bn * Hn), 64>>>();
    split_k<<<(M * Cn) / 256, 256>>>(nullptr, 2);        // g_ao -> g_A
    split_k<<<(Cn * Cn) / 256, 256>>>(w_out, 3);         // w_out -> g_B3
    gemm_mma<1><<<dim3(Cn / 128, M / 128), 256>>>(b_out, out);
}

// round 5
// speedup vs baseline: 3.1543x; 1.9887x over previous
#include <cuda_runtime.h>
#include <cuda_bf16.h>

namespace {
constexpr int Bn = 4, Tn = 2048, Cn = 1024, Hn = 16, Dn = 64;
constexpr int Kp = 3072;     // split-K concat: A=[h|l|h], B=[h|h|l]
constexpr int LDS = 40;      // GEMM smem row stride (elems)
constexpr int SD = 72;       // attention smem row stride (elems), 144B: conflict-free
constexpr unsigned ATTN_SMEM = 6 * 64 * SD * 2;   // 55296 B
}

// ---------------- scratch (device globals; no allocs allowed) ----------------
__device__ __align__(16) __nv_bfloat16 g_A[(size_t)Bn * Tn * Kp];
__device__ __align__(16) __nv_bfloat16 g_B1[(size_t)3 * Cn * Kp];
__device__ __align__(16) __nv_bfloat16 g_B3[(size_t)Cn * Kp];
__device__ __align__(16) float g_q[(size_t)Bn * Hn * Tn * Dn];   // pre-scaled D^-0.5
__device__ __align__(16) float g_k[(size_t)Bn * Hn * Tn * Dn];
__device__ __align__(16) float g_v[(size_t)Bn * Hn * Tn * Dn];
__device__ __align__(16) float g_ao[(size_t)Bn * Tn * Cn];

// ---------------- helpers ----------------
__device__ __forceinline__ unsigned smem_u32(const void* p) {
    unsigned a;
    asm("{ .reg .u64 t; cvta.to.shared.u64 t, %1; cvt.u32.u64 %0, t; }" : "=r"(a) : "l"(p));
    return a;
}
__device__ __forceinline__ void ldsm4(unsigned* r, unsigned addr) {
    asm volatile("ldmatrix.sync.aligned.m8n8.x4.shared.b16 {%0,%1,%2,%3}, [%4];"
        : "=r"(r[0]), "=r"(r[1]), "=r"(r[2]), "=r"(r[3]) : "r"(addr));
}
__device__ __forceinline__ void ldsm4t(unsigned* r, unsigned addr) {
    asm volatile("ldmatrix.sync.aligned.m8n8.x4.trans.shared.b16 {%0,%1,%2,%3}, [%4];"
        : "=r"(r[0]), "=r"(r[1]), "=r"(r[2]), "=r"(r[3]) : "r"(addr));
}
__device__ __forceinline__ void mma16816(float* c, const unsigned* a, const unsigned* b) {
    asm volatile("mma.sync.aligned.m16n8k16.row.col.f32.bf16.bf16.f32 "
        "{%0,%1,%2,%3}, {%4,%5,%6,%7}, {%8,%9}, {%0,%1,%2,%3};"
        : "+f"(c[0]), "+f"(c[1]), "+f"(c[2]), "+f"(c[3])
        : "r"(a[0]), "r"(a[1]), "r"(a[2]), "r"(a[3]), "r"(b[0]), "r"(b[1]));
}
__device__ __forceinline__ unsigned packbf2(float lo, float hi) {
    unsigned u;
    asm("cvt.rn.bf16x2.f32 %0, %1, %2;" : "=r"(u) : "f"(hi), "f"(lo));
    return u;
}
// FFMA-only exp (args <= 0); avoids the MUFU throughput wall.
__device__ __forceinline__ float fexp(float x) {
    x = fmaxf(x, -80.0f);
    const float z = x * 1.4426950408889634f;
    const float zf = z + 12582912.0f;                 // RN -> integer in mantissa
    const int n = __float_as_int(zf);
    const float r = z - (zf - 12582912.0f);           // [-0.5, 0.5]
    float p = 0.009618129f;
    p = fmaf(p, r, 0.05550411f);
    p = fmaf(p, r, 0.2402265f);
    p = fmaf(p, r, 0.6931472f);
    p = fmaf(p, r, 1.0f);
    return p * __int_as_float((n << 23) + 0x3F800000);
}

// ---------------- fp32 -> split-bf16 converters ----------------
__global__ __launch_bounds__(256) void split_k(const float* __restrict__ srcIn, int mode)
{
    const float* src = (mode == 2) ? (const float*)g_ao : srcIn;
    __nv_bfloat16* dst = (mode == 0 || mode == 2) ? g_A : (mode == 1) ? g_B1 : g_B3;
    const bool apat = (mode == 0 || mode == 2);
    const size_t idx = (size_t)blockIdx.x * 256 + threadIdx.x;
    const size_t row = idx >> 10;
    const int k = (int)(idx & 1023);
    const float v = src[idx];
    const __nv_bfloat16 h = __float2bfloat16(v);
    const __nv_bfloat16 l = __float2bfloat16(v - __bfloat162float(h));
    const size_t base = row * Kp;
    dst[base + k] = h;
    dst[base + 1024 + k] = apat ? l : h;
    dst[base + 2048 + k] = apat ? h : l;
}

// ---------------- HMMA GEMM (unchanged from R4, validated) ----------------
template <int MODE>
__global__ __launch_bounds__(256) void gemm_mma(
    const float* __restrict__ bias, float* __restrict__ out)
{
    const __nv_bfloat16* __restrict__ A = g_A;
    const __nv_bfloat16* __restrict__ Bw = (MODE == 0) ? g_B1 : g_B3;

    __shared__ __align__(16) __nv_bfloat16 sA[2][128 * LDS];
    __shared__ __align__(16) __nv_bfloat16 sB[2][128 * LDS];

    const int tid = threadIdx.x, lane = tid & 31, wid = tid >> 5;
    const int wm = wid & 3, wn = wid >> 2;
    const int m0 = blockIdx.y * 128, n0 = blockIdx.x * 128;

    const int grow = tid >> 1;
    const int gcol = (tid & 1) * 16;
    const __nv_bfloat16* ag = A  + (size_t)(m0 + grow) * Kp + gcol;
    const __nv_bfloat16* bg = Bw + (size_t)(n0 + grow) * Kp + gcol;

    const unsigned sAu = smem_u32(sA), sBu = smem_u32(sB);
    const unsigned a_base = sAu + ((wm * 32 + (lane & 15)) * LDS + (lane >> 4) * 8) * 2;
    const unsigned b_base = sBu + ((wn * 64 + (lane & 7) + ((lane >> 4) << 3)) * LDS
                                   + ((lane >> 3) & 1) * 8) * 2;
    constexpr unsigned STG = 128 * LDS * 2;

    float acc[2][8][4];
#pragma unroll
    for (int i = 0; i < 2; i++)
#pragma unroll
        for (int j = 0; j < 8; j++)
#pragma unroll
            for (int q = 0; q < 4; q++) acc[i][j][q] = 0.0f;

    {
        uint4 a0 = *(const uint4*)ag, a1 = *(const uint4*)(ag + 8);
        uint4 b0 = *(const uint4*)bg, b1 = *(const uint4*)(bg + 8);
        uint4* pa = (uint4*)&sA[0][grow * LDS + gcol];
        uint4* pb = (uint4*)&sB[0][grow * LDS + gcol];
        pa[0] = a0; pa[1] = a1; pb[0] = b0; pb[1] = b1;
    }
    __syncthreads();

    const int nst = Kp / 32;
    for (int st = 0; st < nst; st++) {
        const int cur = st & 1;
        const bool has_next = (st + 1 < nst);
        uint4 a0, a1, b0, b1;
        if (has_next) {
            const int kc = (st + 1) * 32;
            a0 = *(const uint4*)(ag + kc); a1 = *(const uint4*)(ag + kc + 8);
            b0 = *(const uint4*)(bg + kc); b1 = *(const uint4*)(bg + kc + 8);
        }
#pragma unroll
        for (int ks = 0; ks < 2; ks++) {
            unsigned afr[2][4], bfr[4][4];
#pragma unroll
            for (int mi = 0; mi < 2; mi++)
                ldsm4(afr[mi], a_base + cur * STG + mi * 16 * LDS * 2 + ks * 32);
#pragma unroll
            for (int nb = 0; nb < 4; nb++)
                ldsm4(bfr[nb], b_base + cur * STG + nb * 16 * LDS * 2 + ks * 32);
#pragma unroll
            for (int mi = 0; mi < 2; mi++)
#pragma unroll
                for (int nb = 0; nb < 4; nb++) {
                    mma16816(acc[mi][2 * nb],     afr[mi], &bfr[nb][0]);
                    mma16816(acc[mi][2 * nb + 1], afr[mi], &bfr[nb][2]);
                }
        }
        if (has_next) {
            const int nxt = cur ^ 1;
            uint4* pa = (uint4*)&sA[nxt][grow * LDS + gcol];
            uint4* pb = (uint4*)&sB[nxt][grow * LDS + gcol];
            pa[0] = a0; pa[1] = a1; pb[0] = b0; pb[1] = b1;
        }
        __syncthreads();
    }

    const int g = lane >> 2, tig = lane & 3;
    if (MODE == 0) {
        const int nblock = n0 + wn * 64;
        const int sec = nblock >> 10;
        const int h = (nblock & 1023) >> 6;
        const float scale = (sec == 0) ? 0.125f : 1.0f;
        float* dstb = (sec == 0) ? g_q : (sec == 1) ? g_k : g_v;
#pragma unroll
        for (int mi = 0; mi < 2; mi++) {
            const int m1 = m0 + wm * 32 + mi * 16 + g;
            const int b = m1 >> 11, t = m1 & 2047;
            float* rbase = dstb + (size_t)((b * Hn + h) * Tn + t) * Dn;
#pragma unroll
            for (int ni = 0; ni < 8; ni++) {
                const int d = ni * 8 + 2 * tig;
                float2 lo = {acc[mi][ni][0] * scale, acc[mi][ni][1] * scale};
                float2 hi = {acc[mi][ni][2] * scale, acc[mi][ni][3] * scale};
                *(float2*)(rbase + d) = lo;
                *(float2*)(rbase + 8 * (size_t)Dn + d) = hi;
            }
        }
    } else {
#pragma unroll
        for (int mi = 0; mi < 2; mi++) {
            const int m1 = m0 + wm * 32 + mi * 16 + g;
#pragma unroll
            for (int ni = 0; ni < 8; ni++) {
                const int n = n0 + wn * 64 + ni * 8 + 2 * tig;
                const float2 bb = *(const float2*)(bias + n);
                float2 lo = {acc[mi][ni][0] + bb.x, acc[mi][ni][1] + bb.y};
                float2 hi = {acc[mi][ni][2] + bb.x, acc[mi][ni][3] + bb.y};
                *(float2*)(out + (size_t)m1 * Cn + n) = lo;
                *(float2*)(out + (size_t)(m1 + 8) * Cn + n) = hi;
            }
        }
    }
}

// ---------------- tensor-core causal flash attention ----------------
// Grid (32, B*H). Block 128 = 4 warps, each owns 16 q-rows of a 64-row q tile.
// KV tiles of 64. Split-bf16 with correction terms for both QK^T and PV.
__global__ __launch_bounds__(128) void attn_mma()
{
    extern __shared__ __align__(16) __nv_bfloat16 sm[];
    // element offsets
    const int OQH = 0, OQL = 64 * SD, OKH = 2 * 64 * SD, OKL = 3 * 64 * SD,
              OVH = 4 * 64 * SD, OVL = 5 * 64 * SD;

    const int tid = threadIdx.x, lane = tid & 31, wid = tid >> 5;
    const int qt = gridDim.x - 1 - blockIdx.x;        // heavy tiles first
    const int bh = blockIdx.y;
    const int g = lane >> 2, tig = lane & 3;

    const float* qg = g_q + (size_t)bh * Tn * Dn + (size_t)qt * 64 * Dn;
    const float* kg = g_k + (size_t)bh * Tn * Dn;
    const float* vg = g_v + (size_t)bh * Tn * Dn;

    const unsigned su = smem_u32(sm);

    // ---- load + split Q tile (once) ----
    {
        const int r = tid >> 1, c0 = (tid & 1) * 32;
        const float4* s4 = (const float4*)(qg + r * Dn + c0);
#pragma unroll
        for (int j = 0; j < 8; j++) {
            float4 v = s4[j];
            float hx = __bfloat162float(__float2bfloat16(v.x));
            float hy = __bfloat162float(__float2bfloat16(v.y));
            float hz = __bfloat162float(__float2bfloat16(v.z));
            float hw = __bfloat162float(__float2bfloat16(v.w));
            unsigned* ph = (unsigned*)&sm[OQH + r * SD + c0 + 4 * j];
            unsigned* pl = (unsigned*)&sm[OQL + r * SD + c0 + 4 * j];
            ph[0] = packbf2(hx, hy); ph[1] = packbf2(hz, hw);
            pl[0] = packbf2(v.x - hx, v.y - hy); pl[1] = packbf2(v.z - hz, v.w - hw);
        }
    }

    // fragment addresses
    const unsigned a_q = su + 2u * ((wid * 16 + (lane & 15)) * SD + (lane >> 4) * 8);
    const int brow = (lane & 7) + ((lane >> 4) << 3);
    const int bcol = ((lane >> 3) & 1) * 8;
    const int vrow = (((lane >> 3) & 1) << 3) + (lane & 7);
    const int vd = (lane >> 4) * 8;

    float O[8][4];
#pragma unroll
    for (int i = 0; i < 8; i++)
#pragma unroll
        for (int q = 0; q < 4; q++) O[i][q] = 0.0f;
    float m0r = -1e30f, m1r = -1e30f, l0 = 0.0f, l1 = 0.0f;

    const int qrow_g = qt * 64 + wid * 16 + g;        // thread's row (and +8)
    const int ldr = tid >> 1, ldc = (tid & 1) * 32;   // KV loader mapping

    for (int kt = 0; kt <= qt; kt++) {
        __syncthreads();
        // ---- load + split K,V tiles ----
        {
            const float4* k4 = (const float4*)(kg + ((size_t)kt * 64 + ldr) * Dn + ldc);
            const float4* v4 = (const float4*)(vg + ((size_t)kt * 64 + ldr) * Dn + ldc);
#pragma unroll
            for (int j = 0; j < 8; j++) {
                float4 v = k4[j];
                float hx = __bfloat162float(__float2bfloat16(v.x));
                float hy = __bfloat162float(__float2bfloat16(v.y));
                float hz = __bfloat162float(__float2bfloat16(v.z));
                float hw = __bfloat162float(__float2bfloat16(v.w));
                unsigned* ph = (unsigned*)&sm[OKH + ldr * SD + ldc + 4 * j];
                unsigned* pl = (unsigned*)&sm[OKL + ldr * SD + ldc + 4 * j];
                ph[0] = packbf2(hx, hy); ph[1] = packbf2(hz, hw);
                pl[0] = packbf2(v.x - hx, v.y - hy); pl[1] = packbf2(v.z - hz, v.w - hw);
                v = v4[j];
                hx = __bfloat162float(__float2bfloat16(v.x));
                hy = __bfloat162float(__float2bfloat16(v.y));
                hz = __bfloat162float(__float2bfloat16(v.z));
                hw = __bfloat162float(__float2bfloat16(v.w));
                ph = (unsigned*)&sm[OVH + ldr * SD + ldc + 4 * j];
                pl = (unsigned*)&sm[OVL + ldr * SD + ldc + 4 * j];
                ph[0] = packbf2(hx, hy); ph[1] = packbf2(hz, hw);
                pl[0] = packbf2(v.x - hx, v.y - hy); pl[1] = packbf2(v.z - hz, v.w - hw);
            }
        }
        __syncthreads();

        // ---- S = Q K^T (3-term split) ----
        float sc[8][4];
#pragma unroll
        for (int i = 0; i < 8; i++)
#pragma unroll
            for (int q = 0; q < 4; q++) sc[i][q] = 0.0f;

#pragma unroll
        for (int ks = 0; ks < 4; ks++) {
            unsigned aqh[4], aql[4], bkh[4][4], bkl[4][4];
            ldsm4(aqh, a_q + 2u * OQH + ks * 32);
            ldsm4(aql, a_q + 2u * OQL + ks * 32);
#pragma unroll
            for (int nb = 0; nb < 4; nb++) {
                ldsm4(bkh[nb], su + 2u * (OKH + (nb * 16 + brow) * SD + bcol) + ks * 32);
                ldsm4(bkl[nb], su + 2u * (OKL + (nb * 16 + brow) * SD + bcol) + ks * 32);
            }
#pragma unroll
            for (int nb = 0; nb < 4; nb++) {
                mma16816(sc[2 * nb],     aqh, &bkh[nb][0]);
                mma16816(sc[2 * nb + 1], aqh, &bkh[nb][2]);
                mma16816(sc[2 * nb],     aql, &bkh[nb][0]);
                mma16816(sc[2 * nb + 1], aql, &bkh[nb][2]);
                mma16816(sc[2 * nb],     aqh, &bkl[nb][0]);
                mma16816(sc[2 * nb + 1], aqh, &bkl[nb][2]);
            }
        }

        // ---- causal mask (diagonal tile only) ----
        if (kt == qt) {
            const int kb = kt * 64 + 2 * tig;
#pragma unroll
            for (int ni = 0; ni < 8; ni++) {
                const int key = kb + ni * 8;
                if (key > qrow_g)         sc[ni][0] = -1e30f;
                if (key + 1 > qrow_g)     sc[ni][1] = -1e30f;
                if (key > qrow_g + 8)     sc[ni][2] = -1e30f;
                if (key + 1 > qrow_g + 8) sc[ni][3] = -1e30f;
            }
        }

        // ---- online softmax ----
        float mx0 = -1e30f, mx1 = -1e30f;
#pragma unroll
        for (int ni = 0; ni < 8; ni++) {
            mx0 = fmaxf(mx0, fmaxf(sc[ni][0], sc[ni][1]));
            mx1 = fmaxf(mx1, fmaxf(sc[ni][2], sc[ni][3]));
        }
        mx0 = fmaxf(mx0, __shfl_xor_sync(0xFFFFFFFF, mx0, 1));
        mx0 = fmaxf(mx0, __shfl_xor_sync(0xFFFFFFFF, mx0, 2));
        mx1 = fmaxf(mx1, __shfl_xor_sync(0xFFFFFFFF, mx1, 1));
        mx1 = fmaxf(mx1, __shfl_xor_sync(0xFFFFFFFF, mx1, 2));
        const float nm0 = fmaxf(m0r, mx0), nm1 = fmaxf(m1r, mx1);
        const float cr0 = fexp(m0r - nm0), cr1 = fexp(m1r - nm1);
        m0r = nm0; m1r = nm1;
        l0 *= cr0; l1 *= cr1;
#pragma unroll
        for (int ni = 0; ni < 8; ni++) {
            O[ni][0] *= cr0; O[ni][1] *= cr0;
            O[ni][2] *= cr1; O[ni][3] *= cr1;
        }
        float ps0 = 0.0f, ps1 = 0.0f;
#pragma unroll
        for (int ni = 0; ni < 8; ni++) {
            sc[ni][0] = fexp(sc[ni][0] - nm0);
            sc[ni][1] = fexp(sc[ni][1] - nm0);
            sc[ni][2] = fexp(sc[ni][2] - nm1);
            sc[ni][3] = fexp(sc[ni][3] - nm1);
            ps0 += sc[ni][0] + sc[ni][1];
            ps1 += sc[ni][2] + sc[ni][3];
        }
        l0 += ps0; l1 += ps1;

        // ---- pack P (split) into A fragments ----
        unsigned aph[4][4], apl[4][4];
#pragma unroll
        for (int j = 0; j < 4; j++) {
            float h00 = __bfloat162float(__float2bfloat16(sc[2 * j][0]));
            float h01 = __bfloat162float(__float2bfloat16(sc[2 * j][1]));
            float h02 = __bfloat162float(__float2bfloat16(sc[2 * j][2]));
            float h03 = __bfloat162float(__float2bfloat16(sc[2 * j][3]));
            float h10 = __bfloat162float(__float2bfloat16(sc[2 * j + 1][0]));
            float h11 = __bfloat162float(__float2bfloat16(sc[2 * j + 1][1]));
            float h12 = __bfloat162float(__float2bfloat16(sc[2 * j + 1][2]));
            float h13 = __bfloat162float(__float2bfloat16(sc[2 * j + 1][3]));
            aph[j][0] = packbf2(h00, h01);
            aph[j][1] = packbf2(h02, h03);
            aph[j][2] = packbf2(h10, h11);
            aph[j][3] = packbf2(h12, h13);
            apl[j][0] = packbf2(sc[2 * j][0] - h00, sc[2 * j][1] - h01);
            apl[j][1] = packbf2(sc[2 * j][2] - h02, sc[2 * j][3] - h03);
            apl[j][2] = packbf2(sc[2 * j + 1][0] - h10, sc[2 * j + 1][1] - h11);
            apl[j][3] = packbf2(sc[2 * j + 1][2] - h12, sc[2 * j + 1][3] - h13);
        }

        // ---- O += P V (3-term split), V via trans ldmatrix ----
#pragma unroll
        for (int j = 0; j < 4; j++) {
#pragma unroll
            for (int db = 0; db < 4; db++) {
                unsigned vh[4], vl[4];
                ldsm4t(vh, su + 2u * (OVH + (j * 16 + vrow) * SD + db * 16 + vd));
                ldsm4t(vl, su + 2u * (OVL + (j * 16 + vrow) * SD + db * 16 + vd));
                mma16816(O[2 * db],     aph[j], &vh[0]);
                mma16816(O[2 * db + 1], aph[j], &vh[2]);
                mma16816(O[2 * db],     apl[j], &vh[0]);
                mma16816(O[2 * db + 1], apl[j], &vh[2]);
                mma16816(O[2 * db],     aph[j], &vl[0]);
                mma16816(O[2 * db + 1], aph[j], &vl[2]);
            }
        }
    }

    // ---- epilogue ----
    l0 += __shfl_xor_sync(0xFFFFFFFF, l0, 1);
    l0 += __shfl_xor_sync(0xFFFFFFFF, l0, 2);
    l1 += __shfl_xor_sync(0xFFFFFFFF, l1, 1);
    l1 += __shfl_xor_sync(0xFFFFFFFF, l1, 2);
    const float inv0 = 1.0f / l0, inv1 = 1.0f / l1;

    const int b = bh >> 4, h = bh & 15;
    float* d0 = g_ao + (size_t)(b * Tn + qrow_g) * Cn + h * Dn;
    float* d1 = g_ao + (size_t)(b * Tn + qrow_g + 8) * Cn + h * Dn;
#pragma unroll
    for (int ni = 0; ni < 8; ni++) {
        const int d = ni * 8 + 2 * tig;
        float2 lo = {O[ni][0] * inv0, O[ni][1] * inv0};
        float2 hi = {O[ni][2] * inv1, O[ni][3] * inv1};
        *(float2*)(d0 + d) = lo;
        *(float2*)(d1 + d) = hi;
    }
}

// ---------------- launch ----------------
extern "C" void kernel_launch(void* const* d_in, const int* in_sizes, int n_in,
                              void* d_out, int out_size)
{
    const float* x     = (const float*)d_in[0];
    const float* w_qkv = (const float*)d_in[1];
    const float* w_out = (const float*)d_in[2];
    const float* b_out = (const float*)d_in[3];
    float* out = (float*)d_out;

    cudaFuncSetAttribute(attn_mma, cudaFuncAttributeMaxDynamicSharedMemorySize, ATTN_SMEM);

    const int M = Bn * Tn;
    split_k<<<(M * Cn) / 256, 256>>>(x, 0);
    split_k<<<(3 * Cn * Cn) / 256, 256>>>(w_qkv, 1);
    gemm_mma<0><<<dim3(3 * Cn / 128, M / 128), 256>>>(nullptr, nullptr);
    attn_mma<<<dim3(Tn / 64, Bn * Hn), 128, ATTN_SMEM>>>();
    split_k<<<(M * Cn) / 256, 256>>>(nullptr, 2);
    split_k<<<(Cn * Cn) / 256, 256>>>(w_out, 3);
    gemm_mma<1><<<dim3(Cn / 128, M / 128), 256>>>(b_out, out);
}

// round 6
// speedup vs baseline: 3.2533x; 1.0314x over previous
#include <cuda_runtime.h>
#include <cuda_bf16.h>

namespace {
constexpr int Bn = 4, Tn = 2048, Cn = 1024, Hn = 16, Dn = 64;
constexpr int Kp = 3072;     // split-K concat: A=[h|l|h], B=[h|h|l]
constexpr int SD = 72;       // padded row stride (elems) = 144B, conflict-free + 16B-divisible
constexpr int ASTG = 4 * 64 * SD;          // attn stage stride (elems)
constexpr unsigned ATTN_SMEM = 2 * ASTG * 2;        // 73728 B
constexpr int GSTG = 2 * 128 * SD;         // gemm stage stride (elems)
constexpr unsigned GEMM_SMEM = 2 * GSTG * 2;        // 73728 B
}

// ---------------- scratch (device globals; no allocs allowed) ----------------
__device__ __align__(16) __nv_bfloat16 g_A[(size_t)Bn * Tn * Kp];
__device__ __align__(16) __nv_bfloat16 g_B1[(size_t)3 * Cn * Kp];
__device__ __align__(16) __nv_bfloat16 g_B3[(size_t)Cn * Kp];
__device__ __align__(16) __nv_bfloat16 g_qh[(size_t)Bn * Hn * Tn * Dn];
__device__ __align__(16) __nv_bfloat16 g_ql[(size_t)Bn * Hn * Tn * Dn];
__device__ __align__(16) __nv_bfloat16 g_kh[(size_t)Bn * Hn * Tn * Dn];
__device__ __align__(16) __nv_bfloat16 g_kl[(size_t)Bn * Hn * Tn * Dn];
__device__ __align__(16) __nv_bfloat16 g_vh[(size_t)Bn * Hn * Tn * Dn];
__device__ __align__(16) __nv_bfloat16 g_vl[(size_t)Bn * Hn * Tn * Dn];

// ---------------- helpers ----------------
__device__ __forceinline__ unsigned smem_u32(const void* p) {
    unsigned a;
    asm("{ .reg .u64 t; cvta.to.shared.u64 t, %1; cvt.u32.u64 %0, t; }" : "=r"(a) : "l"(p));
    return a;
}
__device__ __forceinline__ void cp16(unsigned s, const void* g) {
    asm volatile("cp.async.cg.shared.global [%0], [%1], 16;" :: "r"(s), "l"(g));
}
__device__ __forceinline__ void cp_commit() {
    asm volatile("cp.async.commit_group;" ::: "memory");
}
template <int N>
__device__ __forceinline__ void cp_wait() {
    asm volatile("cp.async.wait_group %0;" :: "n"(N) : "memory");
}
__device__ __forceinline__ void ldsm4(unsigned* r, unsigned addr) {
    asm volatile("ldmatrix.sync.aligned.m8n8.x4.shared.b16 {%0,%1,%2,%3}, [%4];"
        : "=r"(r[0]), "=r"(r[1]), "=r"(r[2]), "=r"(r[3]) : "r"(addr));
}
__device__ __forceinline__ void ldsm4t(unsigned* r, unsigned addr) {
    asm volatile("ldmatrix.sync.aligned.m8n8.x4.trans.shared.b16 {%0,%1,%2,%3}, [%4];"
        : "=r"(r[0]), "=r"(r[1]), "=r"(r[2]), "=r"(r[3]) : "r"(addr));
}
__device__ __forceinline__ void mma16816(float* c, const unsigned* a, const unsigned* b) {
    asm volatile("mma.sync.aligned.m16n8k16.row.col.f32.bf16.bf16.f32 "
        "{%0,%1,%2,%3}, {%4,%5,%6,%7}, {%8,%9}, {%0,%1,%2,%3};"
        : "+f"(c[0]), "+f"(c[1]), "+f"(c[2]), "+f"(c[3])
        : "r"(a[0]), "r"(a[1]), "r"(a[2]), "r"(a[3]), "r"(b[0]), "r"(b[1]));
}
__device__ __forceinline__ unsigned packbf2(float lo, float hi) {
    unsigned u;
    asm("cvt.rn.bf16x2.f32 %0, %1, %2;" : "=r"(u) : "f"(hi), "f"(lo));
    return u;
}
__device__ __forceinline__ float fexp(float x) {
    x = fmaxf(x, -80.0f);
    const float z = x * 1.4426950408889634f;
    const float zf = z + 12582912.0f;
    const int n = __float_as_int(zf);
    const float r = z - (zf - 12582912.0f);
    float p = 0.009618129f;
    p = fmaf(p, r, 0.05550411f);
    p = fmaf(p, r, 0.2402265f);
    p = fmaf(p, r, 0.6931472f);
    p = fmaf(p, r, 1.0f);
    return p * __int_as_float((n << 23) + 0x3F800000);
}

// ---------------- fp32 -> split-bf16 converters (x, w_qkv, w_out) ----------------
__global__ __launch_bounds__(256) void split_k(const float* __restrict__ src, int mode)
{
    __nv_bfloat16* dst = (mode == 0) ? g_A : (mode == 1) ? g_B1 : g_B3;
    const bool apat = (mode == 0);
    const size_t idx = (size_t)blockIdx.x * 256 + threadIdx.x;
    const size_t row = idx >> 10;
    const int k = (int)(idx & 1023);
    const float v = src[idx];
    const __nv_bfloat16 h = __float2bfloat16(v);
    const __nv_bfloat16 l = __float2bfloat16(v - __bfloat162float(h));
    const size_t base = row * Kp;
    dst[base + k] = h;
    dst[base + 1024 + k] = apat ? l : h;
    dst[base + 2048 + k] = apat ? h : l;
}

// ---------------- cp.async HMMA GEMM: C[m,n] = sum_k A[m,k]B[n,k] ----------------
// 128x128 CTA, BK=64, 2-stage cp.async ring, 8 warps (32x64 warp tile).
// MODE 0: B=g_B1 -> write split q/k/v (q scaled 0.125). MODE 1: B=g_B3 -> out+bias.
template <int MODE>
__global__ __launch_bounds__(256) void gemm_mma(
    const float* __restrict__ bias, float* __restrict__ out)
{
    const __nv_bfloat16* __restrict__ A = g_A;
    const __nv_bfloat16* __restrict__ Bw = (MODE == 0) ? g_B1 : g_B3;
    extern __shared__ __align__(16) __nv_bfloat16 sm[];

    const int tid = threadIdx.x, lane = tid & 31, wid = tid >> 5;
    const int wm = wid & 3, wn = wid >> 2;
    const int m0 = blockIdx.y * 128, n0 = blockIdx.x * 128;

    const unsigned su = smem_u32(sm);
    const int lrow = tid >> 1, lcol = (tid & 1) * 32;        // loader mapping
    const __nv_bfloat16* ag = A  + (size_t)(m0 + lrow) * Kp + lcol;
    const __nv_bfloat16* bg = Bw + (size_t)(n0 + lrow) * Kp + lcol;
    const unsigned sa_st = su + 2u * (lrow * SD + lcol);
    const unsigned sb_st = sa_st + 2u * (128 * SD);

    const unsigned a_base = su + 2u * ((wm * 32 + (lane & 15)) * SD + (lane >> 4) * 8);
    const unsigned b_base = su + 2u * (128 * SD + ((wn * 64 + (lane & 7) + ((lane >> 4) << 3))) * SD
                                       + ((lane >> 3) & 1) * 8);

    float acc[2][8][4];
#pragma unroll
    for (int i = 0; i < 2; i++)
#pragma unroll
        for (int j = 0; j < 8; j++)
#pragma unroll
            for (int q = 0; q < 4; q++) acc[i][j][q] = 0.0f;

    auto issue = [&](int it) {
        const unsigned so = ((unsigned)(it & 1)) * (GSTG * 2u);
        const int kc = it * 64;
#pragma unroll
        for (int j = 0; j < 4; j++) {
            cp16(sa_st + so + 16u * j, ag + kc + 8 * j);
            cp16(sb_st + so + 16u * j, bg + kc + 8 * j);
        }
        cp_commit();
    };

    issue(0);
    const int nst = Kp / 64;                       // 48
    for (int it = 0; it < nst; it++) {
        if (it + 1 < nst) { issue(it + 1); cp_wait<1>(); }
        else              { cp_wait<0>(); }
        __syncthreads();
        const unsigned so = ((unsigned)(it & 1)) * (GSTG * 2u);
#pragma unroll
        for (int ks = 0; ks < 4; ks++) {
            unsigned afr[2][4], bfr[4][4];
#pragma unroll
            for (int mi = 0; mi < 2; mi++)
                ldsm4(afr[mi], a_base + so + mi * (16 * SD * 2) + ks * 32);
#pragma unroll
            for (int nb = 0; nb < 4; nb++)
                ldsm4(bfr[nb], b_base + so + nb * (16 * SD * 2) + ks * 32);
#pragma unroll
            for (int mi = 0; mi < 2; mi++)
#pragma unroll
                for (int nb = 0; nb < 4; nb++) {
                    mma16816(acc[mi][2 * nb],     afr[mi], &bfr[nb][0]);
                    mma16816(acc[mi][2 * nb + 1], afr[mi], &bfr[nb][2]);
                }
        }
        __syncthreads();
    }

    const int g = lane >> 2, tig = lane & 3;
    if (MODE == 0) {
        const int nblock = n0 + wn * 64;                // 64-aligned -> one (sec, head)
        const int sec = nblock >> 10;
        const int h = (nblock & 1023) >> 6;
        const float scale = (sec == 0) ? 0.125f : 1.0f;
        __nv_bfloat16* dh = (sec == 0) ? g_qh : (sec == 1) ? g_kh : g_vh;
        __nv_bfloat16* dl = (sec == 0) ? g_ql : (sec == 1) ? g_kl : g_vl;
#pragma unroll
        for (int mi = 0; mi < 2; mi++) {
            const int m1 = m0 + wm * 32 + mi * 16 + g;
            const int b = m1 >> 11, t = m1 & 2047;
            const size_t rb = (size_t)((b * Hn + h) * Tn + t) * Dn;
#pragma unroll
            for (int ni = 0; ni < 8; ni++) {
                const int d = ni * 8 + 2 * tig;
#pragma unroll
                for (int half = 0; half < 2; half++) {
                    const float v0 = acc[mi][ni][2 * half] * scale;
                    const float v1 = acc[mi][ni][2 * half + 1] * scale;
                    const float h0 = __bfloat162float(__float2bfloat16(v0));
                    const float h1 = __bfloat162float(__float2bfloat16(v1));
                    const size_t o = rb + (size_t)half * 8 * Dn + d;
                    *(unsigned*)&dh[o] = packbf2(h0, h1);
                    *(unsigned*)&dl[o] = packbf2(v0 - h0, v1 - h1);
                }
            }
        }
    } else {
#pragma unroll
        for (int mi = 0; mi < 2; mi++) {
            const int m1 = m0 + wm * 32 + mi * 16 + g;
#pragma unroll
            for (int ni = 0; ni < 8; ni++) {
                const int n = n0 + wn * 64 + ni * 8 + 2 * tig;
                const float2 bb = *(const float2*)(bias + n);
                float2 lo = {acc[mi][ni][0] + bb.x, acc[mi][ni][1] + bb.y};
                float2 hi = {acc[mi][ni][2] + bb.x, acc[mi][ni][3] + bb.y};
                *(float2*)(out + (size_t)m1 * Cn + n) = lo;
                *(float2*)(out + (size_t)(m1 + 8) * Cn + n) = hi;
            }
        }
    }
}

// ---------------- tensor-core causal flash attention (pre-split KV) ----------------
// Grid (32, B*H). 128 thr / 4 warps. Q frags in regs; KV double-buffered cp.async.
__global__ __launch_bounds__(128) void attn_mma()
{
    extern __shared__ __align__(16) __nv_bfloat16 sm[];
    const int OKH = 0, OKL = 64 * SD, OVH = 2 * 64 * SD, OVL = 3 * 64 * SD;

    const int tid = threadIdx.x, lane = tid & 31, wid = tid >> 5;
    const int qt = gridDim.x - 1 - blockIdx.x;      // heavy tiles first
    const int bh = blockIdx.y;
    const int g = lane >> 2, tig = lane & 3;

    const size_t hb = (size_t)bh * Tn * Dn;
    const unsigned su = smem_u32(sm);
    const int lrow = tid >> 1, lcol = (tid & 1) * 32;

    // ---- Q: cp.async into stage0, ldmatrix to regs ----
    {
        const __nv_bfloat16* qh = g_qh + hb + ((size_t)qt * 64 + lrow) * Dn + lcol;
        const __nv_bfloat16* ql = g_ql + hb + ((size_t)qt * 64 + lrow) * Dn + lcol;
        const unsigned s0 = su + 2u * (lrow * SD + lcol);
#pragma unroll
        for (int j = 0; j < 4; j++) {
            cp16(s0 + 16u * j, qh + 8 * j);
            cp16(s0 + 2u * OKL + 16u * j, ql + 8 * j);
        }
        cp_commit(); cp_wait<0>();
    }
    __syncthreads();
    unsigned aqh[4][4], aql[4][4];
    {
        const unsigned a_q = su + 2u * ((wid * 16 + (lane & 15)) * SD + (lane >> 4) * 8);
#pragma unroll
        for (int ks = 0; ks < 4; ks++) {
            ldsm4(aqh[ks], a_q + ks * 32);
            ldsm4(aql[ks], a_q + 2u * OKL + ks * 32);
        }
    }
    __syncthreads();

    const int brow = (lane & 7) + ((lane >> 4) << 3);
    const int bcol = ((lane >> 3) & 1) * 8;
    const int vrow = (((lane >> 3) & 1) << 3) + (lane & 7);
    const int vd = (lane >> 4) * 8;

    float O[8][4];
#pragma unroll
    for (int i = 0; i < 8; i++)
#pragma unroll
        for (int q = 0; q < 4; q++) O[i][q] = 0.0f;
    float m0r = -1e30f, m1r = -1e30f, l0 = 0.0f, l1 = 0.0f;
    const int qrow_g = qt * 64 + wid * 16 + g;

    auto issue_kv = [&](int kt) {
        const unsigned so = ((unsigned)(kt & 1)) * (ASTG * 2u);
        const size_t gb = hb + ((size_t)kt * 64 + lrow) * Dn + lcol;
        const unsigned s0 = su + so + 2u * (lrow * SD + lcol);
#pragma unroll
        for (int j = 0; j < 4; j++) {
            cp16(s0 + 16u * j, g_kh + gb + 8 * j);
            cp16(s0 + 2u * OKL + 16u * j, g_kl + gb + 8 * j);
            cp16(s0 + 2u * OVH + 16u * j, g_vh + gb + 8 * j);
            cp16(s0 + 2u * OVL + 16u * j, g_vl + gb + 8 * j);
        }
        cp_commit();
    };

    issue_kv(0);
    for (int kt = 0; kt <= qt; kt++) {
        if (kt < qt) { issue_kv(kt + 1); cp_wait<1>(); }
        else         { cp_wait<0>(); }
        __syncthreads();
        const unsigned so = ((unsigned)(kt & 1)) * (ASTG * 2u);

        // ---- S = Q K^T (3-term) ----
        float sc[8][4];
#pragma unroll
        for (int i = 0; i < 8; i++)
#pragma unroll
            for (int q = 0; q < 4; q++) sc[i][q] = 0.0f;
#pragma unroll
        for (int ks = 0; ks < 4; ks++) {
            unsigned bkh[4][4], bkl[4][4];
#pragma unroll
            for (int nb = 0; nb < 4; nb++) {
                const unsigned ra = su + so + 2u * ((nb * 16 + brow) * SD + bcol) + ks * 32;
                ldsm4(bkh[nb], ra);
                ldsm4(bkl[nb], ra + 2u * OKL);
            }
#pragma unroll
            for (int nb = 0; nb < 4; nb++) {
                mma16816(sc[2 * nb],     aqh[ks], &bkh[nb][0]);
                mma16816(sc[2 * nb + 1], aqh[ks], &bkh[nb][2]);
                mma16816(sc[2 * nb],     aql[ks], &bkh[nb][0]);
                mma16816(sc[2 * nb + 1], aql[ks], &bkh[nb][2]);
                mma16816(sc[2 * nb],     aqh[ks], &bkl[nb][0]);
                mma16816(sc[2 * nb + 1], aqh[ks], &bkl[nb][2]);
            }
        }

        if (kt == qt) {
            const int kb = kt * 64 + 2 * tig;
#pragma unroll
            for (int ni = 0; ni < 8; ni++) {
                const int key = kb + ni * 8;
                if (key > qrow_g)         sc[ni][0] = -1e30f;
                if (key + 1 > qrow_g)     sc[ni][1] = -1e30f;
                if (key > qrow_g + 8)     sc[ni][2] = -1e30f;
                if (key + 1 > qrow_g + 8) sc[ni][3] = -1e30f;
            }
        }

        // ---- online softmax ----
        float mx0 = -1e30f, mx1 = -1e30f;
#pragma unroll
        for (int ni = 0; ni < 8; ni++) {
            mx0 = fmaxf(mx0, fmaxf(sc[ni][0], sc[ni][1]));
            mx1 = fmaxf(mx1, fmaxf(sc[ni][2], sc[ni][3]));
        }
        mx0 = fmaxf(mx0, __shfl_xor_sync(0xFFFFFFFF, mx0, 1));
        mx0 = fmaxf(mx0, __shfl_xor_sync(0xFFFFFFFF, mx0, 2));
        mx1 = fmaxf(mx1, __shfl_xor_sync(0xFFFFFFFF, mx1, 1));
        mx1 = fmaxf(mx1, __shfl_xor_sync(0xFFFFFFFF, mx1, 2));
        const float nm0 = fmaxf(m0r, mx0), nm1 = fmaxf(m1r, mx1);
        const float cr0 = fexp(m0r - nm0), cr1 = fexp(m1r - nm1);
        m0r = nm0; m1r = nm1;
        l0 *= cr0; l1 *= cr1;
#pragma unroll
        for (int ni = 0; ni < 8; ni++) {
            O[ni][0] *= cr0; O[ni][1] *= cr0;
            O[ni][2] *= cr1; O[ni][3] *= cr1;
        }
        float ps0 = 0.0f, ps1 = 0.0f;
#pragma unroll
        for (int ni = 0; ni < 8; ni++) {
            sc[ni][0] = fexp(sc[ni][0] - nm0);
            sc[ni][1] = fexp(sc[ni][1] - nm0);
            sc[ni][2] = fexp(sc[ni][2] - nm1);
            sc[ni][3] = fexp(sc[ni][3] - nm1);
            ps0 += sc[ni][0] + sc[ni][1];
            ps1 += sc[ni][2] + sc[ni][3];
        }
        l0 += ps0; l1 += ps1;

        // ---- pack P (split) ----
        unsigned aph[4][4], apl[4][4];
#pragma unroll
        for (int j = 0; j < 4; j++) {
            float h00 = __bfloat162float(__float2bfloat16(sc[2 * j][0]));
            float h01 = __bfloat162float(__float2bfloat16(sc[2 * j][1]));
            float h02 = __bfloat162float(__float2bfloat16(sc[2 * j][2]));
            float h03 = __bfloat162float(__float2bfloat16(sc[2 * j][3]));
            float h10 = __bfloat162float(__float2bfloat16(sc[2 * j + 1][0]));
            float h11 = __bfloat162float(__float2bfloat16(sc[2 * j + 1][1]));
            float h12 = __bfloat162float(__float2bfloat16(sc[2 * j + 1][2]));
            float h13 = __bfloat162float(__float2bfloat16(sc[2 * j + 1][3]));
            aph[j][0] = packbf2(h00, h01);
            aph[j][1] = packbf2(h02, h03);
            aph[j][2] = packbf2(h10, h11);
            aph[j][3] = packbf2(h12, h13);
            apl[j][0] = packbf2(sc[2 * j][0] - h00, sc[2 * j][1] - h01);
            apl[j][1] = packbf2(sc[2 * j][2] - h02, sc[2 * j][3] - h03);
            apl[j][2] = packbf2(sc[2 * j + 1][0] - h10, sc[2 * j + 1][1] - h11);
            apl[j][3] = packbf2(sc[2 * j + 1][2] - h12, sc[2 * j + 1][3] - h13);
        }

        // ---- O += P V (3-term) ----
#pragma unroll
        for (int j = 0; j < 4; j++) {
#pragma unroll
            for (int db = 0; db < 4; db++) {
                unsigned vh[4], vl[4];
                const unsigned ra = su + so + 2u * ((j * 16 + vrow) * SD + db * 16 + vd);
                ldsm4t(vh, ra + 2u * OVH);
                ldsm4t(vl, ra + 2u * OVL);
                mma16816(O[2 * db],     aph[j], &vh[0]);
                mma16816(O[2 * db + 1], aph[j], &vh[2]);
                mma16816(O[2 * db],     apl[j], &vh[0]);
                mma16816(O[2 * db + 1], apl[j], &vh[2]);
                mma16816(O[2 * db],     aph[j], &vl[0]);
                mma16816(O[2 * db + 1], aph[j], &vl[2]);
            }
        }
        __syncthreads();
    }

    // ---- epilogue: write g_A split (pattern h | l | h) ----
    l0 += __shfl_xor_sync(0xFFFFFFFF, l0, 1);
    l0 += __shfl_xor_sync(0xFFFFFFFF, l0, 2);
    l1 += __shfl_xor_sync(0xFFFFFFFF, l1, 1);
    l1 += __shfl_xor_sync(0xFFFFFFFF, l1, 2);
    const float inv0 = 1.0f / l0, inv1 = 1.0f / l1;

    const int b = bh >> 4, h = bh & 15;
    const size_t r0 = (size_t)(b * Tn + qrow_g) * Kp;
    const size_t r1 = (size_t)(b * Tn + qrow_g + 8) * Kp;
#pragma unroll
    for (int ni = 0; ni < 8; ni++) {
        const int k = h * Dn + ni * 8 + 2 * tig;
        {
            const float v0 = O[ni][0] * inv0, v1 = O[ni][1] * inv0;
            const float h0 = __bfloat162float(__float2bfloat16(v0));
            const float h1 = __bfloat162float(__float2bfloat16(v1));
            const unsigned ph = packbf2(h0, h1), pl = packbf2(v0 - h0, v1 - h1);
            *(unsigned*)&g_A[r0 + k] = ph;
            *(unsigned*)&g_A[r0 + 1024 + k] = pl;
            *(unsigned*)&g_A[r0 + 2048 + k] = ph;
        }
        {
            const float v0 = O[ni][2] * inv1, v1 = O[ni][3] * inv1;
            const float h0 = __bfloat162float(__float2bfloat16(v0));
            const float h1 = __bfloat162float(__float2bfloat16(v1));
            const unsigned ph = packbf2(h0, h1), pl = packbf2(v0 - h0, v1 - h1);
            *(unsigned*)&g_A[r1 + k] = ph;
            *(unsigned*)&g_A[r1 + 1024 + k] = pl;
            *(unsigned*)&g_A[r1 + 2048 + k] = ph;
        }
    }
}

// ---------------- launch ----------------
extern "C" void kernel_launch(void* const* d_in, const int* in_sizes, int n_in,
                              void* d_out, int out_size)
{
    const float* x     = (const float*)d_in[0];
    const float* w_qkv = (const float*)d_in[1];
    const float* w_out = (const float*)d_in[2];
    const float* b_out = (const float*)d_in[3];
    float* out = (float*)d_out;

    cudaFuncSetAttribute(attn_mma, cudaFuncAttributeMaxDynamicSharedMemorySize, ATTN_SMEM);
    cudaFuncSetAttribute(gemm_mma<0>, cudaFuncAttributeMaxDynamicSharedMemorySize, GEMM_SMEM);
    cudaFuncSetAttribute(gemm_mma<1>, cudaFuncAttributeMaxDynamicSharedMemorySize, GEMM_SMEM);

    const int M = Bn * Tn;
    split_k<<<(M * Cn) / 256, 256>>>(x, 0);
    split_k<<<(3 * Cn * Cn) / 256, 256>>>(w_qkv, 1);
    split_k<<<(Cn * Cn) / 256, 256>>>(w_out, 3);
    gemm_mma<0><<<dim3(3 * Cn / 128, M / 128), 256, GEMM_SMEM>>>(nullptr, nullptr);
    attn_mma<<<dim3(Tn / 64, Bn * Hn), 128, ATTN_SMEM>>>();
    gemm_mma<1><<<dim3(Cn / 128, M / 128), 256, GEMM_SMEM>>>(b_out, out);
}

// round 7
// speedup vs baseline: 5.4619x; 1.6789x over previous
#include <cuda.h>
#include <cuda_runtime.h>
#include <cuda_bf16.h>

namespace {
constexpr int Bn = 4, Tn = 2048, Cn = 1024, Hn = 16, Dn = 64;
constexpr unsigned GEMM_SMEM = 2 * 65536 + 1024 + 64;        // 2 stages x 4 tiles x 16KB
constexpr unsigned ATTN_SMEM = 16384 + 2 * 32768 + 1024 + 64; // Q(2x8KB) + 2 KV stages
}

// ---------------- scratch (device globals; no allocs allowed) ----------------
__device__ __align__(16) __nv_bfloat16 g_Ah[(size_t)Bn * Tn * Cn];     // x / ao high
__device__ __align__(16) __nv_bfloat16 g_Al[(size_t)Bn * Tn * Cn];     // x / ao low
__device__ __align__(16) __nv_bfloat16 g_B1h[(size_t)3 * Cn * Cn];
__device__ __align__(16) __nv_bfloat16 g_B1l[(size_t)3 * Cn * Cn];
__device__ __align__(16) __nv_bfloat16 g_B3h[(size_t)Cn * Cn];
__device__ __align__(16) __nv_bfloat16 g_B3l[(size_t)Cn * Cn];
__device__ __align__(16) __nv_bfloat16 g_qh[(size_t)Bn * Hn * Tn * Dn];  // [BH*T, 64]
__device__ __align__(16) __nv_bfloat16 g_ql[(size_t)Bn * Hn * Tn * Dn];
__device__ __align__(16) __nv_bfloat16 g_kh[(size_t)Bn * Hn * Tn * Dn];
__device__ __align__(16) __nv_bfloat16 g_kl[(size_t)Bn * Hn * Tn * Dn];
__device__ __align__(16) __nv_bfloat16 g_vh[(size_t)Bn * Hn * Tn * Dn];
__device__ __align__(16) __nv_bfloat16 g_vl[(size_t)Bn * Hn * Tn * Dn];

// ---------------- device helpers ----------------
__device__ __forceinline__ unsigned smem_u32(const void* p) {
    unsigned a;
    asm("{ .reg .u64 t; cvta.to.shared.u64 t, %1; cvt.u32.u64 %0, t; }" : "=r"(a) : "l"(p));
    return a;
}
__device__ __forceinline__ void mbar_init(unsigned addr, unsigned cnt) {
    asm volatile("mbarrier.init.shared.b64 [%0], %1;" :: "r"(addr), "r"(cnt) : "memory");
}
__device__ __forceinline__ void mbar_expect(unsigned addr, unsigned bytes) {
    asm volatile("mbarrier.arrive.expect_tx.shared.b64 _, [%0], %1;"
                 :: "r"(addr), "r"(bytes) : "memory");
}
__device__ __forceinline__ void mbar_wait(unsigned addr, unsigned parity) {
    asm volatile(
        "{\n\t.reg .pred P;\n\t"
        "WL_%=:\n\t"
        "mbarrier.try_wait.parity.acquire.cta.shared::cta.b64 P, [%0], %1, 0x989680;\n\t"
        "@P bra.uni WD_%=;\n\t"
        "bra.uni WL_%=;\n\t"
        "WD_%=:\n\t}"
        :: "r"(addr), "r"(parity) : "memory");
}
__device__ __forceinline__ void tma2d(unsigned smem, const CUtensorMap* m,
                                      int x, int y, unsigned mbar) {
    asm volatile(
        "cp.async.bulk.tensor.2d.shared::cta.global.tile.mbarrier::complete_tx::bytes "
        "[%0], [%1, {%2, %3}], [%4];"
        :: "r"(smem), "l"(m), "r"(x), "r"(y), "r"(mbar) : "memory");
}
__device__ __forceinline__ void ldsm4(unsigned* r, unsigned addr) {
    asm volatile("ldmatrix.sync.aligned.m8n8.x4.shared.b16 {%0,%1,%2,%3}, [%4];"
        : "=r"(r[0]), "=r"(r[1]), "=r"(r[2]), "=r"(r[3]) : "r"(addr));
}
__device__ __forceinline__ void ldsm4t(unsigned* r, unsigned addr) {
    asm volatile("ldmatrix.sync.aligned.m8n8.x4.trans.shared.b16 {%0,%1,%2,%3}, [%4];"
        : "=r"(r[0]), "=r"(r[1]), "=r"(r[2]), "=r"(r[3]) : "r"(addr));
}
__device__ __forceinline__ void mma16816(float* c, const unsigned* a, const unsigned* b) {
    asm volatile("mma.sync.aligned.m16n8k16.row.col.f32.bf16.bf16.f32 "
        "{%0,%1,%2,%3}, {%4,%5,%6,%7}, {%8,%9}, {%0,%1,%2,%3};"
        : "+f"(c[0]), "+f"(c[1]), "+f"(c[2]), "+f"(c[3])
        : "r"(a[0]), "r"(a[1]), "r"(a[2]), "r"(a[3]), "r"(b[0]), "r"(b[1]));
}
__device__ __forceinline__ unsigned packbf2(float lo, float hi) {
    unsigned u;
    asm("cvt.rn.bf16x2.f32 %0, %1, %2;" : "=r"(u) : "f"(hi), "f"(lo));
    return u;
}
__device__ __forceinline__ float fexp(float x) {
    x = fmaxf(x, -80.0f);
    const float z = x * 1.4426950408889634f;
    const float zf = z + 12582912.0f;
    const int n = __float_as_int(zf);
    const float r = z - (zf - 12582912.0f);
    float p = 0.009618129f;
    p = fmaf(p, r, 0.05550411f);
    p = fmaf(p, r, 0.2402265f);
    p = fmaf(p, r, 0.6931472f);
    p = fmaf(p, r, 1.0f);
    return p * __int_as_float((n << 23) + 0x3F800000);
}

// ---------------- fp32 -> (h, l) bf16 split ----------------
__global__ __launch_bounds__(256) void split2(const float* __restrict__ src,
                                              __nv_bfloat16* __restrict__ dh,
                                              __nv_bfloat16* __restrict__ dl)
{
    const size_t i = (size_t)blockIdx.x * 256 + threadIdx.x;
    const float v = src[i];
    const __nv_bfloat16 h = __float2bfloat16(v);
    dh[i] = h;
    dl[i] = __float2bfloat16(v - __bfloat162float(h));
}

// ---------------- TMA HMMA GEMM: C[m,n] = sum_k A[m,k]B[n,k] ----------------
// 128x128 CTA, BK=64, 2-stage TMA ring, 3-term split (Ah*Bh + Al*Bh + Ah*Bl).
// MODE 0: write split q/k/v (q scaled 0.125). MODE 1: out = C + bias.
template <int MODE>
__global__ __launch_bounds__(256) void gemm_tma(
    const __grid_constant__ CUtensorMap tAh, const __grid_constant__ CUtensorMap tAl,
    const __grid_constant__ CUtensorMap tBh, const __grid_constant__ CUtensorMap tBl,
    const float* __restrict__ bias, float* __restrict__ out)
{
    extern __shared__ __align__(16) unsigned char smraw[];
    const unsigned sb = (smem_u32(smraw) + 1023u) & ~1023u;
    const unsigned ctrl = sb + 2u * 65536u;                 // full[0], full[1]

    const int tid = threadIdx.x, lane = tid & 31, wid = tid >> 5;
    const int wm = wid & 3, wn = wid >> 2;
    const int m0 = blockIdx.y * 128, n0 = blockIdx.x * 128;

    if (tid == 0) { mbar_init(ctrl, 1); mbar_init(ctrl + 8, 1); }
    __syncthreads();

    auto issue = [&](int s) {   // tid 0 only
        const unsigned base = sb + (unsigned)(s & 1) * 65536u;
        const unsigned mb = ctrl + (unsigned)(s & 1) * 8u;
        mbar_expect(mb, 65536u);
        const int kc = s * 64;
        tma2d(base,           &tAh, kc, m0, mb);
        tma2d(base + 16384u,  &tAl, kc, m0, mb);
        tma2d(base + 32768u,  &tBh, kc, n0, mb);
        tma2d(base + 49152u,  &tBl, kc, n0, mb);
    };
    if (tid == 0) { issue(0); issue(1); }

    // fragment addressing (intra-tile bytes, SW128 XOR applied at use)
    const int arow = wm * 32 + (lane & 15);
    const unsigned abase0 = (unsigned)(arow * 128);
    const unsigned acolb = (unsigned)((lane >> 4) * 16);
    const unsigned aswz = (unsigned)((arow & 7) << 4);
    const int brow = wn * 64 + (lane & 7) + ((lane >> 4) << 3);
    const unsigned bbase0 = (unsigned)(brow * 128);
    const unsigned bcolb = (unsigned)(((lane >> 3) & 1) * 16);
    const unsigned bswz = (unsigned)((brow & 7) << 4);

    float acc[2][8][4];
#pragma unroll
    for (int i = 0; i < 2; i++)
#pragma unroll
        for (int j = 0; j < 8; j++)
#pragma unroll
            for (int q = 0; q < 4; q++) acc[i][j][q] = 0.0f;

    for (int s = 0; s < 16; s++) {                          // K = 1024 / 64
        const unsigned stb = sb + (unsigned)(s & 1) * 65536u;
        mbar_wait(ctrl + (unsigned)(s & 1) * 8u, (unsigned)((s >> 1) & 1));
#pragma unroll
        for (int ks = 0; ks < 4; ks++) {
            unsigned ah[2][4], al[2][4], bh[4][4], bl[4][4];
            const unsigned ac = (acolb + ks * 32) ^ aswz;
#pragma unroll
            for (int mi = 0; mi < 2; mi++) {
                ldsm4(ah[mi], stb + abase0 + mi * 2048u + ac);
                ldsm4(al[mi], stb + 16384u + abase0 + mi * 2048u + ac);
            }
            const unsigned bc = (bcolb + ks * 32) ^ bswz;
#pragma unroll
            for (int nb = 0; nb < 4; nb++) {
                ldsm4(bh[nb], stb + 32768u + bbase0 + nb * 2048u + bc);
                ldsm4(bl[nb], stb + 49152u + bbase0 + nb * 2048u + bc);
            }
#pragma unroll
            for (int mi = 0; mi < 2; mi++)
#pragma unroll
                for (int nb = 0; nb < 4; nb++) {
                    mma16816(acc[mi][2 * nb],     ah[mi], &bh[nb][0]);
                    mma16816(acc[mi][2 * nb + 1], ah[mi], &bh[nb][2]);
                    mma16816(acc[mi][2 * nb],     al[mi], &bh[nb][0]);
                    mma16816(acc[mi][2 * nb + 1], al[mi], &bh[nb][2]);
                    mma16816(acc[mi][2 * nb],     ah[mi], &bl[nb][0]);
                    mma16816(acc[mi][2 * nb + 1], ah[mi], &bl[nb][2]);
                }
        }
        __syncthreads();
        if (tid == 0 && s + 2 < 16) issue(s + 2);
    }

    const int g = lane >> 2, tig = lane & 3;
    if (MODE == 0) {
        const int nblock = n0 + wn * 64;                    // one (sec, head)
        const int sec = nblock >> 10;
        const int h = (nblock & 1023) >> 6;
        const float scale = (sec == 0) ? 0.125f : 1.0f;
        __nv_bfloat16* dh = (sec == 0) ? g_qh : (sec == 1) ? g_kh : g_vh;
        __nv_bfloat16* dl = (sec == 0) ? g_ql : (sec == 1) ? g_kl : g_vl;
#pragma unroll
        for (int mi = 0; mi < 2; mi++) {
            const int m1 = m0 + wm * 32 + mi * 16 + g;
            const int b = m1 >> 11, t = m1 & 2047;
            const size_t rb = (size_t)((b * Hn + h) * Tn + t) * Dn;
#pragma unroll
            for (int ni = 0; ni < 8; ni++) {
                const int d = ni * 8 + 2 * tig;
#pragma unroll
                for (int half = 0; half < 2; half++) {
                    const float v0 = acc[mi][ni][2 * half] * scale;
                    const float v1 = acc[mi][ni][2 * half + 1] * scale;
                    const float h0 = __bfloat162float(__float2bfloat16(v0));
                    const float h1 = __bfloat162float(__float2bfloat16(v1));
                    const size_t o = rb + (size_t)half * 8 * Dn + d;
                    *(unsigned*)&dh[o] = packbf2(h0, h1);
                    *(unsigned*)&dl[o] = packbf2(v0 - h0, v1 - h1);
                }
            }
        }
    } else {
#pragma unroll
        for (int mi = 0; mi < 2; mi++) {
            const int m1 = m0 + wm * 32 + mi * 16 + g;
#pragma unroll
            for (int ni = 0; ni < 8; ni++) {
                const int n = n0 + wn * 64 + ni * 8 + 2 * tig;
                const float2 bb = *(const float2*)(bias + n);
                float2 lo = {acc[mi][ni][0] + bb.x, acc[mi][ni][1] + bb.y};
                float2 hi = {acc[mi][ni][2] + bb.x, acc[mi][ni][3] + bb.y};
                *(float2*)(out + (size_t)m1 * Cn + n) = lo;
                *(float2*)(out + (size_t)(m1 + 8) * Cn + n) = hi;
            }
        }
    }
}

// ---------------- TMA tensor-core causal flash attention ----------------
// Grid (32, B*H), 128 thr / 4 warps; KV 2-stage TMA ring; writes split ao.
__global__ __launch_bounds__(128) void attn_tma(
    const __grid_constant__ CUtensorMap tQh, const __grid_constant__ CUtensorMap tQl,
    const __grid_constant__ CUtensorMap tKh, const __grid_constant__ CUtensorMap tKl,
    const __grid_constant__ CUtensorMap tVh, const __grid_constant__ CUtensorMap tVl)
{
    extern __shared__ __align__(16) unsigned char smraw[];
    const unsigned sb = (smem_u32(smraw) + 1023u) & ~1023u;
    const unsigned kvb = sb + 16384u;                       // KV stages
    const unsigned ctrl = kvb + 2u * 32768u;                // qbar, full[0], full[1]

    const int tid = threadIdx.x, lane = tid & 31, wid = tid >> 5;
    const int qt = gridDim.x - 1 - blockIdx.x;              // heavy tiles first
    const int bh = blockIdx.y;
    const int g = lane >> 2, tig = lane & 3;
    const int grow0 = bh * Tn;                              // row base in [BH*T, 64]

    if (tid == 0) { mbar_init(ctrl, 1); mbar_init(ctrl + 8, 1); mbar_init(ctrl + 16, 1); }
    __syncthreads();

    auto issue_kv = [&](int s) {   // tid 0 only
        const unsigned base = kvb + (unsigned)(s & 1) * 32768u;
        const unsigned mb = ctrl + 8u + (unsigned)(s & 1) * 8u;
        mbar_expect(mb, 32768u);
        const int y = grow0 + s * 64;
        tma2d(base,           &tKh, 0, y, mb);
        tma2d(base + 8192u,   &tKl, 0, y, mb);
        tma2d(base + 16384u,  &tVh, 0, y, mb);
        tma2d(base + 24576u,  &tVl, 0, y, mb);
    };
    if (tid == 0) {
        mbar_expect(ctrl, 16384u);
        tma2d(sb,          &tQh, 0, grow0 + qt * 64, ctrl);
        tma2d(sb + 8192u,  &tQl, 0, grow0 + qt * 64, ctrl);
        issue_kv(0);
        if (qt >= 1) issue_kv(1);
    }

    // Q fragments -> registers
    mbar_wait(ctrl, 0u);
    const int qrow = wid * 16 + (lane & 15);
    const unsigned qswz = (unsigned)((qrow & 7) << 4);
    unsigned aqh[4][4], aql[4][4];
#pragma unroll
    for (int ks = 0; ks < 4; ks++) {
        const unsigned ac = (unsigned)((lane >> 4) * 16 + ks * 32) ^ qswz;
        ldsm4(aqh[ks], sb + (unsigned)(qrow * 128) + ac);
        ldsm4(aql[ks], sb + 8192u + (unsigned)(qrow * 128) + ac);
    }

    const int brow = (lane & 7) + ((lane >> 4) << 3);
    const unsigned bbase0 = (unsigned)(brow * 128);
    const unsigned bcolb = (unsigned)(((lane >> 3) & 1) * 16);
    const unsigned bswz = (unsigned)((brow & 7) << 4);
    const int vrow = (((lane >> 3) & 1) << 3) + (lane & 7);
    const unsigned vbase0 = (unsigned)(vrow * 128);
    const unsigned vd2 = (unsigned)((lane >> 4) * 16);
    const unsigned vswz = (unsigned)((vrow & 7) << 4);

    float O[8][4];
#pragma unroll
    for (int i = 0; i < 8; i++)
#pragma unroll
        for (int q = 0; q < 4; q++) O[i][q] = 0.0f;
    float m0r = -1e30f, m1r = -1e30f, l0 = 0.0f, l1 = 0.0f;
    const int qrow_g = qt * 64 + wid * 16 + g;

    for (int kt = 0; kt <= qt; kt++) {
        const unsigned stb = kvb + (unsigned)(kt & 1) * 32768u;
        mbar_wait(ctrl + 8u + (unsigned)(kt & 1) * 8u, (unsigned)((kt >> 1) & 1));

        // ---- S = Q K^T (3-term) ----
        float sc[8][4];
#pragma unroll
        for (int i = 0; i < 8; i++)
#pragma unroll
            for (int q = 0; q < 4; q++) sc[i][q] = 0.0f;
#pragma unroll
        for (int ks = 0; ks < 4; ks++) {
            unsigned bkh[4][4], bkl[4][4];
            const unsigned bc = (bcolb + ks * 32) ^ bswz;
#pragma unroll
            for (int nb = 0; nb < 4; nb++) {
                ldsm4(bkh[nb], stb + bbase0 + nb * 2048u + bc);
                ldsm4(bkl[nb], stb + 8192u + bbase0 + nb * 2048u + bc);
            }
#pragma unroll
            for (int nb = 0; nb < 4; nb++) {
                mma16816(sc[2 * nb],     aqh[ks], &bkh[nb][0]);
                mma16816(sc[2 * nb + 1], aqh[ks], &bkh[nb][2]);
                mma16816(sc[2 * nb],     aql[ks], &bkh[nb][0]);
                mma16816(sc[2 * nb + 1], aql[ks], &bkh[nb][2]);
                mma16816(sc[2 * nb],     aqh[ks], &bkl[nb][0]);
                mma16816(sc[2 * nb + 1], aqh[ks], &bkl[nb][2]);
            }
        }

        if (kt == qt) {
            const int kb = kt * 64 + 2 * tig;
#pragma unroll
            for (int ni = 0; ni < 8; ni++) {
                const int key = kb + ni * 8;
                if (key > qrow_g)         sc[ni][0] = -1e30f;
                if (key + 1 > qrow_g)     sc[ni][1] = -1e30f;
                if (key > qrow_g + 8)     sc[ni][2] = -1e30f;
                if (key + 1 > qrow_g + 8) sc[ni][3] = -1e30f;
            }
        }

        // ---- online softmax ----
        float mx0 = -1e30f, mx1 = -1e30f;
#pragma unroll
        for (int ni = 0; ni < 8; ni++) {
            mx0 = fmaxf(mx0, fmaxf(sc[ni][0], sc[ni][1]));
            mx1 = fmaxf(mx1, fmaxf(sc[ni][2], sc[ni][3]));
        }
        mx0 = fmaxf(mx0, __shfl_xor_sync(0xFFFFFFFF, mx0, 1));
        mx0 = fmaxf(mx0, __shfl_xor_sync(0xFFFFFFFF, mx0, 2));
        mx1 = fmaxf(mx1, __shfl_xor_sync(0xFFFFFFFF, mx1, 1));
        mx1 = fmaxf(mx1, __shfl_xor_sync(0xFFFFFFFF, mx1, 2));
        const float nm0 = fmaxf(m0r, mx0), nm1 = fmaxf(m1r, mx1);
        const float cr0 = fexp(m0r - nm0), cr1 = fexp(m1r - nm1);
        m0r = nm0; m1r = nm1;
        l0 *= cr0; l1 *= cr1;
#pragma unroll
        for (int ni = 0; ni < 8; ni++) {
            O[ni][0] *= cr0; O[ni][1] *= cr0;
            O[ni][2] *= cr1; O[ni][3] *= cr1;
        }
        float ps0 = 0.0f, ps1 = 0.0f;
#pragma unroll
        for (int ni = 0; ni < 8; ni++) {
            sc[ni][0] = fexp(sc[ni][0] - nm0);
            sc[ni][1] = fexp(sc[ni][1] - nm0);
            sc[ni][2] = fexp(sc[ni][2] - nm1);
            sc[ni][3] = fexp(sc[ni][3] - nm1);
            ps0 += sc[ni][0] + sc[ni][1];
            ps1 += sc[ni][2] + sc[ni][3];
        }
        l0 += ps0; l1 += ps1;

        // ---- pack P (split) ----
        unsigned aph[4][4], apl[4][4];
#pragma unroll
        for (int j = 0; j < 4; j++) {
            float h00 = __bfloat162float(__float2bfloat16(sc[2 * j][0]));
            float h01 = __bfloat162float(__float2bfloat16(sc[2 * j][1]));
            float h02 = __bfloat162float(__float2bfloat16(sc[2 * j][2]));
            float h03 = __bfloat162float(__float2bfloat16(sc[2 * j][3]));
            float h10 = __bfloat162float(__float2bfloat16(sc[2 * j + 1][0]));
            float h11 = __bfloat162float(__float2bfloat16(sc[2 * j + 1][1]));
            float h12 = __bfloat162float(__float2bfloat16(sc[2 * j + 1][2]));
            float h13 = __bfloat162float(__float2bfloat16(sc[2 * j + 1][3]));
            aph[j][0] = packbf2(h00, h01);
            aph[j][1] = packbf2(h02, h03);
            aph[j][2] = packbf2(h10, h11);
            aph[j][3] = packbf2(h12, h13);
            apl[j][0] = packbf2(sc[2 * j][0] - h00, sc[2 * j][1] - h01);
            apl[j][1] = packbf2(sc[2 * j][2] - h02, sc[2 * j][3] - h03);
            apl[j][2] = packbf2(sc[2 * j + 1][0] - h10, sc[2 * j + 1][1] - h11);
            apl[j][3] = packbf2(sc[2 * j + 1][2] - h12, sc[2 * j + 1][3] - h13);
        }

        // ---- O += P V (3-term) ----
#pragma unroll
        for (int j = 0; j < 4; j++) {
#pragma unroll
            for (int db = 0; db < 4; db++) {
                unsigned vh[4], vl[4];
                const unsigned off = vbase0 + j * 2048u + ((db * 32u + vd2) ^ vswz);
                ldsm4t(vh, stb + 16384u + off);
                ldsm4t(vl, stb + 24576u + off);
                mma16816(O[2 * db],     aph[j], &vh[0]);
                mma16816(O[2 * db + 1], aph[j], &vh[2]);
                mma16816(O[2 * db],     apl[j], &vh[0]);
                mma16816(O[2 * db + 1], apl[j], &vh[2]);
                mma16816(O[2 * db],     aph[j], &vl[0]);
                mma16816(O[2 * db + 1], aph[j], &vl[2]);
            }
        }
        __syncthreads();
        if (tid == 0 && kt + 2 <= qt) issue_kv(kt + 2);
    }

    // ---- epilogue: split ao -> g_Ah / g_Al ----
    l0 += __shfl_xor_sync(0xFFFFFFFF, l0, 1);
    l0 += __shfl_xor_sync(0xFFFFFFFF, l0, 2);
    l1 += __shfl_xor_sync(0xFFFFFFFF, l1, 1);
    l1 += __shfl_xor_sync(0xFFFFFFFF, l1, 2);
    const float inv0 = 1.0f / l0, inv1 = 1.0f / l1;

    const int b = bh >> 4, h = bh & 15;
    const size_t r0 = (size_t)(b * Tn + qrow_g) * Cn;
    const size_t r1 = (size_t)(b * Tn + qrow_g + 8) * Cn;
#pragma unroll
    for (int ni = 0; ni < 8; ni++) {
        const int k = h * Dn + ni * 8 + 2 * tig;
        {
            const float v0 = O[ni][0] * inv0, v1 = O[ni][1] * inv0;
            const float h0 = __bfloat162float(__float2bfloat16(v0));
            const float h1 = __bfloat162float(__float2bfloat16(v1));
            *(unsigned*)&g_Ah[r0 + k] = packbf2(h0, h1);
            *(unsigned*)&g_Al[r0 + k] = packbf2(v0 - h0, v1 - h1);
        }
        {
            const float v0 = O[ni][2] * inv1, v1 = O[ni][3] * inv1;
            const float h0 = __bfloat162float(__float2bfloat16(v0));
            const float h1 = __bfloat162float(__float2bfloat16(v1));
            *(unsigned*)&g_Ah[r1 + k] = packbf2(h0, h1);
            *(unsigned*)&g_Al[r1 + k] = packbf2(v0 - h0, v1 - h1);
        }
    }
}

// ---------------- host ----------------
typedef CUresult (CUDAAPI* EncodeFn)(
    CUtensorMap*, CUtensorMapDataType, cuuint32_t, void*,
    const cuuint64_t*, const cuuint64_t*, const cuuint32_t*, const cuuint32_t*,
    CUtensorMapInterleave, CUtensorMapSwizzle, CUtensorMapL2promotion,
    CUtensorMapFloatOOBfill);

static void mk_map(EncodeFn enc, CUtensorMap* m, void* base,
                   unsigned long long rows, unsigned long long cols,
                   unsigned boxc, unsigned boxr)
{
    cuuint64_t dims[2] = {cols, rows};
    cuuint64_t strides[1] = {cols * 2};
    cuuint32_t box[2] = {boxc, boxr};
    cuuint32_t es[2] = {1, 1};
    enc(m, CU_TENSOR_MAP_DATA_TYPE_BFLOAT16, 2, base, dims, strides, box, es,
        CU_TENSOR_MAP_INTERLEAVE_NONE, CU_TENSOR_MAP_SWIZZLE_128B,
        CU_TENSOR_MAP_L2_PROMOTION_L2_128B, CU_TENSOR_MAP_FLOAT_OOB_FILL_NONE);
}

extern "C" void kernel_launch(void* const* d_in, const int* in_sizes, int n_in,
                              void* d_out, int out_size)
{
    const float* x     = (const float*)d_in[0];
    const float* w_qkv = (const float*)d_in[1];
    const float* w_out = (const float*)d_in[2];
    const float* b_out = (const float*)d_in[3];
    float* out = (float*)d_out;

    void *pAh, *pAl, *pB1h, *pB1l, *pB3h, *pB3l, *pQh, *pQl, *pKh, *pKl, *pVh, *pVl;
    cudaGetSymbolAddress(&pAh, g_Ah);   cudaGetSymbolAddress(&pAl, g_Al);
    cudaGetSymbolAddress(&pB1h, g_B1h); cudaGetSymbolAddress(&pB1l, g_B1l);
    cudaGetSymbolAddress(&pB3h, g_B3h); cudaGetSymbolAddress(&pB3l, g_B3l);
    cudaGetSymbolAddress(&pQh, g_qh);   cudaGetSymbolAddress(&pQl, g_ql);
    cudaGetSymbolAddress(&pKh, g_kh);   cudaGetSymbolAddress(&pKl, g_kl);
    cudaGetSymbolAddress(&pVh, g_vh);   cudaGetSymbolAddress(&pVl, g_vl);

    EncodeFn enc = nullptr;
    cudaDriverEntryPointQueryResult qr;
    cudaGetDriverEntryPointByVersion("cuTensorMapEncodeTiled", (void**)&enc,
                                     12000, cudaEnableDefault, &qr);

    const unsigned long long MR = (unsigned long long)Bn * Tn;        // 8192
    const unsigned long long KVR = (unsigned long long)Bn * Hn * Tn;  // 131072
    CUtensorMap mAh, mAl, mB1h, mB1l, mB3h, mB3l, mQh, mQl, mKh, mKl, mVh, mVl;
    mk_map(enc, &mAh, pAh, MR, 1024, 64, 128);
    mk_map(enc, &mAl, pAl, MR, 1024, 64, 128);
    mk_map(enc, &mB1h, pB1h, 3072, 1024, 64, 128);
    mk_map(enc, &mB1l, pB1l, 3072, 1024, 64, 128);
    mk_map(enc, &mB3h, pB3h, 1024, 1024, 64, 128);
    mk_map(enc, &mB3l, pB3l, 1024, 1024, 64, 128);
    mk_map(enc, &mQh, pQh, KVR, 64, 64, 64);
    mk_map(enc, &mQl, pQl, KVR, 64, 64, 64);
    mk_map(enc, &mKh, pKh, KVR, 64, 64, 64);
    mk_map(enc, &mKl, pKl, KVR, 64, 64, 64);
    mk_map(enc, &mVh, pVh, KVR, 64, 64, 64);
    mk_map(enc, &mVl, pVl, KVR, 64, 64, 64);

    cudaFuncSetAttribute(gemm_tma<0>, cudaFuncAttributeMaxDynamicSharedMemorySize, GEMM_SMEM);
    cudaFuncSetAttribute(gemm_tma<1>, cudaFuncAttributeMaxDynamicSharedMemorySize, GEMM_SMEM);
    cudaFuncSetAttribute(attn_tma, cudaFuncAttributeMaxDynamicSharedMemorySize, ATTN_SMEM);

    split2<<<(Bn * Tn * Cn) / 256, 256>>>(x, (__nv_bfloat16*)pAh, (__nv_bfloat16*)pAl);
    split2<<<(3 * Cn * Cn) / 256, 256>>>(w_qkv, (__nv_bfloat16*)pB1h, (__nv_bfloat16*)pB1l);
    split2<<<(Cn * Cn) / 256, 256>>>(w_out, (__nv_bfloat16*)pB3h, (__nv_bfloat16*)pB3l);
    gemm_tma<0><<<dim3(24, 64), 256, GEMM_SMEM>>>(mAh, mAl, mB1h, mB1l, nullptr, nullptr);
    attn_tma<<<dim3(Tn / 64, Bn * Hn), 128, ATTN_SMEM>>>(mQh, mQl, mKh, mKl, mVh, mVl);
    gemm_tma<1><<<dim3(8, 64), 256, GEMM_SMEM>>>(mAh, mAl, mB3h, mB3l, b_out, out);
}

// round 8
// speedup vs baseline: 6.2107x; 1.1371x over previous
#include <cuda.h>
#include <cuda_runtime.h>
#include <cuda_bf16.h>

namespace {
constexpr int Bn = 4, Tn = 2048, Cn = 1024, Hn = 16, Dn = 64;
constexpr unsigned GEMM_SMEM = 3 * 65536 + 1024 + 64;             // 3-stage ring
constexpr unsigned ATTN_SMEM = 32768 + 3 * 24576 + 1024 + 64;     // Q(2x16K) + 3 KV stages
}

// ---------------- scratch (device globals; no allocs allowed) ----------------
__device__ __align__(16) __nv_bfloat16 g_Ah[(size_t)Bn * Tn * Cn];
__device__ __align__(16) __nv_bfloat16 g_Al[(size_t)Bn * Tn * Cn];
__device__ __align__(16) __nv_bfloat16 g_B1h[(size_t)3 * Cn * Cn];
__device__ __align__(16) __nv_bfloat16 g_B1l[(size_t)3 * Cn * Cn];
__device__ __align__(16) __nv_bfloat16 g_B3h[(size_t)Cn * Cn];
__device__ __align__(16) __nv_bfloat16 g_B3l[(size_t)Cn * Cn];
__device__ __align__(16) __nv_bfloat16 g_qh[(size_t)Bn * Hn * Tn * Dn];  // [BH*T, 64]
__device__ __align__(16) __nv_bfloat16 g_ql[(size_t)Bn * Hn * Tn * Dn];
__device__ __align__(16) __nv_bfloat16 g_kh[(size_t)Bn * Hn * Tn * Dn];
__device__ __align__(16) __nv_bfloat16 g_kl[(size_t)Bn * Hn * Tn * Dn];
__device__ __align__(16) unsigned short g_vf[(size_t)Bn * Hn * Tn * Dn]; // fp16 V

// ---------------- device helpers ----------------
__device__ __forceinline__ unsigned smem_u32(const void* p) {
    unsigned a;
    asm("{ .reg .u64 t; cvta.to.shared.u64 t, %1; cvt.u32.u64 %0, t; }" : "=r"(a) : "l"(p));
    return a;
}
__device__ __forceinline__ void mbar_init(unsigned addr, unsigned cnt) {
    asm volatile("mbarrier.init.shared.b64 [%0], %1;" :: "r"(addr), "r"(cnt) : "memory");
}
__device__ __forceinline__ void mbar_expect(unsigned addr, unsigned bytes) {
    asm volatile("mbarrier.arrive.expect_tx.shared.b64 _, [%0], %1;"
                 :: "r"(addr), "r"(bytes) : "memory");
}
__device__ __forceinline__ void mbar_wait(unsigned addr, unsigned parity) {
    asm volatile(
        "{\n\t.reg .pred P;\n\t"
        "WL_%=:\n\t"
        "mbarrier.try_wait.parity.acquire.cta.shared::cta.b64 P, [%0], %1, 0x989680;\n\t"
        "@P bra.uni WD_%=;\n\t"
        "bra.uni WL_%=;\n\t"
        "WD_%=:\n\t}"
        :: "r"(addr), "r"(parity) : "memory");
}
__device__ __forceinline__ void tma2d(unsigned smem, const CUtensorMap* m,
                                      int x, int y, unsigned mbar) {
    asm volatile(
        "cp.async.bulk.tensor.2d.shared::cta.global.tile.mbarrier::complete_tx::bytes "
        "[%0], [%1, {%2, %3}], [%4];"
        :: "r"(smem), "l"(m), "r"(x), "r"(y), "r"(mbar) : "memory");
}
__device__ __forceinline__ void ldsm4(unsigned* r, unsigned addr) {
    asm volatile("ldmatrix.sync.aligned.m8n8.x4.shared.b16 {%0,%1,%2,%3}, [%4];"
        : "=r"(r[0]), "=r"(r[1]), "=r"(r[2]), "=r"(r[3]) : "r"(addr));
}
__device__ __forceinline__ void ldsm4t(unsigned* r, unsigned addr) {
    asm volatile("ldmatrix.sync.aligned.m8n8.x4.trans.shared.b16 {%0,%1,%2,%3}, [%4];"
        : "=r"(r[0]), "=r"(r[1]), "=r"(r[2]), "=r"(r[3]) : "r"(addr));
}
__device__ __forceinline__ void mma16816(float* c, const unsigned* a, const unsigned* b) {
    asm volatile("mma.sync.aligned.m16n8k16.row.col.f32.bf16.bf16.f32 "
        "{%0,%1,%2,%3}, {%4,%5,%6,%7}, {%8,%9}, {%0,%1,%2,%3};"
        : "+f"(c[0]), "+f"(c[1]), "+f"(c[2]), "+f"(c[3])
        : "r"(a[0]), "r"(a[1]), "r"(a[2]), "r"(a[3]), "r"(b[0]), "r"(b[1]));
}
__device__ __forceinline__ void mma16816h(float* c, const unsigned* a, const unsigned* b) {
    asm volatile("mma.sync.aligned.m16n8k16.row.col.f32.f16.f16.f32 "
        "{%0,%1,%2,%3}, {%4,%5,%6,%7}, {%8,%9}, {%0,%1,%2,%3};"
        : "+f"(c[0]), "+f"(c[1]), "+f"(c[2]), "+f"(c[3])
        : "r"(a[0]), "r"(a[1]), "r"(a[2]), "r"(a[3]), "r"(b[0]), "r"(b[1]));
}
__device__ __forceinline__ unsigned packbf2(float lo, float hi) {
    unsigned u;
    asm("cvt.rn.bf16x2.f32 %0, %1, %2;" : "=r"(u) : "f"(hi), "f"(lo));
    return u;
}
__device__ __forceinline__ unsigned packh2(float lo, float hi) {
    unsigned u;
    asm("{ .reg .b16 l, h; cvt.rn.f16.f32 l, %1; cvt.rn.f16.f32 h, %2; "
        "mov.b32 %0, {l, h}; }" : "=r"(u) : "f"(lo), "f"(hi));
    return u;
}
__device__ __forceinline__ float fexp(float x) {
    x = fmaxf(x, -80.0f);
    const float z = x * 1.4426950408889634f;
    const float zf = z + 12582912.0f;
    const int n = __float_as_int(zf);
    const float r = z - (zf - 12582912.0f);
    float p = 0.009618129f;
    p = fmaf(p, r, 0.05550411f);
    p = fmaf(p, r, 0.2402265f);
    p = fmaf(p, r, 0.6931472f);
    p = fmaf(p, r, 1.0f);
    return p * __int_as_float((n << 23) + 0x3F800000);
}

// ---------------- fp32 -> (h, l) bf16 split ----------------
__global__ __launch_bounds__(256) void split2(const float* __restrict__ src,
                                              __nv_bfloat16* __restrict__ dh,
                                              __nv_bfloat16* __restrict__ dl)
{
    const size_t i = (size_t)blockIdx.x * 256 + threadIdx.x;
    const float v = src[i];
    const __nv_bfloat16 h = __float2bfloat16(v);
    dh[i] = h;
    dl[i] = __float2bfloat16(v - __bfloat162float(h));
}

// ---------------- TMA HMMA GEMM, 3-stage ring ----------------
// MODE 0: write split q/k (bf16 h/l, q scaled 0.125) + V fp16. MODE 1: out+bias.
template <int MODE>
__global__ __launch_bounds__(256) void gemm_tma(
    const __grid_constant__ CUtensorMap tAh, const __grid_constant__ CUtensorMap tAl,
    const __grid_constant__ CUtensorMap tBh, const __grid_constant__ CUtensorMap tBl,
    const float* __restrict__ bias, float* __restrict__ out)
{
    extern __shared__ __align__(16) unsigned char smraw[];
    const unsigned sb = (smem_u32(smraw) + 1023u) & ~1023u;
    const unsigned ctrl = sb + 3u * 65536u;                 // full[0..2]

    const int tid = threadIdx.x, lane = tid & 31, wid = tid >> 5;
    const int wm = wid & 3, wn = wid >> 2;
    const int m0 = blockIdx.y * 128, n0 = blockIdx.x * 128;

    if (tid == 0) { mbar_init(ctrl, 1); mbar_init(ctrl + 8, 1); mbar_init(ctrl + 16, 1); }
    __syncthreads();

    auto issue = [&](int s) {   // tid 0 only
        const unsigned base = sb + (unsigned)(s % 3) * 65536u;
        const unsigned mb = ctrl + (unsigned)(s % 3) * 8u;
        mbar_expect(mb, 65536u);
        const int kc = s * 64;
        tma2d(base,           &tAh, kc, m0, mb);
        tma2d(base + 16384u,  &tAl, kc, m0, mb);
        tma2d(base + 32768u,  &tBh, kc, n0, mb);
        tma2d(base + 49152u,  &tBl, kc, n0, mb);
    };
    if (tid == 0) { issue(0); issue(1); issue(2); }

    const int arow = wm * 32 + (lane & 15);
    const unsigned abase0 = (unsigned)(arow * 128);
    const unsigned acolb = (unsigned)((lane >> 4) * 16);
    const unsigned aswz = (unsigned)((arow & 7) << 4);
    const int brow = wn * 64 + (lane & 7) + ((lane >> 4) << 3);
    const unsigned bbase0 = (unsigned)(brow * 128);
    const unsigned bcolb = (unsigned)(((lane >> 3) & 1) * 16);
    const unsigned bswz = (unsigned)((brow & 7) << 4);

    float acc[2][8][4];
#pragma unroll
    for (int i = 0; i < 2; i++)
#pragma unroll
        for (int j = 0; j < 8; j++)
#pragma unroll
            for (int q = 0; q < 4; q++) acc[i][j][q] = 0.0f;

    for (int s = 0; s < 16; s++) {                          // K = 1024 / 64
        const unsigned stb = sb + (unsigned)(s % 3) * 65536u;
        mbar_wait(ctrl + (unsigned)(s % 3) * 8u, (unsigned)((s / 3) & 1));
#pragma unroll
        for (int ks = 0; ks < 4; ks++) {
            unsigned ah[2][4], al[2][4], bh[4][4], bl[4][4];
            const unsigned ac = (acolb + ks * 32) ^ aswz;
#pragma unroll
            for (int mi = 0; mi < 2; mi++) {
                ldsm4(ah[mi], stb + abase0 + mi * 2048u + ac);
                ldsm4(al[mi], stb + 16384u + abase0 + mi * 2048u + ac);
            }
            const unsigned bc = (bcolb + ks * 32) ^ bswz;
#pragma unroll
            for (int nb = 0; nb < 4; nb++) {
                ldsm4(bh[nb], stb + 32768u + bbase0 + nb * 2048u + bc);
                ldsm4(bl[nb], stb + 49152u + bbase0 + nb * 2048u + bc);
            }
#pragma unroll
            for (int mi = 0; mi < 2; mi++)
#pragma unroll
                for (int nb = 0; nb < 4; nb++) {
                    mma16816(acc[mi][2 * nb],     ah[mi], &bh[nb][0]);
                    mma16816(acc[mi][2 * nb + 1], ah[mi], &bh[nb][2]);
                    mma16816(acc[mi][2 * nb],     al[mi], &bh[nb][0]);
                    mma16816(acc[mi][2 * nb + 1], al[mi], &bh[nb][2]);
                    mma16816(acc[mi][2 * nb],     ah[mi], &bl[nb][0]);
                    mma16816(acc[mi][2 * nb + 1], ah[mi], &bl[nb][2]);
                }
        }
        __syncthreads();
        if (tid == 0 && s + 3 < 16) issue(s + 3);
    }

    const int g = lane >> 2, tig = lane & 3;
    if (MODE == 0) {
        const int nblock = n0 + wn * 64;                    // one (sec, head)
        const int sec = nblock >> 10;
        const int h = (nblock & 1023) >> 6;
        if (sec == 2) {                                     // V -> fp16 single
#pragma unroll
            for (int mi = 0; mi < 2; mi++) {
                const int m1 = m0 + wm * 32 + mi * 16 + g;
                const int b = m1 >> 11, t = m1 & 2047;
                const size_t rb = (size_t)((b * Hn + h) * Tn + t) * Dn;
#pragma unroll
                for (int ni = 0; ni < 8; ni++) {
                    const int d = ni * 8 + 2 * tig;
#pragma unroll
                    for (int half = 0; half < 2; half++) {
                        const size_t o = rb + (size_t)half * 8 * Dn + d;
                        *(unsigned*)&g_vf[o] =
                            packh2(acc[mi][ni][2 * half], acc[mi][ni][2 * half + 1]);
                    }
                }
            }
        } else {                                            // q/k -> split bf16
            const float scale = (sec == 0) ? 0.125f : 1.0f;
            __nv_bfloat16* dh = (sec == 0) ? g_qh : g_kh;
            __nv_bfloat16* dl = (sec == 0) ? g_ql : g_kl;
#pragma unroll
            for (int mi = 0; mi < 2; mi++) {
                const int m1 = m0 + wm * 32 + mi * 16 + g;
                const int b = m1 >> 11, t = m1 & 2047;
                const size_t rb = (size_t)((b * Hn + h) * Tn + t) * Dn;
#pragma unroll
                for (int ni = 0; ni < 8; ni++) {
                    const int d = ni * 8 + 2 * tig;
#pragma unroll
                    for (int half = 0; half < 2; half++) {
                        const float v0 = acc[mi][ni][2 * half] * scale;
                        const float v1 = acc[mi][ni][2 * half + 1] * scale;
                        const float h0 = __bfloat162float(__float2bfloat16(v0));
                        const float h1 = __bfloat162float(__float2bfloat16(v1));
                        const size_t o = rb + (size_t)half * 8 * Dn + d;
                        *(unsigned*)&dh[o] = packbf2(h0, h1);
                        *(unsigned*)&dl[o] = packbf2(v0 - h0, v1 - h1);
                    }
                }
            }
        }
    } else {
#pragma unroll
        for (int mi = 0; mi < 2; mi++) {
            const int m1 = m0 + wm * 32 + mi * 16 + g;
#pragma unroll
            for (int ni = 0; ni < 8; ni++) {
                const int n = n0 + wn * 64 + ni * 8 + 2 * tig;
                const float2 bb = *(const float2*)(bias + n);
                float2 lo = {acc[mi][ni][0] + bb.x, acc[mi][ni][1] + bb.y};
                float2 hi = {acc[mi][ni][2] + bb.x, acc[mi][ni][3] + bb.y};
                *(float2*)(out + (size_t)m1 * Cn + n) = lo;
                *(float2*)(out + (size_t)(m1 + 8) * Cn + n) = hi;
            }
        }
    }
}

// ---------------- TMA flash attention: 128-row Q tile, 8 warps, fp16 PV ----------------
__global__ __launch_bounds__(256) void attn_tma(
    const __grid_constant__ CUtensorMap tQh, const __grid_constant__ CUtensorMap tQl,
    const __grid_constant__ CUtensorMap tKh, const __grid_constant__ CUtensorMap tKl,
    const __grid_constant__ CUtensorMap tVf)
{
    extern __shared__ __align__(16) unsigned char smraw[];
    const unsigned sb = (smem_u32(smraw) + 1023u) & ~1023u;
    const unsigned kvb = sb + 32768u;                       // 3 KV stages x 24576
    const unsigned ctrl = kvb + 3u * 24576u;                // qbar, full[0..2]

    const int tid = threadIdx.x, lane = tid & 31, wid = tid >> 5;
    const int qt = (int)gridDim.x - 1 - (int)blockIdx.x;    // heavy tiles first
    const int bh = blockIdx.y;
    const int g = lane >> 2, tig = lane & 3;
    const int grow0 = bh * Tn;
    const int nkt = 2 * qt + 2;

    if (tid == 0) {
        mbar_init(ctrl, 1); mbar_init(ctrl + 8, 1);
        mbar_init(ctrl + 16, 1); mbar_init(ctrl + 24, 1);
    }
    __syncthreads();

    auto issue_kv = [&](int s) {   // tid 0 only
        const unsigned base = kvb + (unsigned)(s % 3) * 24576u;
        const unsigned mb = ctrl + 8u + (unsigned)(s % 3) * 8u;
        mbar_expect(mb, 24576u);
        const int y = grow0 + s * 64;
        tma2d(base,           &tKh, 0, y, mb);
        tma2d(base + 8192u,   &tKl, 0, y, mb);
        tma2d(base + 16384u,  &tVf, 0, y, mb);
    };
    if (tid == 0) {
        mbar_expect(ctrl, 32768u);
        tma2d(sb,           &tQh, 0, grow0 + qt * 128, ctrl);
        tma2d(sb + 16384u,  &tQl, 0, grow0 + qt * 128, ctrl);
        issue_kv(0); issue_kv(1);
        if (nkt > 2) issue_kv(2);
    }

    // Q fragments -> registers (warp w owns rows w*16..+15)
    mbar_wait(ctrl, 0u);
    const int qrow = wid * 16 + (lane & 15);
    const unsigned qswz = (unsigned)((qrow & 7) << 4);
    unsigned aqh[4][4], aql[4][4];
#pragma unroll
    for (int ks = 0; ks < 4; ks++) {
        const unsigned ac = (unsigned)((lane >> 4) * 16 + ks * 32) ^ qswz;
        ldsm4(aqh[ks], sb + (unsigned)(qrow * 128) + ac);
        ldsm4(aql[ks], sb + 16384u + (unsigned)(qrow * 128) + ac);
    }

    const int brow = (lane & 7) + ((lane >> 4) << 3);
    const unsigned bbase0 = (unsigned)(brow * 128);
    const unsigned bcolb = (unsigned)(((lane >> 3) & 1) * 16);
    const unsigned bswz = (unsigned)((brow & 7) << 4);
    const int vrow = (((lane >> 3) & 1) << 3) + (lane & 7);
    const unsigned vbase0 = (unsigned)(vrow * 128);
    const unsigned vd2 = (unsigned)((lane >> 4) * 16);
    const unsigned vswz = (unsigned)((vrow & 7) << 4);

    float O[8][4];
#pragma unroll
    for (int i = 0; i < 8; i++)
#pragma unroll
        for (int q = 0; q < 4; q++) O[i][q] = 0.0f;
    float m0r = -1e30f, m1r = -1e30f, l0 = 0.0f, l1 = 0.0f;
    const int qrow_g = qt * 128 + wid * 16 + g;

    for (int kt = 0; kt < nkt; kt++) {
        const unsigned stb = kvb + (unsigned)(kt % 3) * 24576u;
        mbar_wait(ctrl + 8u + (unsigned)(kt % 3) * 8u, (unsigned)((kt / 3) & 1));

        // ---- S = Q K^T (3-term bf16) ----
        float sc[8][4];
#pragma unroll
        for (int i = 0; i < 8; i++)
#pragma unroll
            for (int q = 0; q < 4; q++) sc[i][q] = 0.0f;
#pragma unroll
        for (int ks = 0; ks < 4; ks++) {
            unsigned bkh[4][4], bkl[4][4];
            const unsigned bc = (bcolb + ks * 32) ^ bswz;
#pragma unroll
            for (int nb = 0; nb < 4; nb++) {
                ldsm4(bkh[nb], stb + bbase0 + nb * 2048u + bc);
                ldsm4(bkl[nb], stb + 8192u + bbase0 + nb * 2048u + bc);
            }
#pragma unroll
            for (int nb = 0; nb < 4; nb++) {
                mma16816(sc[2 * nb],     aqh[ks], &bkh[nb][0]);
                mma16816(sc[2 * nb + 1], aqh[ks], &bkh[nb][2]);
                mma16816(sc[2 * nb],     aql[ks], &bkh[nb][0]);
                mma16816(sc[2 * nb + 1], aql[ks], &bkh[nb][2]);
                mma16816(sc[2 * nb],     aqh[ks], &bkl[nb][0]);
                mma16816(sc[2 * nb + 1], aqh[ks], &bkl[nb][2]);
            }
        }

        if (kt >= 2 * qt) {                     // diagonal band -> causal mask
            const int kb = kt * 64 + 2 * tig;
#pragma unroll
            for (int ni = 0; ni < 8; ni++) {
                const int key = kb + ni * 8;
                if (key > qrow_g)         sc[ni][0] = -1e30f;
                if (key + 1 > qrow_g)     sc[ni][1] = -1e30f;
                if (key > qrow_g + 8)     sc[ni][2] = -1e30f;
                if (key + 1 > qrow_g + 8) sc[ni][3] = -1e30f;
            }
        }

        // ---- online softmax ----
        float mx0 = -1e30f, mx1 = -1e30f;
#pragma unroll
        for (int ni = 0; ni < 8; ni++) {
            mx0 = fmaxf(mx0, fmaxf(sc[ni][0], sc[ni][1]));
            mx1 = fmaxf(mx1, fmaxf(sc[ni][2], sc[ni][3]));
        }
        mx0 = fmaxf(mx0, __shfl_xor_sync(0xFFFFFFFF, mx0, 1));
        mx0 = fmaxf(mx0, __shfl_xor_sync(0xFFFFFFFF, mx0, 2));
        mx1 = fmaxf(mx1, __shfl_xor_sync(0xFFFFFFFF, mx1, 1));
        mx1 = fmaxf(mx1, __shfl_xor_sync(0xFFFFFFFF, mx1, 2));
        const float nm0 = fmaxf(m0r, mx0), nm1 = fmaxf(m1r, mx1);
        const float cr0 = fexp(m0r - nm0), cr1 = fexp(m1r - nm1);
        m0r = nm0; m1r = nm1;
        l0 *= cr0; l1 *= cr1;
#pragma unroll
        for (int ni = 0; ni < 8; ni++) {
            O[ni][0] *= cr0; O[ni][1] *= cr0;
            O[ni][2] *= cr1; O[ni][3] *= cr1;
        }
        float ps0 = 0.0f, ps1 = 0.0f;
#pragma unroll
        for (int ni = 0; ni < 8; ni++) {
            sc[ni][0] = fexp(sc[ni][0] - nm0);
            sc[ni][1] = fexp(sc[ni][1] - nm0);
            sc[ni][2] = fexp(sc[ni][2] - nm1);
            sc[ni][3] = fexp(sc[ni][3] - nm1);
            ps0 += sc[ni][0] + sc[ni][1];
            ps1 += sc[ni][2] + sc[ni][3];
        }
        l0 += ps0; l1 += ps1;

        // ---- pack P as fp16 (single term) ----
        unsigned apf[4][4];
#pragma unroll
        for (int j = 0; j < 4; j++) {
            apf[j][0] = packh2(sc[2 * j][0], sc[2 * j][1]);
            apf[j][1] = packh2(sc[2 * j][2], sc[2 * j][3]);
            apf[j][2] = packh2(sc[2 * j + 1][0], sc[2 * j + 1][1]);
            apf[j][3] = packh2(sc[2 * j + 1][2], sc[2 * j + 1][3]);
        }

        // ---- O += P V (fp16 1-term) ----
#pragma unroll
        for (int j = 0; j < 4; j++) {
#pragma unroll
            for (int db = 0; db < 4; db++) {
                unsigned vf[4];
                const unsigned off = vbase0 + j * 2048u + ((db * 32u + vd2) ^ vswz);
                ldsm4t(vf, stb + 16384u + off);
                mma16816h(O[2 * db],     apf[j], &vf[0]);
                mma16816h(O[2 * db + 1], apf[j], &vf[2]);
            }
        }
        __syncthreads();
        if (tid == 0 && kt + 3 < nkt) issue_kv(kt + 3);
    }

    // ---- epilogue: split ao -> g_Ah / g_Al ----
    l0 += __shfl_xor_sync(0xFFFFFFFF, l0, 1);
    l0 += __shfl_xor_sync(0xFFFFFFFF, l0, 2);
    l1 += __shfl_xor_sync(0xFFFFFFFF, l1, 1);
    l1 += __shfl_xor_sync(0xFFFFFFFF, l1, 2);
    const float inv0 = 1.0f / l0, inv1 = 1.0f / l1;

    const int b = bh >> 4, h = bh & 15;
    const size_t r0 = (size_t)(b * Tn + qrow_g) * Cn;
    const size_t r1 = (size_t)(b * Tn + qrow_g + 8) * Cn;
#pragma unroll
    for (int ni = 0; ni < 8; ni++) {
        const int k = h * Dn + ni * 8 + 2 * tig;
        {
            const float v0 = O[ni][0] * inv0, v1 = O[ni][1] * inv0;
            const float h0 = __bfloat162float(__float2bfloat16(v0));
            const float h1 = __bfloat162float(__float2bfloat16(v1));
            *(unsigned*)&g_Ah[r0 + k] = packbf2(h0, h1);
            *(unsigned*)&g_Al[r0 + k] = packbf2(v0 - h0, v1 - h1);
        }
        {
            const float v0 = O[ni][2] * inv1, v1 = O[ni][3] * inv1;
            const float h0 = __bfloat162float(__float2bfloat16(v0));
            const float h1 = __bfloat162float(__float2bfloat16(v1));
            *(unsigned*)&g_Ah[r1 + k] = packbf2(h0, h1);
            *(unsigned*)&g_Al[r1 + k] = packbf2(v0 - h0, v1 - h1);
        }
    }
}

// ---------------- host ----------------
typedef CUresult (CUDAAPI* EncodeFn)(
    CUtensorMap*, CUtensorMapDataType, cuuint32_t, void*,
    const cuuint64_t*, const cuuint64_t*, const cuuint32_t*, const cuuint32_t*,
    CUtensorMapInterleave, CUtensorMapSwizzle, CUtensorMapL2promotion,
    CUtensorMapFloatOOBfill);

static void mk_map(EncodeFn enc, CUtensorMap* m, void* base, CUtensorMapDataType dt,
                   unsigned long long rows, unsigned long long cols,
                   unsigned boxc, unsigned boxr)
{
    cuuint64_t dims[2] = {cols, rows};
    cuuint64_t strides[1] = {cols * 2};
    cuuint32_t box[2] = {boxc, boxr};
    cuuint32_t es[2] = {1, 1};
    enc(m, dt, 2, base, dims, strides, box, es,
        CU_TENSOR_MAP_INTERLEAVE_NONE, CU_TENSOR_MAP_SWIZZLE_128B,
        CU_TENSOR_MAP_L2_PROMOTION_L2_128B, CU_TENSOR_MAP_FLOAT_OOB_FILL_NONE);
}

extern "C" void kernel_launch(void* const* d_in, const int* in_sizes, int n_in,
                              void* d_out, int out_size)
{
    const float* x     = (const float*)d_in[0];
    const float* w_qkv = (const float*)d_in[1];
    const float* w_out = (const float*)d_in[2];
    const float* b_out = (const float*)d_in[3];
    float* out = (float*)d_out;

    void *pAh, *pAl, *pB1h, *pB1l, *pB3h, *pB3l, *pQh, *pQl, *pKh, *pKl, *pVf;
    cudaGetSymbolAddress(&pAh, g_Ah);   cudaGetSymbolAddress(&pAl, g_Al);
    cudaGetSymbolAddress(&pB1h, g_B1h); cudaGetSymbolAddress(&pB1l, g_B1l);
    cudaGetSymbolAddress(&pB3h, g_B3h); cudaGetSymbolAddress(&pB3l, g_B3l);
    cudaGetSymbolAddress(&pQh, g_qh);   cudaGetSymbolAddress(&pQl, g_ql);
    cudaGetSymbolAddress(&pKh, g_kh);   cudaGetSymbolAddress(&pKl, g_kl);
    cudaGetSymbolAddress(&pVf, g_vf);

    EncodeFn enc = nullptr;
    cudaDriverEntryPointQueryResult qr;
    cudaGetDriverEntryPointByVersion("cuTensorMapEncodeTiled", (void**)&enc,
                                     12000, cudaEnableDefault, &qr);

    const auto BF = CU_TENSOR_MAP_DATA_TYPE_BFLOAT16;
    const auto F16 = CU_TENSOR_MAP_DATA_TYPE_FLOAT16;
    const unsigned long long MR = (unsigned long long)Bn * Tn;        // 8192
    const unsigned long long KVR = (unsigned long long)Bn * Hn * Tn;  // 131072
    CUtensorMap mAh, mAl, mB1h, mB1l, mB3h, mB3l, mQh, mQl, mKh, mKl, mVf;
    mk_map(enc, &mAh, pAh, BF, MR, 1024, 64, 128);
    mk_map(enc, &mAl, pAl, BF, MR, 1024, 64, 128);
    mk_map(enc, &mB1h, pB1h, BF, 3072, 1024, 64, 128);
    mk_map(enc, &mB1l, pB1l, BF, 3072, 1024, 64, 128);
    mk_map(enc, &mB3h, pB3h, BF, 1024, 1024, 64, 128);
    mk_map(enc, &mB3l, pB3l, BF, 1024, 1024, 64, 128);
    mk_map(enc, &mQh, pQh, BF, KVR, 64, 64, 128);
    mk_map(enc, &mQl, pQl, BF, KVR, 64, 64, 128);
    mk_map(enc, &mKh, pKh, BF, KVR, 64, 64, 64);
    mk_map(enc, &mKl, pKl, BF, KVR, 64, 64, 64);
    mk_map(enc, &mVf, pVf, F16, KVR, 64, 64, 64);

    cudaFuncSetAttribute(gemm_tma<0>, cudaFuncAttributeMaxDynamicSharedMemorySize, GEMM_SMEM);
    cudaFuncSetAttribute(gemm_tma<1>, cudaFuncAttributeMaxDynamicSharedMemorySize, GEMM_SMEM);
    cudaFuncSetAttribute(attn_tma, cudaFuncAttributeMaxDynamicSharedMemorySize, ATTN_SMEM);

    split2<<<(Bn * Tn * Cn) / 256, 256>>>(x, (__nv_bfloat16*)pAh, (__nv_bfloat16*)pAl);
    split2<<<(3 * Cn * Cn) / 256, 256>>>(w_qkv, (__nv_bfloat16*)pB1h, (__nv_bfloat16*)pB1l);
    split2<<<(Cn * Cn) / 256, 256>>>(w_out, (__nv_bfloat16*)pB3h, (__nv_bfloat16*)pB3l);
    gemm_tma<0><<<dim3(24, 64), 256, GEMM_SMEM>>>(mAh, mAl, mB1h, mB1l, nullptr, nullptr);
    attn_tma<<<dim3(Tn / 128, Bn * Hn), 256, ATTN_SMEM>>>(mQh, mQl, mKh, mKl, mVf);
    gemm_tma<1><<<dim3(8, 64), 256, GEMM_SMEM>>>(mAh, mAl, mB3h, mB3l, b_out, out);
}

// round 9
// speedup vs baseline: 9.6354x; 1.5514x over previous
#include <cuda.h>
#include <cuda_runtime.h>
#include <cuda_bf16.h>

namespace {
constexpr int Bn = 4, Tn = 2048, Cn = 1024, Hn = 16, Dn = 64;
constexpr unsigned GEMM_SMEM = 4 * 32768 + 1024 + 64;             // 4-stage ring (Af+Bf)
constexpr unsigned ATTN_SMEM = 32768 + 3 * 24576 + 1024 + 64;     // Q(2x16K) + 3 KV stages
}

// ---------------- scratch (device globals; no allocs allowed) ----------------
__device__ __align__(16) unsigned short g_xf[(size_t)Bn * Tn * Cn];     // fp16 x
__device__ __align__(16) unsigned short g_w1f[(size_t)3 * Cn * Cn];     // fp16 w_qkv
__device__ __align__(16) unsigned short g_w3f[(size_t)Cn * Cn];         // fp16 w_out
__device__ __align__(16) unsigned short g_aof[(size_t)Bn * Tn * Cn];    // fp16 attn out
__device__ __align__(16) __nv_bfloat16 g_qh[(size_t)Bn * Hn * Tn * Dn]; // [BH*T, 64]
__device__ __align__(16) __nv_bfloat16 g_ql[(size_t)Bn * Hn * Tn * Dn];
__device__ __align__(16) __nv_bfloat16 g_kh[(size_t)Bn * Hn * Tn * Dn];
__device__ __align__(16) __nv_bfloat16 g_kl[(size_t)Bn * Hn * Tn * Dn];
__device__ __align__(16) unsigned short g_vf[(size_t)Bn * Hn * Tn * Dn]; // fp16 V

// ---------------- device helpers ----------------
__device__ __forceinline__ unsigned smem_u32(const void* p) {
    unsigned a;
    asm("{ .reg .u64 t; cvta.to.shared.u64 t, %1; cvt.u32.u64 %0, t; }" : "=r"(a) : "l"(p));
    return a;
}
__device__ __forceinline__ void mbar_init(unsigned addr, unsigned cnt) {
    asm volatile("mbarrier.init.shared.b64 [%0], %1;" :: "r"(addr), "r"(cnt) : "memory");
}
__device__ __forceinline__ void mbar_expect(unsigned addr, unsigned bytes) {
    asm volatile("mbarrier.arrive.expect_tx.shared.b64 _, [%0], %1;"
                 :: "r"(addr), "r"(bytes) : "memory");
}
__device__ __forceinline__ void mbar_wait(unsigned addr, unsigned parity) {
    asm volatile(
        "{\n\t.reg .pred P;\n\t"
        "WL_%=:\n\t"
        "mbarrier.try_wait.parity.acquire.cta.shared::cta.b64 P, [%0], %1, 0x989680;\n\t"
        "@P bra.uni WD_%=;\n\t"
        "bra.uni WL_%=;\n\t"
        "WD_%=:\n\t}"
        :: "r"(addr), "r"(parity) : "memory");
}
__device__ __forceinline__ void tma2d(unsigned smem, const CUtensorMap* m,
                                      int x, int y, unsigned mbar) {
    asm volatile(
        "cp.async.bulk.tensor.2d.shared::cta.global.tile.mbarrier::complete_tx::bytes "
        "[%0], [%1, {%2, %3}], [%4];"
        :: "r"(smem), "l"(m), "r"(x), "r"(y), "r"(mbar) : "memory");
}
__device__ __forceinline__ void ldsm4(unsigned* r, unsigned addr) {
    asm volatile("ldmatrix.sync.aligned.m8n8.x4.shared.b16 {%0,%1,%2,%3}, [%4];"
        : "=r"(r[0]), "=r"(r[1]), "=r"(r[2]), "=r"(r[3]) : "r"(addr));
}
__device__ __forceinline__ void ldsm4t(unsigned* r, unsigned addr) {
    asm volatile("ldmatrix.sync.aligned.m8n8.x4.trans.shared.b16 {%0,%1,%2,%3}, [%4];"
        : "=r"(r[0]), "=r"(r[1]), "=r"(r[2]), "=r"(r[3]) : "r"(addr));
}
__device__ __forceinline__ void mma16816(float* c, const unsigned* a, const unsigned* b) {
    asm volatile("mma.sync.aligned.m16n8k16.row.col.f32.bf16.bf16.f32 "
        "{%0,%1,%2,%3}, {%4,%5,%6,%7}, {%8,%9}, {%0,%1,%2,%3};"
        : "+f"(c[0]), "+f"(c[1]), "+f"(c[2]), "+f"(c[3])
        : "r"(a[0]), "r"(a[1]), "r"(a[2]), "r"(a[3]), "r"(b[0]), "r"(b[1]));
}
__device__ __forceinline__ void mma16816h(float* c, const unsigned* a, const unsigned* b) {
    asm volatile("mma.sync.aligned.m16n8k16.row.col.f32.f16.f16.f32 "
        "{%0,%1,%2,%3}, {%4,%5,%6,%7}, {%8,%9}, {%0,%1,%2,%3};"
        : "+f"(c[0]), "+f"(c[1]), "+f"(c[2]), "+f"(c[3])
        : "r"(a[0]), "r"(a[1]), "r"(a[2]), "r"(a[3]), "r"(b[0]), "r"(b[1]));
}
__device__ __forceinline__ unsigned packbf2(float lo, float hi) {
    unsigned u;
    asm("cvt.rn.bf16x2.f32 %0, %1, %2;" : "=r"(u) : "f"(hi), "f"(lo));
    return u;
}
__device__ __forceinline__ unsigned packh2(float lo, float hi) {
    unsigned u;
    asm("{ .reg .b16 l, h; cvt.rn.f16.f32 l, %1; cvt.rn.f16.f32 h, %2; "
        "mov.b32 %0, {l, h}; }" : "=r"(u) : "f"(lo), "f"(hi));
    return u;
}
__device__ __forceinline__ float fexp(float x) {
    x = fmaxf(x, -80.0f);
    const float z = x * 1.4426950408889634f;
    const float zf = z + 12582912.0f;
    const int n = __float_as_int(zf);
    const float r = z - (zf - 12582912.0f);
    float p = 0.009618129f;
    p = fmaf(p, r, 0.05550411f);
    p = fmaf(p, r, 0.2402265f);
    p = fmaf(p, r, 0.6931472f);
    p = fmaf(p, r, 1.0f);
    return p * __int_as_float((n << 23) + 0x3F800000);
}

// ---------------- fp32 -> fp16 convert ----------------
__global__ __launch_bounds__(256) void tof16(const float* __restrict__ src,
                                             unsigned short* __restrict__ dst)
{
    const size_t i = ((size_t)blockIdx.x * 256 + threadIdx.x) * 2;
    const float2 v = *(const float2*)(src + i);
    *(unsigned*)(dst + i) = packh2(v.x, v.y);
}

// ---------------- TMA fp16 HMMA GEMM, 4-stage ring ----------------
// MODE 0: A=xf, B=w1f -> write split q/k (bf16 h/l, q scaled 0.125) + V fp16.
// MODE 1: A=aof, B=w3f -> out = C + bias.
template <int MODE>
__global__ __launch_bounds__(256) void gemm_tma(
    const __grid_constant__ CUtensorMap tA, const __grid_constant__ CUtensorMap tB,
    const float* __restrict__ bias, float* __restrict__ out)
{
    extern __shared__ __align__(16) unsigned char smraw[];
    const unsigned sb = (smem_u32(smraw) + 1023u) & ~1023u;
    const unsigned ctrl = sb + 4u * 32768u;                 // full[0..3]

    const int tid = threadIdx.x, lane = tid & 31, wid = tid >> 5;
    const int wm = wid & 3, wn = wid >> 2;
    const int m0 = blockIdx.y * 128, n0 = blockIdx.x * 128;

    if (tid == 0) {
        mbar_init(ctrl, 1); mbar_init(ctrl + 8, 1);
        mbar_init(ctrl + 16, 1); mbar_init(ctrl + 24, 1);
    }
    __syncthreads();

    auto issue = [&](int s) {   // tid 0 only
        const unsigned base = sb + (unsigned)(s & 3) * 32768u;
        const unsigned mb = ctrl + (unsigned)(s & 3) * 8u;
        mbar_expect(mb, 32768u);
        const int kc = s * 64;
        tma2d(base,           &tA, kc, m0, mb);
        tma2d(base + 16384u,  &tB, kc, n0, mb);
    };
    if (tid == 0) { issue(0); issue(1); issue(2); issue(3); }

    const int arow = wm * 32 + (lane & 15);
    const unsigned abase0 = (unsigned)(arow * 128);
    const unsigned acolb = (unsigned)((lane >> 4) * 16);
    const unsigned aswz = (unsigned)((arow & 7) << 4);
    const int brow = wn * 64 + (lane & 7) + ((lane >> 4) << 3);
    const unsigned bbase0 = (unsigned)(brow * 128);
    const unsigned bcolb = (unsigned)(((lane >> 3) & 1) * 16);
    const unsigned bswz = (unsigned)((brow & 7) << 4);

    float acc[2][8][4];
#pragma unroll
    for (int i = 0; i < 2; i++)
#pragma unroll
        for (int j = 0; j < 8; j++)
#pragma unroll
            for (int q = 0; q < 4; q++) acc[i][j][q] = 0.0f;

    for (int s = 0; s < 16; s++) {                          // K = 1024 / 64
        const unsigned stb = sb + (unsigned)(s & 3) * 32768u;
        mbar_wait(ctrl + (unsigned)(s & 3) * 8u, (unsigned)((s >> 2) & 1));
#pragma unroll
        for (int ks = 0; ks < 4; ks++) {
            unsigned af[2][4], bf[4][4];
            const unsigned ac = (acolb + ks * 32) ^ aswz;
#pragma unroll
            for (int mi = 0; mi < 2; mi++)
                ldsm4(af[mi], stb + abase0 + mi * 2048u + ac);
            const unsigned bc = (bcolb + ks * 32) ^ bswz;
#pragma unroll
            for (int nb = 0; nb < 4; nb++)
                ldsm4(bf[nb], stb + 16384u + bbase0 + nb * 2048u + bc);
#pragma unroll
            for (int mi = 0; mi < 2; mi++)
#pragma unroll
                for (int nb = 0; nb < 4; nb++) {
                    mma16816h(acc[mi][2 * nb],     af[mi], &bf[nb][0]);
                    mma16816h(acc[mi][2 * nb + 1], af[mi], &bf[nb][2]);
                }
        }
        __syncthreads();
        if (tid == 0 && s + 4 < 16) issue(s + 4);
    }

    const int g = lane >> 2, tig = lane & 3;
    if (MODE == 0) {
        const int nblock = n0 + wn * 64;                    // one (sec, head)
        const int sec = nblock >> 10;
        const int h = (nblock & 1023) >> 6;
        if (sec == 2) {                                     // V -> fp16 single
#pragma unroll
            for (int mi = 0; mi < 2; mi++) {
                const int m1 = m0 + wm * 32 + mi * 16 + g;
                const int b = m1 >> 11, t = m1 & 2047;
                const size_t rb = (size_t)((b * Hn + h) * Tn + t) * Dn;
#pragma unroll
                for (int ni = 0; ni < 8; ni++) {
                    const int d = ni * 8 + 2 * tig;
#pragma unroll
                    for (int half = 0; half < 2; half++) {
                        const size_t o = rb + (size_t)half * 8 * Dn + d;
                        *(unsigned*)&g_vf[o] =
                            packh2(acc[mi][ni][2 * half], acc[mi][ni][2 * half + 1]);
                    }
                }
            }
        } else {                                            // q/k -> split bf16
            const float scale = (sec == 0) ? 0.125f : 1.0f;
            __nv_bfloat16* dh = (sec == 0) ? g_qh : g_kh;
            __nv_bfloat16* dl = (sec == 0) ? g_ql : g_kl;
#pragma unroll
            for (int mi = 0; mi < 2; mi++) {
                const int m1 = m0 + wm * 32 + mi * 16 + g;
                const int b = m1 >> 11, t = m1 & 2047;
                const size_t rb = (size_t)((b * Hn + h) * Tn + t) * Dn;
#pragma unroll
                for (int ni = 0; ni < 8; ni++) {
                    const int d = ni * 8 + 2 * tig;
#pragma unroll
                    for (int half = 0; half < 2; half++) {
                        const float v0 = acc[mi][ni][2 * half] * scale;
                        const float v1 = acc[mi][ni][2 * half + 1] * scale;
                        const float h0 = __bfloat162float(__float2bfloat16(v0));
                        const float h1 = __bfloat162float(__float2bfloat16(v1));
                        const size_t o = rb + (size_t)half * 8 * Dn + d;
                        *(unsigned*)&dh[o] = packbf2(h0, h1);
                        *(unsigned*)&dl[o] = packbf2(v0 - h0, v1 - h1);
                    }
                }
            }
        }
    } else {
#pragma unroll
        for (int mi = 0; mi < 2; mi++) {
            const int m1 = m0 + wm * 32 + mi * 16 + g;
#pragma unroll
            for (int ni = 0; ni < 8; ni++) {
                const int n = n0 + wn * 64 + ni * 8 + 2 * tig;
                const float2 bb = *(const float2*)(bias + n);
                float2 lo = {acc[mi][ni][0] + bb.x, acc[mi][ni][1] + bb.y};
                float2 hi = {acc[mi][ni][2] + bb.x, acc[mi][ni][3] + bb.y};
                *(float2*)(out + (size_t)m1 * Cn + n) = lo;
                *(float2*)(out + (size_t)(m1 + 8) * Cn + n) = hi;
            }
        }
    }
}

// ---------------- TMA flash attention: 128-row Q tile, 8 warps, fp16 PV ----------------
__global__ __launch_bounds__(256) void attn_tma(
    const __grid_constant__ CUtensorMap tQh, const __grid_constant__ CUtensorMap tQl,
    const __grid_constant__ CUtensorMap tKh, const __grid_constant__ CUtensorMap tKl,
    const __grid_constant__ CUtensorMap tVf)
{
    extern __shared__ __align__(16) unsigned char smraw[];
    const unsigned sb = (smem_u32(smraw) + 1023u) & ~1023u;
    const unsigned kvb = sb + 32768u;                       // 3 KV stages x 24576
    const unsigned ctrl = kvb + 3u * 24576u;                // qbar, full[0..2]

    const int tid = threadIdx.x, lane = tid & 31, wid = tid >> 5;
    const int qt = (int)gridDim.x - 1 - (int)blockIdx.x;    // heavy tiles first
    const int bh = blockIdx.y;
    const int g = lane >> 2, tig = lane & 3;
    const int grow0 = bh * Tn;
    const int nkt = 2 * qt + 2;

    if (tid == 0) {
        mbar_init(ctrl, 1); mbar_init(ctrl + 8, 1);
        mbar_init(ctrl + 16, 1); mbar_init(ctrl + 24, 1);
    }
    __syncthreads();

    auto issue_kv = [&](int s) {   // tid 0 only
        const unsigned base = kvb + (unsigned)(s % 3) * 24576u;
        const unsigned mb = ctrl + 8u + (unsigned)(s % 3) * 8u;
        mbar_expect(mb, 24576u);
        const int y = grow0 + s * 64;
        tma2d(base,           &tKh, 0, y, mb);
        tma2d(base + 8192u,   &tKl, 0, y, mb);
        tma2d(base + 16384u,  &tVf, 0, y, mb);
    };
    if (tid == 0) {
        mbar_expect(ctrl, 32768u);
        tma2d(sb,           &tQh, 0, grow0 + qt * 128, ctrl);
        tma2d(sb + 16384u,  &tQl, 0, grow0 + qt * 128, ctrl);
        issue_kv(0); issue_kv(1);
        if (nkt > 2) issue_kv(2);
    }

    // Q fragments -> registers (warp w owns rows w*16..+15)
    mbar_wait(ctrl, 0u);
    const int qrow = wid * 16 + (lane & 15);
    const unsigned qswz = (unsigned)((qrow & 7) << 4);
    unsigned aqh[4][4], aql[4][4];
#pragma unroll
    for (int ks = 0; ks < 4; ks++) {
        const unsigned ac = (unsigned)((lane >> 4) * 16 + ks * 32) ^ qswz;
        ldsm4(aqh[ks], sb + (unsigned)(qrow * 128) + ac);
        ldsm4(aql[ks], sb + 16384u + (unsigned)(qrow * 128) + ac);
    }

    const int brow = (lane & 7) + ((lane >> 4) << 3);
    const unsigned bbase0 = (unsigned)(brow * 128);
    const unsigned bcolb = (unsigned)(((lane >> 3) & 1) * 16);
    const unsigned bswz = (unsigned)((brow & 7) << 4);
    const int vrow = (((lane >> 3) & 1) << 3) + (lane & 7);
    const unsigned vbase0 = (unsigned)(vrow * 128);
    const unsigned vd2 = (unsigned)((lane >> 4) * 16);
    const unsigned vswz = (unsigned)((vrow & 7) << 4);

    float O[8][4];
#pragma unroll
    for (int i = 0; i < 8; i++)
#pragma unroll
        for (int q = 0; q < 4; q++) O[i][q] = 0.0f;
    float m0r = -1e30f, m1r = -1e30f, l0 = 0.0f, l1 = 0.0f;
    const int qrow_g = qt * 128 + wid * 16 + g;

    for (int kt = 0; kt < nkt; kt++) {
        const unsigned stb = kvb + (unsigned)(kt % 3) * 24576u;
        mbar_wait(ctrl + 8u + (unsigned)(kt % 3) * 8u, (unsigned)((kt / 3) & 1));

        // ---- S = Q K^T (3-term bf16) ----
        float sc[8][4];
#pragma unroll
        for (int i = 0; i < 8; i++)
#pragma unroll
            for (int q = 0; q < 4; q++) sc[i][q] = 0.0f;
#pragma unroll
        for (int ks = 0; ks < 4; ks++) {
            unsigned bkh[4][4], bkl[4][4];
            const unsigned bc = (bcolb + ks * 32) ^ bswz;
#pragma unroll
            for (int nb = 0; nb < 4; nb++) {
                ldsm4(bkh[nb], stb + bbase0 + nb * 2048u + bc);
                ldsm4(bkl[nb], stb + 8192u + bbase0 + nb * 2048u + bc);
            }
#pragma unroll
            for (int nb = 0; nb < 4; nb++) {
                mma16816(sc[2 * nb],     aqh[ks], &bkh[nb][0]);
                mma16816(sc[2 * nb + 1], aqh[ks], &bkh[nb][2]);
                mma16816(sc[2 * nb],     aql[ks], &bkh[nb][0]);
                mma16816(sc[2 * nb + 1], aql[ks], &bkh[nb][2]);
                mma16816(sc[2 * nb],     aqh[ks], &bkl[nb][0]);
                mma16816(sc[2 * nb + 1], aqh[ks], &bkl[nb][2]);
            }
        }

        if (kt >= 2 * qt) {                     // diagonal band -> causal mask
            const int kb = kt * 64 + 2 * tig;
#pragma unroll
            for (int ni = 0; ni < 8; ni++) {
                const int key = kb + ni * 8;
                if (key > qrow_g)         sc[ni][0] = -1e30f;
                if (key + 1 > qrow_g)     sc[ni][1] = -1e30f;
                if (key > qrow_g + 8)     sc[ni][2] = -1e30f;
                if (key + 1 > qrow_g + 8) sc[ni][3] = -1e30f;
            }
        }

        // ---- online softmax ----
        float mx0 = -1e30f, mx1 = -1e30f;
#pragma unroll
        for (int ni = 0; ni < 8; ni++) {
            mx0 = fmaxf(mx0, fmaxf(sc[ni][0], sc[ni][1]));
            mx1 = fmaxf(mx1, fmaxf(sc[ni][2], sc[ni][3]));
        }
        mx0 = fmaxf(mx0, __shfl_xor_sync(0xFFFFFFFF, mx0, 1));
        mx0 = fmaxf(mx0, __shfl_xor_sync(0xFFFFFFFF, mx0, 2));
        mx1 = fmaxf(mx1, __shfl_xor_sync(0xFFFFFFFF, mx1, 1));
        mx1 = fmaxf(mx1, __shfl_xor_sync(0xFFFFFFFF, mx1, 2));
        const float nm0 = fmaxf(m0r, mx0), nm1 = fmaxf(m1r, mx1);
        const float cr0 = fexp(m0r - nm0), cr1 = fexp(m1r - nm1);
        m0r = nm0; m1r = nm1;
        l0 *= cr0; l1 *= cr1;
#pragma unroll
        for (int ni = 0; ni < 8; ni++) {
            O[ni][0] *= cr0; O[ni][1] *= cr0;
            O[ni][2] *= cr1; O[ni][3] *= cr1;
        }
        float ps0 = 0.0f, ps1 = 0.0f;
#pragma unroll
        for (int ni = 0; ni < 8; ni++) {
            sc[ni][0] = fexp(sc[ni][0] - nm0);
            sc[ni][1] = fexp(sc[ni][1] - nm0);
            sc[ni][2] = fexp(sc[ni][2] - nm1);
            sc[ni][3] = fexp(sc[ni][3] - nm1);
            ps0 += sc[ni][0] + sc[ni][1];
            ps1 += sc[ni][2] + sc[ni][3];
        }
        l0 += ps0; l1 += ps1;

        // ---- pack P as fp16 (single term) ----
        unsigned apf[4][4];
#pragma unroll
        for (int j = 0; j < 4; j++) {
            apf[j][0] = packh2(sc[2 * j][0], sc[2 * j][1]);
            apf[j][1] = packh2(sc[2 * j][2], sc[2 * j][3]);
            apf[j][2] = packh2(sc[2 * j + 1][0], sc[2 * j + 1][1]);
            apf[j][3] = packh2(sc[2 * j + 1][2], sc[2 * j + 1][3]);
        }

        // ---- O += P V (fp16 1-term) ----
#pragma unroll
        for (int j = 0; j < 4; j++) {
#pragma unroll
            for (int db = 0; db < 4; db++) {
                unsigned vf[4];
                const unsigned off = vbase0 + j * 2048u + ((db * 32u + vd2) ^ vswz);
                ldsm4t(vf, stb + 16384u + off);
                mma16816h(O[2 * db],     apf[j], &vf[0]);
                mma16816h(O[2 * db + 1], apf[j], &vf[2]);
            }
        }
        __syncthreads();
        if (tid == 0 && kt + 3 < nkt) issue_kv(kt + 3);
    }

    // ---- epilogue: ao -> fp16 single ----
    l0 += __shfl_xor_sync(0xFFFFFFFF, l0, 1);
    l0 += __shfl_xor_sync(0xFFFFFFFF, l0, 2);
    l1 += __shfl_xor_sync(0xFFFFFFFF, l1, 1);
    l1 += __shfl_xor_sync(0xFFFFFFFF, l1, 2);
    const float inv0 = 1.0f / l0, inv1 = 1.0f / l1;

    const int b = bh >> 4, h = bh & 15;
    const size_t r0 = (size_t)(b * Tn + qrow_g) * Cn;
    const size_t r1 = (size_t)(b * Tn + qrow_g + 8) * Cn;
#pragma unroll
    for (int ni = 0; ni < 8; ni++) {
        const int k = h * Dn + ni * 8 + 2 * tig;
        *(unsigned*)&g_aof[r0 + k] = packh2(O[ni][0] * inv0, O[ni][1] * inv0);
        *(unsigned*)&g_aof[r1 + k] = packh2(O[ni][2] * inv1, O[ni][3] * inv1);
    }
}

// ---------------- host ----------------
typedef CUresult (CUDAAPI* EncodeFn)(
    CUtensorMap*, CUtensorMapDataType, cuuint32_t, void*,
    const cuuint64_t*, const cuuint64_t*, const cuuint32_t*, const cuuint32_t*,
    CUtensorMapInterleave, CUtensorMapSwizzle, CUtensorMapL2promotion,
    CUtensorMapFloatOOBfill);

static void mk_map(EncodeFn enc, CUtensorMap* m, void* base, CUtensorMapDataType dt,
                   unsigned long long rows, unsigned long long cols,
                   unsigned boxc, unsigned boxr)
{
    cuuint64_t dims[2] = {cols, rows};
    cuuint64_t strides[1] = {cols * 2};
    cuuint32_t box[2] = {boxc, boxr};
    cuuint32_t es[2] = {1, 1};
    enc(m, dt, 2, base, dims, strides, box, es,
        CU_TENSOR_MAP_INTERLEAVE_NONE, CU_TENSOR_MAP_SWIZZLE_128B,
        CU_TENSOR_MAP_L2_PROMOTION_L2_128B, CU_TENSOR_MAP_FLOAT_OOB_FILL_NONE);
}

extern "C" void kernel_launch(void* const* d_in, const int* in_sizes, int n_in,
                              void* d_out, int out_size)
{
    const float* x     = (const float*)d_in[0];
    const float* w_qkv = (const float*)d_in[1];
    const float* w_out = (const float*)d_in[2];
    const float* b_out = (const float*)d_in[3];
    float* out = (float*)d_out;

    void *pXf, *pW1, *pW3, *pAo, *pQh, *pQl, *pKh, *pKl, *pVf;
    cudaGetSymbolAddress(&pXf, g_xf);
    cudaGetSymbolAddress(&pW1, g_w1f);
    cudaGetSymbolAddress(&pW3, g_w3f);
    cudaGetSymbolAddress(&pAo, g_aof);
    cudaGetSymbolAddress(&pQh, g_qh);   cudaGetSymbolAddress(&pQl, g_ql);
    cudaGetSymbolAddress(&pKh, g_kh);   cudaGetSymbolAddress(&pKl, g_kl);
    cudaGetSymbolAddress(&pVf, g_vf);

    EncodeFn enc = nullptr;
    cudaDriverEntryPointQueryResult qr;
    cudaGetDriverEntryPointByVersion("cuTensorMapEncodeTiled", (void**)&enc,
                                     12000, cudaEnableDefault, &qr);

    const auto BF = CU_TENSOR_MAP_DATA_TYPE_BFLOAT16;
    const auto F16 = CU_TENSOR_MAP_DATA_TYPE_FLOAT16;
    const unsigned long long MR = (unsigned long long)Bn * Tn;        // 8192
    const unsigned long long KVR = (unsigned long long)Bn * Hn * Tn;  // 131072
    CUtensorMap mXf, mW1, mW3, mAo, mQh, mQl, mKh, mKl, mVf;
    mk_map(enc, &mXf, pXf, F16, MR, 1024, 64, 128);
    mk_map(enc, &mW1, pW1, F16, 3072, 1024, 64, 128);
    mk_map(enc, &mW3, pW3, F16, 1024, 1024, 64, 128);
    mk_map(enc, &mAo, pAo, F16, MR, 1024, 64, 128);
    mk_map(enc, &mQh, pQh, BF, KVR, 64, 64, 128);
    mk_map(enc, &mQl, pQl, BF, KVR, 64, 64, 128);
    mk_map(enc, &mKh, pKh, BF, KVR, 64, 64, 64);
    mk_map(enc, &mKl, pKl, BF, KVR, 64, 64, 64);
    mk_map(enc, &mVf, pVf, F16, KVR, 64, 64, 64);

    cudaFuncSetAttribute(gemm_tma<0>, cudaFuncAttributeMaxDynamicSharedMemorySize, GEMM_SMEM);
    cudaFuncSetAttribute(gemm_tma<1>, cudaFuncAttributeMaxDynamicSharedMemorySize, GEMM_SMEM);
    cudaFuncSetAttribute(attn_tma, cudaFuncAttributeMaxDynamicSharedMemorySize, ATTN_SMEM);

    tof16<<<(Bn * Tn * Cn) / 512, 256>>>(x, (unsigned short*)pXf);
    tof16<<<(3 * Cn * Cn) / 512, 256>>>(w_qkv, (unsigned short*)pW1);
    tof16<<<(Cn * Cn) / 512, 256>>>(w_out, (unsigned short*)pW3);
    gemm_tma<0><<<dim3(24, 64), 256, GEMM_SMEM>>>(mXf, mW1, nullptr, nullptr);
    attn_tma<<<dim3(Tn / 128, Bn * Hn), 256, ATTN_SMEM>>>(mQh, mQl, mKh, mKl, mVf);
    gemm_tma<1><<<dim3(8, 64), 256, GEMM_SMEM>>>(mAo, mW3, b_out, out);
}

// round 10
// speedup vs baseline: 10.1255x; 1.0509x over previous
#include <cuda.h>
#include <cuda_runtime.h>
#include <cuda_bf16.h>

namespace {
constexpr int Bn = 4, Tn = 2048, Cn = 1024, Hn = 16, Dn = 64;
constexpr unsigned GSTG = 49152;                                   // A 32K + B 16K
constexpr unsigned GEMM_SMEM = 3 * GSTG + 1024 + 64;               // 3-stage ring
constexpr unsigned ATTN_SMEM = 32768 + 3 * 24576 + 1024 + 64;      // Q + 3 KV stages
}

// ---------------- scratch (device globals; no allocs allowed) ----------------
__device__ __align__(16) unsigned short g_xf[(size_t)Bn * Tn * Cn];     // fp16 x
__device__ __align__(16) unsigned short g_w1f[(size_t)3 * Cn * Cn];     // fp16 w_qkv
__device__ __align__(16) unsigned short g_w3f[(size_t)Cn * Cn];         // fp16 w_out
__device__ __align__(16) unsigned short g_aof[(size_t)Bn * Tn * Cn];    // fp16 attn out
__device__ __align__(16) __nv_bfloat16 g_qh[(size_t)Bn * Hn * Tn * Dn]; // [BH*T, 64]
__device__ __align__(16) __nv_bfloat16 g_ql[(size_t)Bn * Hn * Tn * Dn];
__device__ __align__(16) __nv_bfloat16 g_kh[(size_t)Bn * Hn * Tn * Dn];
__device__ __align__(16) __nv_bfloat16 g_kl[(size_t)Bn * Hn * Tn * Dn];
__device__ __align__(16) unsigned short g_vf[(size_t)Bn * Hn * Tn * Dn]; // fp16 V

// ---------------- device helpers ----------------
__device__ __forceinline__ unsigned smem_u32(const void* p) {
    unsigned a;
    asm("{ .reg .u64 t; cvta.to.shared.u64 t, %1; cvt.u32.u64 %0, t; }" : "=r"(a) : "l"(p));
    return a;
}
__device__ __forceinline__ void mbar_init(unsigned addr, unsigned cnt) {
    asm volatile("mbarrier.init.shared.b64 [%0], %1;" :: "r"(addr), "r"(cnt) : "memory");
}
__device__ __forceinline__ void mbar_arrive(unsigned addr) {
    asm volatile("mbarrier.arrive.shared.b64 _, [%0];" :: "r"(addr) : "memory");
}
__device__ __forceinline__ void mbar_expect(unsigned addr, unsigned bytes) {
    asm volatile("mbarrier.arrive.expect_tx.shared.b64 _, [%0], %1;"
                 :: "r"(addr), "r"(bytes) : "memory");
}
__device__ __forceinline__ void mbar_wait(unsigned addr, unsigned parity) {
    asm volatile(
        "{\n\t.reg .pred P;\n\t"
        "WL_%=:\n\t"
        "mbarrier.try_wait.parity.acquire.cta.shared::cta.b64 P, [%0], %1, 0x989680;\n\t"
        "@P bra.uni WD_%=;\n\t"
        "bra.uni WL_%=;\n\t"
        "WD_%=:\n\t}"
        :: "r"(addr), "r"(parity) : "memory");
}
__device__ __forceinline__ void tma2d(unsigned smem, const CUtensorMap* m,
                                      int x, int y, unsigned mbar) {
    asm volatile(
        "cp.async.bulk.tensor.2d.shared::cta.global.tile.mbarrier::complete_tx::bytes "
        "[%0], [%1, {%2, %3}], [%4];"
        :: "r"(smem), "l"(m), "r"(x), "r"(y), "r"(mbar) : "memory");
}
__device__ __forceinline__ void ldsm4(unsigned* r, unsigned addr) {
    asm volatile("ldmatrix.sync.aligned.m8n8.x4.shared.b16 {%0,%1,%2,%3}, [%4];"
        : "=r"(r[0]), "=r"(r[1]), "=r"(r[2]), "=r"(r[3]) : "r"(addr));
}
__device__ __forceinline__ void ldsm4t(unsigned* r, unsigned addr) {
    asm volatile("ldmatrix.sync.aligned.m8n8.x4.trans.shared.b16 {%0,%1,%2,%3}, [%4];"
        : "=r"(r[0]), "=r"(r[1]), "=r"(r[2]), "=r"(r[3]) : "r"(addr));
}
__device__ __forceinline__ void mma16816(float* c, const unsigned* a, const unsigned* b) {
    asm volatile("mma.sync.aligned.m16n8k16.row.col.f32.bf16.bf16.f32 "
        "{%0,%1,%2,%3}, {%4,%5,%6,%7}, {%8,%9}, {%0,%1,%2,%3};"
        : "+f"(c[0]), "+f"(c[1]), "+f"(c[2]), "+f"(c[3])
        : "r"(a[0]), "r"(a[1]), "r"(a[2]), "r"(a[3]), "r"(b[0]), "r"(b[1]));
}
__device__ __forceinline__ void mma16816h(float* c, const unsigned* a, const unsigned* b) {
    asm volatile("mma.sync.aligned.m16n8k16.row.col.f32.f16.f16.f32 "
        "{%0,%1,%2,%3}, {%4,%5,%6,%7}, {%8,%9}, {%0,%1,%2,%3};"
        : "+f"(c[0]), "+f"(c[1]), "+f"(c[2]), "+f"(c[3])
        : "r"(a[0]), "r"(a[1]), "r"(a[2]), "r"(a[3]), "r"(b[0]), "r"(b[1]));
}
__device__ __forceinline__ unsigned packbf2(float lo, float hi) {
    unsigned u;
    asm("cvt.rn.bf16x2.f32 %0, %1, %2;" : "=r"(u) : "f"(hi), "f"(lo));
    return u;
}
__device__ __forceinline__ unsigned packh2(float lo, float hi) {
    unsigned u;
    asm("{ .reg .b16 l, h; cvt.rn.f16.f32 l, %1; cvt.rn.f16.f32 h, %2; "
        "mov.b32 %0, {l, h}; }" : "=r"(u) : "f"(lo), "f"(hi));
    return u;
}
__device__ __forceinline__ float fexp(float x) {
    x = fmaxf(x, -80.0f);
    const float z = x * 1.4426950408889634f;
    const float zf = z + 12582912.0f;
    const int n = __float_as_int(zf);
    const float r = z - (zf - 12582912.0f);
    float p = 0.009618129f;
    p = fmaf(p, r, 0.05550411f);
    p = fmaf(p, r, 0.2402265f);
    p = fmaf(p, r, 0.6931472f);
    p = fmaf(p, r, 1.0f);
    return p * __int_as_float((n << 23) + 0x3F800000);
}

// ---------------- fp32 -> fp16 convert ----------------
__global__ __launch_bounds__(256) void tof16(const float* __restrict__ src,
                                             unsigned short* __restrict__ dst)
{
    const size_t i = ((size_t)blockIdx.x * 256 + threadIdx.x) * 2;
    const float2 v = *(const float2*)(src + i);
    *(unsigned*)(dst + i) = packh2(v.x, v.y);
}

// ---------------- TMA fp16 HMMA GEMM, 256x128 tile, 3-stage ring ----------------
// MODE 0: A=xf, B=w1f -> split q/k (bf16 h/l, q scaled 0.125) + V fp16. MODE 1: out+bias.
template <int MODE>
__global__ __launch_bounds__(256) void gemm_tma(
    const __grid_constant__ CUtensorMap tA, const __grid_constant__ CUtensorMap tB,
    const float* __restrict__ bias, float* __restrict__ out)
{
    extern __shared__ __align__(16) unsigned char smraw[];
    const unsigned sb = (smem_u32(smraw) + 1023u) & ~1023u;
    const unsigned ctrl = sb + 3u * GSTG;                   // full[0..2]

    const int tid = threadIdx.x, lane = tid & 31, wid = tid >> 5;
    const int wm = wid & 3, wn = wid >> 2;                  // 4(m) x 2(n)
    const int m0 = blockIdx.y * 256, n0 = blockIdx.x * 128;

    if (tid == 0) { mbar_init(ctrl, 1); mbar_init(ctrl + 8, 1); mbar_init(ctrl + 16, 1); }
    __syncthreads();

    auto issue = [&](int s) {   // tid 0 only
        const unsigned base = sb + (unsigned)(s % 3) * GSTG;
        const unsigned mb = ctrl + (unsigned)(s % 3) * 8u;
        mbar_expect(mb, GSTG);
        const int kc = s * 64;
        tma2d(base,           &tA, kc, m0, mb);             // 256x64 fp16 = 32KB
        tma2d(base + 32768u,  &tB, kc, n0, mb);             // 128x64 fp16 = 16KB
    };
    if (tid == 0) { issue(0); issue(1); issue(2); }

    const int arow = wm * 64 + (lane & 15);
    const unsigned acolb = (unsigned)((lane >> 4) * 16);
    const unsigned aswz = (unsigned)((arow & 7) << 4);
    const int brow = wn * 64 + (lane & 7) + ((lane >> 4) << 3);
    const unsigned bbase0 = (unsigned)(brow * 128);
    const unsigned bcolb = (unsigned)(((lane >> 3) & 1) * 16);
    const unsigned bswz = (unsigned)((brow & 7) << 4);

    float acc[4][8][4];
#pragma unroll
    for (int i = 0; i < 4; i++)
#pragma unroll
        for (int j = 0; j < 8; j++)
#pragma unroll
            for (int q = 0; q < 4; q++) acc[i][j][q] = 0.0f;

    for (int s = 0; s < 16; s++) {                          // K = 1024 / 64
        const unsigned stb = sb + (unsigned)(s % 3) * GSTG;
        mbar_wait(ctrl + (unsigned)(s % 3) * 8u, (unsigned)((s / 3) & 1));
#pragma unroll
        for (int ks = 0; ks < 4; ks++) {
            unsigned af[4][4], bf[4][4];
            const unsigned ac = (acolb + ks * 32) ^ aswz;
#pragma unroll
            for (int mi = 0; mi < 4; mi++)
                ldsm4(af[mi], stb + (unsigned)((arow + mi * 16) * 128) + ac);
            const unsigned bc = (bcolb + ks * 32) ^ bswz;
#pragma unroll
            for (int nb = 0; nb < 4; nb++)
                ldsm4(bf[nb], stb + 32768u + bbase0 + nb * 2048u + bc);
#pragma unroll
            for (int mi = 0; mi < 4; mi++)
#pragma unroll
                for (int nb = 0; nb < 4; nb++) {
                    mma16816h(acc[mi][2 * nb],     af[mi], &bf[nb][0]);
                    mma16816h(acc[mi][2 * nb + 1], af[mi], &bf[nb][2]);
                }
        }
        __syncthreads();
        if (tid == 0 && s + 3 < 16) issue(s + 3);
    }

    const int g = lane >> 2, tig = lane & 3;
    if (MODE == 0) {
        const int nblock = n0 + wn * 64;                    // one (sec, head)
        const int sec = nblock >> 10;
        const int h = (nblock & 1023) >> 6;
        if (sec == 2) {                                     // V -> fp16 single
#pragma unroll
            for (int mi = 0; mi < 4; mi++) {
                const int m1 = m0 + wm * 64 + mi * 16 + g;
                const int b = m1 >> 11, t = m1 & 2047;
                const size_t rb = (size_t)((b * Hn + h) * Tn + t) * Dn;
#pragma unroll
                for (int ni = 0; ni < 8; ni++) {
                    const int d = ni * 8 + 2 * tig;
#pragma unroll
                    for (int half = 0; half < 2; half++) {
                        const size_t o = rb + (size_t)half * 8 * Dn + d;
                        *(unsigned*)&g_vf[o] =
                            packh2(acc[mi][ni][2 * half], acc[mi][ni][2 * half + 1]);
                    }
                }
            }
        } else {                                            // q/k -> split bf16
            const float scale = (sec == 0) ? 0.125f : 1.0f;
            __nv_bfloat16* dh = (sec == 0) ? g_qh : g_kh;
            __nv_bfloat16* dl = (sec == 0) ? g_ql : g_kl;
#pragma unroll
            for (int mi = 0; mi < 4; mi++) {
                const int m1 = m0 + wm * 64 + mi * 16 + g;
                const int b = m1 >> 11, t = m1 & 2047;
                const size_t rb = (size_t)((b * Hn + h) * Tn + t) * Dn;
#pragma unroll
                for (int ni = 0; ni < 8; ni++) {
                    const int d = ni * 8 + 2 * tig;
#pragma unroll
                    for (int half = 0; half < 2; half++) {
                        const float v0 = acc[mi][ni][2 * half] * scale;
                        const float v1 = acc[mi][ni][2 * half + 1] * scale;
                        const float h0 = __bfloat162float(__float2bfloat16(v0));
                        const float h1 = __bfloat162float(__float2bfloat16(v1));
                        const size_t o = rb + (size_t)half * 8 * Dn + d;
                        *(unsigned*)&dh[o] = packbf2(h0, h1);
                        *(unsigned*)&dl[o] = packbf2(v0 - h0, v1 - h1);
                    }
                }
            }
        }
    } else {
#pragma unroll
        for (int mi = 0; mi < 4; mi++) {
            const int m1 = m0 + wm * 64 + mi * 16 + g;
#pragma unroll
            for (int ni = 0; ni < 8; ni++) {
                const int n = n0 + wn * 64 + ni * 8 + 2 * tig;
                const float2 bb = *(const float2*)(bias + n);
                float2 lo = {acc[mi][ni][0] + bb.x, acc[mi][ni][1] + bb.y};
                float2 hi = {acc[mi][ni][2] + bb.x, acc[mi][ni][3] + bb.y};
                *(float2*)(out + (size_t)m1 * Cn + n) = lo;
                *(float2*)(out + (size_t)(m1 + 8) * Cn + n) = hi;
            }
        }
    }
}

// ---------------- TMA flash attention: empty-mbarrier pipelining ----------------
// Grid (16, B*H), 256 thr / 8 warps, 128-row Q tile. No __syncthreads in mainloop:
// per-slot empty barriers (count 8) let warps drift across KV tiles.
__global__ __launch_bounds__(256) void attn_tma(
    const __grid_constant__ CUtensorMap tQh, const __grid_constant__ CUtensorMap tQl,
    const __grid_constant__ CUtensorMap tKh, const __grid_constant__ CUtensorMap tKl,
    const __grid_constant__ CUtensorMap tVf)
{
    extern __shared__ __align__(16) unsigned char smraw[];
    const unsigned sb = (smem_u32(smraw) + 1023u) & ~1023u;
    const unsigned kvb = sb + 32768u;                       // 3 KV stages x 24576
    const unsigned ctrl = kvb + 3u * 24576u;  // qbar, full[0..2], empty[0..2]

    const int tid = threadIdx.x, lane = tid & 31, wid = tid >> 5;
    const int qt = (int)gridDim.x - 1 - (int)blockIdx.x;    // heavy tiles first
    const int bh = blockIdx.y;
    const int g = lane >> 2, tig = lane & 3;
    const int grow0 = bh * Tn;
    const int nkt = 2 * qt + 2;

    if (tid == 0) {
        mbar_init(ctrl, 1);
        mbar_init(ctrl + 8, 1);  mbar_init(ctrl + 16, 1); mbar_init(ctrl + 24, 1);
        mbar_init(ctrl + 32, 8); mbar_init(ctrl + 40, 8);  mbar_init(ctrl + 48, 8);
    }
    __syncthreads();

    auto issue_kv = [&](int s) {   // tid 0 only
        const unsigned base = kvb + (unsigned)(s % 3) * 24576u;
        const unsigned mb = ctrl + 8u + (unsigned)(s % 3) * 8u;
        mbar_expect(mb, 24576u);
        const int y = grow0 + s * 64;
        tma2d(base,           &tKh, 0, y, mb);
        tma2d(base + 8192u,   &tKl, 0, y, mb);
        tma2d(base + 16384u,  &tVf, 0, y, mb);
    };
    if (tid == 0) {
        mbar_expect(ctrl, 32768u);
        tma2d(sb,           &tQh, 0, grow0 + qt * 128, ctrl);
        tma2d(sb + 16384u,  &tQl, 0, grow0 + qt * 128, ctrl);
        issue_kv(0); issue_kv(1);
        if (nkt > 2) issue_kv(2);
    }

    // Q fragments -> registers (warp w owns rows w*16..+15)
    mbar_wait(ctrl, 0u);
    const int qrow = wid * 16 + (lane & 15);
    const unsigned qswz = (unsigned)((qrow & 7) << 4);
    unsigned aqh[4][4], aql[4][4];
#pragma unroll
    for (int ks = 0; ks < 4; ks++) {
        const unsigned ac = (unsigned)((lane >> 4) * 16 + ks * 32) ^ qswz;
        ldsm4(aqh[ks], sb + (unsigned)(qrow * 128) + ac);
        ldsm4(aql[ks], sb + 16384u + (unsigned)(qrow * 128) + ac);
    }

    const int brow = (lane & 7) + ((lane >> 4) << 3);
    const unsigned bbase0 = (unsigned)(brow * 128);
    const unsigned bcolb = (unsigned)(((lane >> 3) & 1) * 16);
    const unsigned bswz = (unsigned)((brow & 7) << 4);
    const int vrow = (((lane >> 3) & 1) << 3) + (lane & 7);
    const unsigned vbase0 = (unsigned)(vrow * 128);
    const unsigned vd2 = (unsigned)((lane >> 4) * 16);
    const unsigned vswz = (unsigned)((vrow & 7) << 4);

    float O[8][4];
#pragma unroll
    for (int i = 0; i < 8; i++)
#pragma unroll
        for (int q = 0; q < 4; q++) O[i][q] = 0.0f;
    float m0r = -1e30f, m1r = -1e30f, l0 = 0.0f, l1 = 0.0f;
    const int qrow_g = qt * 128 + wid * 16 + g;

    for (int kt = 0; kt < nkt; kt++) {
        const unsigned stb = kvb + (unsigned)(kt % 3) * 24576u;
        mbar_wait(ctrl + 8u + (unsigned)(kt % 3) * 8u, (unsigned)((kt / 3) & 1));

        // ---- S = Q K^T (3-term bf16) ----
        float sc[8][4];
#pragma unroll
        for (int i = 0; i < 8; i++)
#pragma unroll
            for (int q = 0; q < 4; q++) sc[i][q] = 0.0f;
#pragma unroll
        for (int ks = 0; ks < 4; ks++) {
            unsigned bkh[4][4], bkl[4][4];
            const unsigned bc = (bcolb + ks * 32) ^ bswz;
#pragma unroll
            for (int nb = 0; nb < 4; nb++) {
                ldsm4(bkh[nb], stb + bbase0 + nb * 2048u + bc);
                ldsm4(bkl[nb], stb + 8192u + bbase0 + nb * 2048u + bc);
            }
#pragma unroll
            for (int nb = 0; nb < 4; nb++) {
                mma16816(sc[2 * nb],     aqh[ks], &bkh[nb][0]);
                mma16816(sc[2 * nb + 1], aqh[ks], &bkh[nb][2]);
                mma16816(sc[2 * nb],     aql[ks], &bkh[nb][0]);
                mma16816(sc[2 * nb + 1], aql[ks], &bkh[nb][2]);
                mma16816(sc[2 * nb],     aqh[ks], &bkl[nb][0]);
                mma16816(sc[2 * nb + 1], aqh[ks], &bkl[nb][2]);
            }
        }

        if (kt >= 2 * qt) {                     // diagonal band -> causal mask
            const int kb = kt * 64 + 2 * tig;
#pragma unroll
            for (int ni = 0; ni < 8; ni++) {
                const int key = kb + ni * 8;
                if (key > qrow_g)         sc[ni][0] = -1e30f;
                if (key + 1 > qrow_g)     sc[ni][1] = -1e30f;
                if (key > qrow_g + 8)     sc[ni][2] = -1e30f;
                if (key + 1 > qrow_g + 8) sc[ni][3] = -1e30f;
            }
        }

        // ---- online softmax ----
        float mx0 = -1e30f, mx1 = -1e30f;
#pragma unroll
        for (int ni = 0; ni < 8; ni++) {
            mx0 = fmaxf(mx0, fmaxf(sc[ni][0], sc[ni][1]));
            mx1 = fmaxf(mx1, fmaxf(sc[ni][2], sc[ni][3]));
        }
        mx0 = fmaxf(mx0, __shfl_xor_sync(0xFFFFFFFF, mx0, 1));
        mx0 = fmaxf(mx0, __shfl_xor_sync(0xFFFFFFFF, mx0, 2));
        mx1 = fmaxf(mx1, __shfl_xor_sync(0xFFFFFFFF, mx1, 1));
        mx1 = fmaxf(mx1, __shfl_xor_sync(0xFFFFFFFF, mx1, 2));
        const float nm0 = fmaxf(m0r, mx0), nm1 = fmaxf(m1r, mx1);
        const float cr0 = fexp(m0r - nm0), cr1 = fexp(m1r - nm1);
        m0r = nm0; m1r = nm1;
        l0 *= cr0; l1 *= cr1;
#pragma unroll
        for (int ni = 0; ni < 8; ni++) {
            O[ni][0] *= cr0; O[ni][1] *= cr0;
            O[ni][2] *= cr1; O[ni][3] *= cr1;
        }
        float ps0 = 0.0f, ps1 = 0.0f;
#pragma unroll
        for (int ni = 0; ni < 8; ni++) {
            sc[ni][0] = fexp(sc[ni][0] - nm0);
            sc[ni][1] = fexp(sc[ni][1] - nm0);
            sc[ni][2] = fexp(sc[ni][2] - nm1);
            sc[ni][3] = fexp(sc[ni][3] - nm1);
            ps0 += sc[ni][0] + sc[ni][1];
            ps1 += sc[ni][2] + sc[ni][3];
        }
        l0 += ps0; l1 += ps1;

        // ---- pack P as fp16 (single term) ----
        unsigned apf[4][4];
#pragma unroll
        for (int j = 0; j < 4; j++) {
            apf[j][0] = packh2(sc[2 * j][0], sc[2 * j][1]);
            apf[j][1] = packh2(sc[2 * j][2], sc[2 * j][3]);
            apf[j][2] = packh2(sc[2 * j + 1][0], sc[2 * j + 1][1]);
            apf[j][3] = packh2(sc[2 * j + 1][2], sc[2 * j + 1][3]);
        }

        // ---- O += P V (fp16 1-term) ----
#pragma unroll
        for (int j = 0; j < 4; j++) {
#pragma unroll
            for (int db = 0; db < 4; db++) {
                unsigned vf[4];
                const unsigned off = vbase0 + j * 2048u + ((db * 32u + vd2) ^ vswz);
                ldsm4t(vf, stb + 16384u + off);
                mma16816h(O[2 * db],     apf[j], &vf[0]);
                mma16816h(O[2 * db + 1], apf[j], &vf[2]);
            }
        }

        // ---- release slot: per-warp arrive; producer refills without block sync ----
        if (lane == 0) mbar_arrive(ctrl + 32u + (unsigned)(kt % 3) * 8u);
        if (tid == 0 && kt + 3 < nkt) {
            mbar_wait(ctrl + 32u + (unsigned)(kt % 3) * 8u, (unsigned)((kt / 3) & 1));
            issue_kv(kt + 3);
        }
    }

    // ---- epilogue: ao -> fp16 single ----
    l0 += __shfl_xor_sync(0xFFFFFFFF, l0, 1);
    l0 += __shfl_xor_sync(0xFFFFFFFF, l0, 2);
    l1 += __shfl_xor_sync(0xFFFFFFFF, l1, 1);
    l1 += __shfl_xor_sync(0xFFFFFFFF, l1, 2);
    const float inv0 = 1.0f / l0, inv1 = 1.0f / l1;

    const int b = bh >> 4, h = bh & 15;
    const size_t r0 = (size_t)(b * Tn + qrow_g) * Cn;
    const size_t r1 = (size_t)(b * Tn + qrow_g + 8) * Cn;
#pragma unroll
    for (int ni = 0; ni < 8; ni++) {
        const int k = h * Dn + ni * 8 + 2 * tig;
        *(unsigned*)&g_aof[r0 + k] = packh2(O[ni][0] * inv0, O[ni][1] * inv0);
        *(unsigned*)&g_aof[r1 + k] = packh2(O[ni][2] * inv1, O[ni][3] * inv1);
    }
}

// ---------------- host ----------------
typedef CUresult (CUDAAPI* EncodeFn)(
    CUtensorMap*, CUtensorMapDataType, cuuint32_t, void*,
    const cuuint64_t*, const cuuint64_t*, const cuuint32_t*, const cuuint32_t*,
    CUtensorMapInterleave, CUtensorMapSwizzle, CUtensorMapL2promotion,
    CUtensorMapFloatOOBfill);

static void mk_map(EncodeFn enc, CUtensorMap* m, void* base, CUtensorMapDataType dt,
                   unsigned long long rows, unsigned long long cols,
                   unsigned boxc, unsigned boxr)
{
    cuuint64_t dims[2] = {cols, rows};
    cuuint64_t strides[1] = {cols * 2};
    cuuint32_t box[2] = {boxc, boxr};
    cuuint32_t es[2] = {1, 1};
    enc(m, dt, 2, base, dims, strides, box, es,
        CU_TENSOR_MAP_INTERLEAVE_NONE, CU_TENSOR_MAP_SWIZZLE_128B,
        CU_TENSOR_MAP_L2_PROMOTION_L2_128B, CU_TENSOR_MAP_FLOAT_OOB_FILL_NONE);
}

extern "C" void kernel_launch(void* const* d_in, const int* in_sizes, int n_in,
                              void* d_out, int out_size)
{
    const float* x     = (const float*)d_in[0];
    const float* w_qkv = (const float*)d_in[1];
    const float* w_out = (const float*)d_in[2];
    const float* b_out = (const float*)d_in[3];
    float* out = (float*)d_out;

    void *pXf, *pW1, *pW3, *pAo, *pQh, *pQl, *pKh, *pKl, *pVf;
    cudaGetSymbolAddress(&pXf, g_xf);
    cudaGetSymbolAddress(&pW1, g_w1f);
    cudaGetSymbolAddress(&pW3, g_w3f);
    cudaGetSymbolAddress(&pAo, g_aof);
    cudaGetSymbolAddress(&pQh, g_qh);   cudaGetSymbolAddress(&pQl, g_ql);
    cudaGetSymbolAddress(&pKh, g_kh);   cudaGetSymbolAddress(&pKl, g_kl);
    cudaGetSymbolAddress(&pVf, g_vf);

    EncodeFn enc = nullptr;
    cudaDriverEntryPointQueryResult qr;
    cudaGetDriverEntryPointByVersion("cuTensorMapEncodeTiled", (void**)&enc,
                                     12000, cudaEnableDefault, &qr);

    const auto BF = CU_TENSOR_MAP_DATA_TYPE_BFLOAT16;
    const auto F16 = CU_TENSOR_MAP_DATA_TYPE_FLOAT16;
    const unsigned long long MR = (unsigned long long)Bn * Tn;        // 8192
    const unsigned long long KVR = (unsigned long long)Bn * Hn * Tn;  // 131072
    CUtensorMap mXf, mW1, mW3, mAo, mQh, mQl, mKh, mKl, mVf;
    mk_map(enc, &mXf, pXf, F16, MR, 1024, 64, 256);
    mk_map(enc, &mW1, pW1, F16, 3072, 1024, 64, 128);
    mk_map(enc, &mW3, pW3, F16, 1024, 1024, 64, 128);
    mk_map(enc, &mAo, pAo, F16, MR, 1024, 64, 256);
    mk_map(enc, &mQh, pQh, BF, KVR, 64, 64, 128);
    mk_map(enc, &mQl, pQl, BF, KVR, 64, 64, 128);
    mk_map(enc, &mKh, pKh, BF, KVR, 64, 64, 64);
    mk_map(enc, &mKl, pKl, BF, KVR, 64, 64, 64);
    mk_map(enc, &mVf, pVf, F16, KVR, 64, 64, 64);

    cudaFuncSetAttribute(gemm_tma<0>, cudaFuncAttributeMaxDynamicSharedMemorySize, GEMM_SMEM);
    cudaFuncSetAttribute(gemm_tma<1>, cudaFuncAttributeMaxDynamicSharedMemorySize, GEMM_SMEM);
    cudaFuncSetAttribute(attn_tma, cudaFuncAttributeMaxDynamicSharedMemorySize, ATTN_SMEM);

    tof16<<<(Bn * Tn * Cn) / 512, 256>>>(x, (unsigned short*)pXf);
    tof16<<<(3 * Cn * Cn) / 512, 256>>>(w_qkv, (unsigned short*)pW1);
    tof16<<<(Cn * Cn) / 512, 256>>>(w_out, (unsigned short*)pW3);
    gemm_tma<0><<<dim3(24, 32), 256, GEMM_SMEM>>>(mXf, mW1, nullptr, nullptr);
    attn_tma<<<dim3(Tn / 128, Bn * Hn), 256, ATTN_SMEM>>>(mQh, mQl, mKh, mKl, mVf);
    gemm_tma<1><<<dim3(8, 32), 256, GEMM_SMEM>>>(mAo, mW3, b_out, out);
}

// round 11
// speedup vs baseline: 11.4501x; 1.1308x over previous
#include <cuda.h>
#include <cuda_runtime.h>
#include <cuda_bf16.h>
#include <cuda_fp16.h>

namespace {
constexpr int Bn = 4, Tn = 2048, Cn = 1024, Hn = 16, Dn = 64;
constexpr unsigned GSTG = 49152;                                   // A 32K + B 16K
constexpr unsigned GEMM_SMEM = 4 * GSTG + 1024 + 64;               // 4-stage ring
constexpr unsigned ATTN_SMEM = 32768 + 3 * 16384 + 1024 + 64;      // Q(2x16K) + 3 KV stages
}

// ---------------- scratch (device globals; no allocs allowed) ----------------
__device__ __align__(16) unsigned short g_xf[(size_t)Bn * Tn * Cn];     // fp16 x
__device__ __align__(16) unsigned short g_w1f[(size_t)3 * Cn * Cn];     // fp16 w_qkv
__device__ __align__(16) unsigned short g_w3f[(size_t)Cn * Cn];         // fp16 w_out
__device__ __align__(16) unsigned short g_aof[(size_t)Bn * Tn * Cn];    // fp16 attn out
__device__ __align__(16) unsigned short g_qf[(size_t)Bn * Hn * Tn * Dn]; // fp16 q high
__device__ __align__(16) unsigned short g_ql[(size_t)Bn * Hn * Tn * Dn]; // fp16 q low
__device__ __align__(16) unsigned short g_kf[(size_t)Bn * Hn * Tn * Dn]; // fp16 k
__device__ __align__(16) unsigned short g_vf[(size_t)Bn * Hn * Tn * Dn]; // fp16 v

// ---------------- device helpers ----------------
__device__ __forceinline__ unsigned smem_u32(const void* p) {
    unsigned a;
    asm("{ .reg .u64 t; cvta.to.shared.u64 t, %1; cvt.u32.u64 %0, t; }" : "=r"(a) : "l"(p));
    return a;
}
__device__ __forceinline__ void mbar_init(unsigned addr, unsigned cnt) {
    asm volatile("mbarrier.init.shared.b64 [%0], %1;" :: "r"(addr), "r"(cnt) : "memory");
}
__device__ __forceinline__ void mbar_arrive(unsigned addr) {
    asm volatile("mbarrier.arrive.shared.b64 _, [%0];" :: "r"(addr) : "memory");
}
__device__ __forceinline__ void mbar_expect(unsigned addr, unsigned bytes) {
    asm volatile("mbarrier.arrive.expect_tx.shared.b64 _, [%0], %1;"
                 :: "r"(addr), "r"(bytes) : "memory");
}
__device__ __forceinline__ void mbar_wait(unsigned addr, unsigned parity) {
    asm volatile(
        "{\n\t.reg .pred P;\n\t"
        "WL_%=:\n\t"
        "mbarrier.try_wait.parity.acquire.cta.shared::cta.b64 P, [%0], %1, 0x989680;\n\t"
        "@P bra.uni WD_%=;\n\t"
        "bra.uni WL_%=;\n\t"
        "WD_%=:\n\t}"
        :: "r"(addr), "r"(parity) : "memory");
}
__device__ __forceinline__ void tma2d(unsigned smem, const CUtensorMap* m,
                                      int x, int y, unsigned mbar) {
    asm volatile(
        "cp.async.bulk.tensor.2d.shared::cta.global.tile.mbarrier::complete_tx::bytes "
        "[%0], [%1, {%2, %3}], [%4];"
        :: "r"(smem), "l"(m), "r"(x), "r"(y), "r"(mbar) : "memory");
}
__device__ __forceinline__ void ldsm4(unsigned* r, unsigned addr) {
    asm volatile("ldmatrix.sync.aligned.m8n8.x4.shared.b16 {%0,%1,%2,%3}, [%4];"
        : "=r"(r[0]), "=r"(r[1]), "=r"(r[2]), "=r"(r[3]) : "r"(addr));
}
__device__ __forceinline__ void ldsm4t(unsigned* r, unsigned addr) {
    asm volatile("ldmatrix.sync.aligned.m8n8.x4.trans.shared.b16 {%0,%1,%2,%3}, [%4];"
        : "=r"(r[0]), "=r"(r[1]), "=r"(r[2]), "=r"(r[3]) : "r"(addr));
}
__device__ __forceinline__ void mma16816h(float* c, const unsigned* a, const unsigned* b) {
    asm volatile("mma.sync.aligned.m16n8k16.row.col.f32.f16.f16.f32 "
        "{%0,%1,%2,%3}, {%4,%5,%6,%7}, {%8,%9}, {%0,%1,%2,%3};"
        : "+f"(c[0]), "+f"(c[1]), "+f"(c[2]), "+f"(c[3])
        : "r"(a[0]), "r"(a[1]), "r"(a[2]), "r"(a[3]), "r"(b[0]), "r"(b[1]));
}
__device__ __forceinline__ unsigned packh2(float lo, float hi) {
    unsigned u;
    asm("{ .reg .b16 l, h; cvt.rn.f16.f32 l, %1; cvt.rn.f16.f32 h, %2; "
        "mov.b32 %0, {l, h}; }" : "=r"(u) : "f"(lo), "f"(hi));
    return u;
}
__device__ __forceinline__ float fexp(float x) {
    x = fmaxf(x, -80.0f);
    const float z = x * 1.4426950408889634f;
    const float zf = z + 12582912.0f;
    const int n = __float_as_int(zf);
    const float r = z - (zf - 12582912.0f);
    float p = 0.009618129f;
    p = fmaf(p, r, 0.05550411f);
    p = fmaf(p, r, 0.2402265f);
    p = fmaf(p, r, 0.6931472f);
    p = fmaf(p, r, 1.0f);
    return p * __int_as_float((n << 23) + 0x3F800000);
}

// ---------------- fp32 -> fp16 convert ----------------
__global__ __launch_bounds__(256) void tof16(const float* __restrict__ src,
                                             unsigned short* __restrict__ dst)
{
    const size_t i = ((size_t)blockIdx.x * 256 + threadIdx.x) * 2;
    const float2 v = *(const float2*)(src + i);
    *(unsigned*)(dst + i) = packh2(v.x, v.y);
}

// ---------------- TMA fp16 HMMA GEMM, 256x128 tile, 4-stage ring, no block sync ----
// MODE 0: A=xf, B=w1f -> q split fp16 (scaled 0.125) + k,v fp16. MODE 1: out+bias.
template <int MODE>
__global__ __launch_bounds__(256) void gemm_tma(
    const __grid_constant__ CUtensorMap tA, const __grid_constant__ CUtensorMap tB,
    const float* __restrict__ bias, float* __restrict__ out)
{
    extern __shared__ __align__(16) unsigned char smraw[];
    const unsigned sb = (smem_u32(smraw) + 1023u) & ~1023u;
    const unsigned ctrl = sb + 4u * GSTG;   // full[0..3] @ +0..24, empty[0..3] @ +32..56

    const int tid = threadIdx.x, lane = tid & 31, wid = tid >> 5;
    const int wm = wid & 3, wn = wid >> 2;                  // 4(m) x 2(n)
    const int m0 = blockIdx.y * 256, n0 = blockIdx.x * 128;

    if (tid == 0) {
#pragma unroll
        for (int i = 0; i < 4; i++) { mbar_init(ctrl + i * 8u, 1); mbar_init(ctrl + 32u + i * 8u, 8); }
    }
    __syncthreads();

    auto issue = [&](int s) {   // tid 0 only
        const unsigned base = sb + (unsigned)(s & 3) * GSTG;
        const unsigned mb = ctrl + (unsigned)(s & 3) * 8u;
        mbar_expect(mb, GSTG);
        const int kc = s * 64;
        tma2d(base,           &tA, kc, m0, mb);             // 256x64 fp16 = 32KB
        tma2d(base + 32768u,  &tB, kc, n0, mb);             // 128x64 fp16 = 16KB
    };
    if (tid == 0) { issue(0); issue(1); issue(2); issue(3); }

    const int arow = wm * 64 + (lane & 15);
    const unsigned acolb = (unsigned)((lane >> 4) * 16);
    const unsigned aswz = (unsigned)((arow & 7) << 4);
    const int brow = wn * 64 + (lane & 7) + ((lane >> 4) << 3);
    const unsigned bbase0 = (unsigned)(brow * 128);
    const unsigned bcolb = (unsigned)(((lane >> 3) & 1) * 16);
    const unsigned bswz = (unsigned)((brow & 7) << 4);

    float acc[4][8][4];
#pragma unroll
    for (int i = 0; i < 4; i++)
#pragma unroll
        for (int j = 0; j < 8; j++)
#pragma unroll
            for (int q = 0; q < 4; q++) acc[i][j][q] = 0.0f;

    for (int s = 0; s < 16; s++) {                          // K = 1024 / 64
        const unsigned slot = (unsigned)(s & 3);
        const unsigned stb = sb + slot * GSTG;
        mbar_wait(ctrl + slot * 8u, (unsigned)((s >> 2) & 1));
#pragma unroll
        for (int ks = 0; ks < 4; ks++) {
            unsigned af[4][4], bf[4][4];
            const unsigned ac = (acolb + ks * 32) ^ aswz;
#pragma unroll
            for (int mi = 0; mi < 4; mi++)
                ldsm4(af[mi], stb + (unsigned)((arow + mi * 16) * 128) + ac);
            const unsigned bc = (bcolb + ks * 32) ^ bswz;
#pragma unroll
            for (int nb = 0; nb < 4; nb++)
                ldsm4(bf[nb], stb + 32768u + bbase0 + nb * 2048u + bc);
#pragma unroll
            for (int mi = 0; mi < 4; mi++)
#pragma unroll
                for (int nb = 0; nb < 4; nb++) {
                    mma16816h(acc[mi][2 * nb],     af[mi], &bf[nb][0]);
                    mma16816h(acc[mi][2 * nb + 1], af[mi], &bf[nb][2]);
                }
        }
        if (lane == 0) mbar_arrive(ctrl + 32u + slot * 8u);
        if (tid == 0 && s + 4 < 16) {
            mbar_wait(ctrl + 32u + slot * 8u, (unsigned)((s >> 2) & 1));
            issue(s + 4);
        }
    }

    const int g = lane >> 2, tig = lane & 3;
    if (MODE == 0) {
        const int nblock = n0 + wn * 64;                    // one (sec, head)
        const int sec = nblock >> 10;
        const int h = (nblock & 1023) >> 6;
        if (sec == 0) {                                     // q -> fp16 h/l, scaled
#pragma unroll
            for (int mi = 0; mi < 4; mi++) {
                const int m1 = m0 + wm * 64 + mi * 16 + g;
                const int b = m1 >> 11, t = m1 & 2047;
                const size_t rb = (size_t)((b * Hn + h) * Tn + t) * Dn;
#pragma unroll
                for (int ni = 0; ni < 8; ni++) {
                    const int d = ni * 8 + 2 * tig;
#pragma unroll
                    for (int half = 0; half < 2; half++) {
                        const float v0 = acc[mi][ni][2 * half] * 0.125f;
                        const float v1 = acc[mi][ni][2 * half + 1] * 0.125f;
                        const float h0 = __half2float(__float2half(v0));
                        const float h1 = __half2float(__float2half(v1));
                        const size_t o = rb + (size_t)half * 8 * Dn + d;
                        *(unsigned*)&g_qf[o] = packh2(h0, h1);
                        *(unsigned*)&g_ql[o] = packh2(v0 - h0, v1 - h1);
                    }
                }
            }
        } else {                                            // k or v -> fp16 single
            unsigned short* dst = (sec == 1) ? g_kf : g_vf;
#pragma unroll
            for (int mi = 0; mi < 4; mi++) {
                const int m1 = m0 + wm * 64 + mi * 16 + g;
                const int b = m1 >> 11, t = m1 & 2047;
                const size_t rb = (size_t)((b * Hn + h) * Tn + t) * Dn;
#pragma unroll
                for (int ni = 0; ni < 8; ni++) {
                    const int d = ni * 8 + 2 * tig;
#pragma unroll
                    for (int half = 0; half < 2; half++) {
                        const size_t o = rb + (size_t)half * 8 * Dn + d;
                        *(unsigned*)&dst[o] =
                            packh2(acc[mi][ni][2 * half], acc[mi][ni][2 * half + 1]);
                    }
                }
            }
        }
    } else {
#pragma unroll
        for (int mi = 0; mi < 4; mi++) {
            const int m1 = m0 + wm * 64 + mi * 16 + g;
#pragma unroll
            for (int ni = 0; ni < 8; ni++) {
                const int n = n0 + wn * 64 + ni * 8 + 2 * tig;
                const float2 bb = *(const float2*)(bias + n);
                float2 lo = {acc[mi][ni][0] + bb.x, acc[mi][ni][1] + bb.y};
                float2 hi = {acc[mi][ni][2] + bb.x, acc[mi][ni][3] + bb.y};
                *(float2*)(out + (size_t)m1 * Cn + n) = lo;
                *(float2*)(out + (size_t)(m1 + 8) * Cn + n) = hi;
            }
        }
    }
}

// ---------------- TMA flash attention: fp16 2-term QK, fp16 PV ----------------
// Grid (16, B*H), 256 thr / 8 warps, 128-row Q tile, 64-row KV tiles, 3-stage ring.
__global__ __launch_bounds__(256) void attn_tma(
    const __grid_constant__ CUtensorMap tQf, const __grid_constant__ CUtensorMap tQl,
    const __grid_constant__ CUtensorMap tKf, const __grid_constant__ CUtensorMap tVf)
{
    extern __shared__ __align__(16) unsigned char smraw[];
    const unsigned sb = (smem_u32(smraw) + 1023u) & ~1023u;
    const unsigned kvb = sb + 32768u;                       // 3 KV stages x 16384
    const unsigned ctrl = kvb + 3u * 16384u;  // qbar, full[0..2] @+8.., empty[0..2] @+32..

    const int tid = threadIdx.x, lane = tid & 31, wid = tid >> 5;
    const int qt = (int)gridDim.x - 1 - (int)blockIdx.x;    // heavy tiles first
    const int bh = blockIdx.y;
    const int g = lane >> 2, tig = lane & 3;
    const int grow0 = bh * Tn;
    const int nkt = 2 * qt + 2;

    if (tid == 0) {
        mbar_init(ctrl, 1);
        mbar_init(ctrl + 8, 1);  mbar_init(ctrl + 16, 1); mbar_init(ctrl + 24, 1);
        mbar_init(ctrl + 32, 8); mbar_init(ctrl + 40, 8); mbar_init(ctrl + 48, 8);
    }
    __syncthreads();

    auto issue_kv = [&](int s) {   // tid 0 only
        const unsigned base = kvb + (unsigned)(s % 3) * 16384u;
        const unsigned mb = ctrl + 8u + (unsigned)(s % 3) * 8u;
        mbar_expect(mb, 16384u);
        const int y = grow0 + s * 64;
        tma2d(base,          &tKf, 0, y, mb);
        tma2d(base + 8192u,  &tVf, 0, y, mb);
    };
    if (tid == 0) {
        mbar_expect(ctrl, 32768u);
        tma2d(sb,           &tQf, 0, grow0 + qt * 128, ctrl);
        tma2d(sb + 16384u,  &tQl, 0, grow0 + qt * 128, ctrl);
        issue_kv(0); issue_kv(1);
        if (nkt > 2) issue_kv(2);
    }

    // Q fragments -> registers (warp w owns rows w*16..+15)
    mbar_wait(ctrl, 0u);
    const int qrow = wid * 16 + (lane & 15);
    const unsigned qswz = (unsigned)((qrow & 7) << 4);
    unsigned aqf[4][4], aql[4][4];
#pragma unroll
    for (int ks = 0; ks < 4; ks++) {
        const unsigned ac = (unsigned)((lane >> 4) * 16 + ks * 32) ^ qswz;
        ldsm4(aqf[ks], sb + (unsigned)(qrow * 128) + ac);
        ldsm4(aql[ks], sb + 16384u + (unsigned)(qrow * 128) + ac);
    }

    const int brow = (lane & 7) + ((lane >> 4) << 3);
    const unsigned bbase0 = (unsigned)(brow * 128);
    const unsigned bcolb = (unsigned)(((lane >> 3) & 1) * 16);
    const unsigned bswz = (unsigned)((brow & 7) << 4);
    const int vrow = (((lane >> 3) & 1) << 3) + (lane & 7);
    const unsigned vbase0 = (unsigned)(vrow * 128);
    const unsigned vd2 = (unsigned)((lane >> 4) * 16);
    const unsigned vswz = (unsigned)((vrow & 7) << 4);

    float O[8][4];
#pragma unroll
    for (int i = 0; i < 8; i++)
#pragma unroll
        for (int q = 0; q < 4; q++) O[i][q] = 0.0f;
    float m0r = -1e30f, m1r = -1e30f, l0 = 0.0f, l1 = 0.0f;
    const int qrow_g = qt * 128 + wid * 16 + g;

    for (int kt = 0; kt < nkt; kt++) {
        const unsigned slot = (unsigned)(kt % 3);
        const unsigned stb = kvb + slot * 16384u;
        mbar_wait(ctrl + 8u + slot * 8u, (unsigned)((kt / 3) & 1));

        // ---- S = Q K^T (2-term fp16: qf*kf + ql*kf) ----
        float sc[8][4];
#pragma unroll
        for (int i = 0; i < 8; i++)
#pragma unroll
            for (int q = 0; q < 4; q++) sc[i][q] = 0.0f;
#pragma unroll
        for (int ks = 0; ks < 4; ks++) {
            unsigned bkf[4][4];
            const unsigned bc = (bcolb + ks * 32) ^ bswz;
#pragma unroll
            for (int nb = 0; nb < 4; nb++)
                ldsm4(bkf[nb], stb + bbase0 + nb * 2048u + bc);
#pragma unroll
            for (int nb = 0; nb < 4; nb++) {
                mma16816h(sc[2 * nb],     aqf[ks], &bkf[nb][0]);
                mma16816h(sc[2 * nb + 1], aqf[ks], &bkf[nb][2]);
                mma16816h(sc[2 * nb],     aql[ks], &bkf[nb][0]);
                mma16816h(sc[2 * nb + 1], aql[ks], &bkf[nb][2]);
            }
        }

        if (kt >= 2 * qt) {                     // diagonal band -> causal mask
            const int kb = kt * 64 + 2 * tig;
#pragma unroll
            for (int ni = 0; ni < 8; ni++) {
                const int key = kb + ni * 8;
                if (key > qrow_g)         sc[ni][0] = -1e30f;
                if (key + 1 > qrow_g)     sc[ni][1] = -1e30f;
                if (key > qrow_g + 8)     sc[ni][2] = -1e30f;
                if (key + 1 > qrow_g + 8) sc[ni][3] = -1e30f;
            }
        }

        // ---- online softmax ----
        float mx0 = -1e30f, mx1 = -1e30f;
#pragma unroll
        for (int ni = 0; ni < 8; ni++) {
            mx0 = fmaxf(mx0, fmaxf(sc[ni][0], sc[ni][1]));
            mx1 = fmaxf(mx1, fmaxf(sc[ni][2], sc[ni][3]));
        }
        mx0 = fmaxf(mx0, __shfl_xor_sync(0xFFFFFFFF, mx0, 1));
        mx0 = fmaxf(mx0, __shfl_xor_sync(0xFFFFFFFF, mx0, 2));
        mx1 = fmaxf(mx1, __shfl_xor_sync(0xFFFFFFFF, mx1, 1));
        mx1 = fmaxf(mx1, __shfl_xor_sync(0xFFFFFFFF, mx1, 2));
        const float nm0 = fmaxf(m0r, mx0), nm1 = fmaxf(m1r, mx1);
        const float cr0 = fexp(m0r - nm0), cr1 = fexp(m1r - nm1);
        m0r = nm0; m1r = nm1;
        l0 *= cr0; l1 *= cr1;
#pragma unroll
        for (int ni = 0; ni < 8; ni++) {
            O[ni][0] *= cr0; O[ni][1] *= cr0;
            O[ni][2] *= cr1; O[ni][3] *= cr1;
        }
        float ps0 = 0.0f, ps1 = 0.0f;
#pragma unroll
        for (int ni = 0; ni < 8; ni++) {
            sc[ni][0] = fexp(sc[ni][0] - nm0);
            sc[ni][1] = fexp(sc[ni][1] - nm0);
            sc[ni][2] = fexp(sc[ni][2] - nm1);
            sc[ni][3] = fexp(sc[ni][3] - nm1);
            ps0 += sc[ni][0] + sc[ni][1];
            ps1 += sc[ni][2] + sc[ni][3];
        }
        l0 += ps0; l1 += ps1;

        // ---- pack P as fp16 ----
        unsigned apf[4][4];
#pragma unroll
        for (int j = 0; j < 4; j++) {
            apf[j][0] = packh2(sc[2 * j][0], sc[2 * j][1]);
            apf[j][1] = packh2(sc[2 * j][2], sc[2 * j][3]);
            apf[j][2] = packh2(sc[2 * j + 1][0], sc[2 * j + 1][1]);
            apf[j][3] = packh2(sc[2 * j + 1][2], sc[2 * j + 1][3]);
        }

        // ---- O += P V (fp16) ----
#pragma unroll
        for (int j = 0; j < 4; j++) {
#pragma unroll
            for (int db = 0; db < 4; db++) {
                unsigned vf[4];
                const unsigned off = vbase0 + j * 2048u + ((db * 32u + vd2) ^ vswz);
                ldsm4t(vf, stb + 8192u + off);
                mma16816h(O[2 * db],     apf[j], &vf[0]);
                mma16816h(O[2 * db + 1], apf[j], &vf[2]);
            }
        }

        // ---- release slot ----
        if (lane == 0) mbar_arrive(ctrl + 32u + slot * 8u);
        if (tid == 0 && kt + 3 < nkt) {
            mbar_wait(ctrl + 32u + slot * 8u, (unsigned)((kt / 3) & 1));
            issue_kv(kt + 3);
        }
    }

    // ---- epilogue: ao -> fp16 single ----
    l0 += __shfl_xor_sync(0xFFFFFFFF, l0, 1);
    l0 += __shfl_xor_sync(0xFFFFFFFF, l0, 2);
    l1 += __shfl_xor_sync(0xFFFFFFFF, l1, 1);
    l1 += __shfl_xor_sync(0xFFFFFFFF, l1, 2);
    const float inv0 = 1.0f / l0, inv1 = 1.0f / l1;

    const int b = bh >> 4, h = bh & 15;
    const size_t r0 = (size_t)(b * Tn + qrow_g) * Cn;
    const size_t r1 = (size_t)(b * Tn + qrow_g + 8) * Cn;
#pragma unroll
    for (int ni = 0; ni < 8; ni++) {
        const int k = h * Dn + ni * 8 + 2 * tig;
        *(unsigned*)&g_aof[r0 + k] = packh2(O[ni][0] * inv0, O[ni][1] * inv0);
        *(unsigned*)&g_aof[r1 + k] = packh2(O[ni][2] * inv1, O[ni][3] * inv1);
    }
}

// ---------------- host ----------------
typedef CUresult (CUDAAPI* EncodeFn)(
    CUtensorMap*, CUtensorMapDataType, cuuint32_t, void*,
    const cuuint64_t*, const cuuint64_t*, const cuuint32_t*, const cuuint32_t*,
    CUtensorMapInterleave, CUtensorMapSwizzle, CUtensorMapL2promotion,
    CUtensorMapFloatOOBfill);

static void mk_map(EncodeFn enc, CUtensorMap* m, void* base, CUtensorMapDataType dt,
                   unsigned long long rows, unsigned long long cols,
                   unsigned boxc, unsigned boxr)
{
    cuuint64_t dims[2] = {cols, rows};
    cuuint64_t strides[1] = {cols * 2};
    cuuint32_t box[2] = {boxc, boxr};
    cuuint32_t es[2] = {1, 1};
    enc(m, dt, 2, base, dims, strides, box, es,
        CU_TENSOR_MAP_INTERLEAVE_NONE, CU_TENSOR_MAP_SWIZZLE_128B,
        CU_TENSOR_MAP_L2_PROMOTION_L2_128B, CU_TENSOR_MAP_FLOAT_OOB_FILL_NONE);
}

extern "C" void kernel_launch(void* const* d_in, const int* in_sizes, int n_in,
                              void* d_out, int out_size)
{
    const float* x     = (const float*)d_in[0];
    const float* w_qkv = (const float*)d_in[1];
    const float* w_out = (const float*)d_in[2];
    const float* b_out = (const float*)d_in[3];
    float* out = (float*)d_out;

    void *pXf, *pW1, *pW3, *pAo, *pQf, *pQl, *pKf, *pVf;
    cudaGetSymbolAddress(&pXf, g_xf);
    cudaGetSymbolAddress(&pW1, g_w1f);
    cudaGetSymbolAddress(&pW3, g_w3f);
    cudaGetSymbolAddress(&pAo, g_aof);
    cudaGetSymbolAddress(&pQf, g_qf);   cudaGetSymbolAddress(&pQl, g_ql);
    cudaGetSymbolAddress(&pKf, g_kf);   cudaGetSymbolAddress(&pVf, g_vf);

    EncodeFn enc = nullptr;
    cudaDriverEntryPointQueryResult qr;
    cudaGetDriverEntryPointByVersion("cuTensorMapEncodeTiled", (void**)&enc,
                                     12000, cudaEnableDefault, &qr);

    const auto F16 = CU_TENSOR_MAP_DATA_TYPE_FLOAT16;
    const unsigned long long MR = (unsigned long long)Bn * Tn;        // 8192
    const unsigned long long KVR = (unsigned long long)Bn * Hn * Tn;  // 131072
    CUtensorMap mXf, mW1, mW3, mAo, mQf, mQl, mKf, mVf;
    mk_map(enc, &mXf, pXf, F16, MR, 1024, 64, 256);
    mk_map(enc, &mW1, pW1, F16, 3072, 1024, 64, 128);
    mk_map(enc, &mW3, pW3, F16, 1024, 1024, 64, 128);
    mk_map(enc, &mAo, pAo, F16, MR, 1024, 64, 256);
    mk_map(enc, &mQf, pQf, F16, KVR, 64, 64, 128);
    mk_map(enc, &mQl, pQl, F16, KVR, 64, 64, 128);
    mk_map(enc, &mKf, pKf, F16, KVR, 64, 64, 64);
    mk_map(enc, &mVf, pVf, F16, KVR, 64, 64, 64);

    cudaFuncSetAttribute(gemm_tma<0>, cudaFuncAttributeMaxDynamicSharedMemorySize, GEMM_SMEM);
    cudaFuncSetAttribute(gemm_tma<1>, cudaFuncAttributeMaxDynamicSharedMemorySize, GEMM_SMEM);
    cudaFuncSetAttribute(attn_tma, cudaFuncAttributeMaxDynamicSharedMemorySize, ATTN_SMEM);

    tof16<<<(Bn * Tn * Cn) / 512, 256>>>(x, (unsigned short*)pXf);
    tof16<<<(3 * Cn * Cn) / 512, 256>>>(w_qkv, (unsigned short*)pW1);
    tof16<<<(Cn * Cn) / 512, 256>>>(w_out, (unsigned short*)pW3);
    gemm_tma<0><<<dim3(24, 32), 256, GEMM_SMEM>>>(mXf, mW1, nullptr, nullptr);
    attn_tma<<<dim3(Tn / 128, Bn * Hn), 256, ATTN_SMEM>>>(mQf, mQl, mKf, mVf);
    gemm_tma<1><<<dim3(8, 32), 256, GEMM_SMEM>>>(mAo, mW3, b_out, out);
}

// round 12
// speedup vs baseline: 11.6809x; 1.0202x over previous
#include <cuda.h>
#include <cuda_runtime.h>
#include <cuda_bf16.h>
#include <cuda_fp16.h>

namespace {
constexpr int Bn = 4, Tn = 2048, Cn = 1024, Hn = 16, Dn = 64;
constexpr unsigned GSTG = 49152;                                   // A 32K + B 16K
constexpr unsigned GEMM_SMEM = 4 * GSTG + 1024 + 64;               // 4-stage ring
constexpr unsigned KVSTG = 32768;                                  // K 16K + V 16K (128 keys)
constexpr unsigned ATTN_SMEM = 32768 + 3 * KVSTG + 1024 + 64;      // Q(2x16K) + 3 KV stages
}

// ---------------- scratch (device globals; no allocs allowed) ----------------
__device__ __align__(16) unsigned short g_xf[(size_t)Bn * Tn * Cn];     // fp16 x
__device__ __align__(16) unsigned short g_w1f[(size_t)3 * Cn * Cn];     // fp16 w_qkv
__device__ __align__(16) unsigned short g_w3f[(size_t)Cn * Cn];         // fp16 w_out
__device__ __align__(16) unsigned short g_aof[(size_t)Bn * Tn * Cn];    // fp16 attn out
__device__ __align__(16) unsigned short g_qf[(size_t)Bn * Hn * Tn * Dn]; // fp16 q high
__device__ __align__(16) unsigned short g_ql[(size_t)Bn * Hn * Tn * Dn]; // fp16 q low
__device__ __align__(16) unsigned short g_kf[(size_t)Bn * Hn * Tn * Dn]; // fp16 k
__device__ __align__(16) unsigned short g_vf[(size_t)Bn * Hn * Tn * Dn]; // fp16 v

// ---------------- device helpers ----------------
__device__ __forceinline__ unsigned smem_u32(const void* p) {
    unsigned a;
    asm("{ .reg .u64 t; cvta.to.shared.u64 t, %1; cvt.u32.u64 %0, t; }" : "=r"(a) : "l"(p));
    return a;
}
__device__ __forceinline__ void mbar_init(unsigned addr, unsigned cnt) {
    asm volatile("mbarrier.init.shared.b64 [%0], %1;" :: "r"(addr), "r"(cnt) : "memory");
}
__device__ __forceinline__ void mbar_arrive(unsigned addr) {
    asm volatile("mbarrier.arrive.shared.b64 _, [%0];" :: "r"(addr) : "memory");
}
__device__ __forceinline__ void mbar_expect(unsigned addr, unsigned bytes) {
    asm volatile("mbarrier.arrive.expect_tx.shared.b64 _, [%0], %1;"
                 :: "r"(addr), "r"(bytes) : "memory");
}
__device__ __forceinline__ void mbar_wait(unsigned addr, unsigned parity) {
    asm volatile(
        "{\n\t.reg .pred P;\n\t"
        "WL_%=:\n\t"
        "mbarrier.try_wait.parity.acquire.cta.shared::cta.b64 P, [%0], %1, 0x989680;\n\t"
        "@P bra.uni WD_%=;\n\t"
        "bra.uni WL_%=;\n\t"
        "WD_%=:\n\t}"
        :: "r"(addr), "r"(parity) : "memory");
}
__device__ __forceinline__ void tma2d(unsigned smem, const CUtensorMap* m,
                                      int x, int y, unsigned mbar) {
    asm volatile(
        "cp.async.bulk.tensor.2d.shared::cta.global.tile.mbarrier::complete_tx::bytes "
        "[%0], [%1, {%2, %3}], [%4];"
        :: "r"(smem), "l"(m), "r"(x), "r"(y), "r"(mbar) : "memory");
}
__device__ __forceinline__ void ldsm4(unsigned* r, unsigned addr) {
    asm volatile("ldmatrix.sync.aligned.m8n8.x4.shared.b16 {%0,%1,%2,%3}, [%4];"
        : "=r"(r[0]), "=r"(r[1]), "=r"(r[2]), "=r"(r[3]) : "r"(addr));
}
__device__ __forceinline__ void ldsm4t(unsigned* r, unsigned addr) {
    asm volatile("ldmatrix.sync.aligned.m8n8.x4.trans.shared.b16 {%0,%1,%2,%3}, [%4];"
        : "=r"(r[0]), "=r"(r[1]), "=r"(r[2]), "=r"(r[3]) : "r"(addr));
}
__device__ __forceinline__ void mma16816h(float* c, const unsigned* a, const unsigned* b) {
    asm volatile("mma.sync.aligned.m16n8k16.row.col.f32.f16.f16.f32 "
        "{%0,%1,%2,%3}, {%4,%5,%6,%7}, {%8,%9}, {%0,%1,%2,%3};"
        : "+f"(c[0]), "+f"(c[1]), "+f"(c[2]), "+f"(c[3])
        : "r"(a[0]), "r"(a[1]), "r"(a[2]), "r"(a[3]), "r"(b[0]), "r"(b[1]));
}
__device__ __forceinline__ unsigned packh2(float lo, float hi) {
    unsigned u;
    asm("{ .reg .b16 l, h; cvt.rn.f16.f32 l, %1; cvt.rn.f16.f32 h, %2; "
        "mov.b32 %0, {l, h}; }" : "=r"(u) : "f"(lo), "f"(hi));
    return u;
}
__device__ __forceinline__ float fexp(float x) {
    x = fmaxf(x, -80.0f);
    const float z = x * 1.4426950408889634f;
    const float zf = z + 12582912.0f;
    const int n = __float_as_int(zf);
    const float r = z - (zf - 12582912.0f);
    float p = 0.009618129f;
    p = fmaf(p, r, 0.05550411f);
    p = fmaf(p, r, 0.2402265f);
    p = fmaf(p, r, 0.6931472f);
    p = fmaf(p, r, 1.0f);
    return p * __int_as_float((n << 23) + 0x3F800000);
}

// ---------------- fp32 -> fp16 convert (x, w_qkv, w_out in ONE launch) ----------------
// pair ranges: x [0, 4194304), w1 [4194304, 5767168), w3 [5767168, 6291456)
__global__ __launch_bounds__(256) void tof16_all(const float* __restrict__ x,
                                                 const float* __restrict__ w1,
                                                 const float* __restrict__ w3)
{
    const size_t p = (size_t)blockIdx.x * 256 + threadIdx.x;
    const float* src;
    unsigned short* dst;
    size_t off;
    if (p < 4194304u) { src = x; dst = g_xf; off = p; }
    else if (p < 5767168u) { src = w1; dst = g_w1f; off = p - 4194304u; }
    else { src = w3; dst = g_w3f; off = p - 5767168u; }
    const float2 v = *(const float2*)(src + off * 2);
    *(unsigned*)(dst + off * 2) = packh2(v.x, v.y);
}

// ---------------- TMA fp16 HMMA GEMM, 256x128 tile, 4-stage ring, no block sync ----
// MODE 0: A=xf, B=w1f -> q split fp16 (scaled 0.125) + k,v fp16. MODE 1: out+bias.
template <int MODE>
__global__ __launch_bounds__(256) void gemm_tma(
    const __grid_constant__ CUtensorMap tA, const __grid_constant__ CUtensorMap tB,
    const float* __restrict__ bias, float* __restrict__ out)
{
    extern __shared__ __align__(16) unsigned char smraw[];
    const unsigned sb = (smem_u32(smraw) + 1023u) & ~1023u;
    const unsigned ctrl = sb + 4u * GSTG;   // full[0..3] @ +0..24, empty[0..3] @ +32..56

    const int tid = threadIdx.x, lane = tid & 31, wid = tid >> 5;
    const int wm = wid & 3, wn = wid >> 2;                  // 4(m) x 2(n)
    const int m0 = blockIdx.y * 256, n0 = blockIdx.x * 128;

    if (tid == 0) {
#pragma unroll
        for (int i = 0; i < 4; i++) { mbar_init(ctrl + i * 8u, 1); mbar_init(ctrl + 32u + i * 8u, 8); }
    }
    __syncthreads();

    auto issue = [&](int s) {   // tid 0 only
        const unsigned base = sb + (unsigned)(s & 3) * GSTG;
        const unsigned mb = ctrl + (unsigned)(s & 3) * 8u;
        mbar_expect(mb, GSTG);
        const int kc = s * 64;
        tma2d(base,           &tA, kc, m0, mb);             // 256x64 fp16 = 32KB
        tma2d(base + 32768u,  &tB, kc, n0, mb);             // 128x64 fp16 = 16KB
    };
    if (tid == 0) { issue(0); issue(1); issue(2); issue(3); }

    const int arow = wm * 64 + (lane & 15);
    const unsigned acolb = (unsigned)((lane >> 4) * 16);
    const unsigned aswz = (unsigned)((arow & 7) << 4);
    const int brow = wn * 64 + (lane & 7) + ((lane >> 4) << 3);
    const unsigned bbase0 = (unsigned)(brow * 128);
    const unsigned bcolb = (unsigned)(((lane >> 3) & 1) * 16);
    const unsigned bswz = (unsigned)((brow & 7) << 4);

    float acc[4][8][4];
#pragma unroll
    for (int i = 0; i < 4; i++)
#pragma unroll
        for (int j = 0; j < 8; j++)
#pragma unroll
            for (int q = 0; q < 4; q++) acc[i][j][q] = 0.0f;

    for (int s = 0; s < 16; s++) {                          // K = 1024 / 64
        const unsigned slot = (unsigned)(s & 3);
        const unsigned stb = sb + slot * GSTG;
        mbar_wait(ctrl + slot * 8u, (unsigned)((s >> 2) & 1));
#pragma unroll
        for (int ks = 0; ks < 4; ks++) {
            unsigned af[4][4], bf[4][4];
            const unsigned ac = (acolb + ks * 32) ^ aswz;
#pragma unroll
            for (int mi = 0; mi < 4; mi++)
                ldsm4(af[mi], stb + (unsigned)((arow + mi * 16) * 128) + ac);
            const unsigned bc = (bcolb + ks * 32) ^ bswz;
#pragma unroll
            for (int nb = 0; nb < 4; nb++)
                ldsm4(bf[nb], stb + 32768u + bbase0 + nb * 2048u + bc);
#pragma unroll
            for (int mi = 0; mi < 4; mi++)
#pragma unroll
                for (int nb = 0; nb < 4; nb++) {
                    mma16816h(acc[mi][2 * nb],     af[mi], &bf[nb][0]);
                    mma16816h(acc[mi][2 * nb + 1], af[mi], &bf[nb][2]);
                }
        }
        if (lane == 0) mbar_arrive(ctrl + 32u + slot * 8u);
        if (tid == 0 && s + 4 < 16) {
            mbar_wait(ctrl + 32u + slot * 8u, (unsigned)((s >> 2) & 1));
            issue(s + 4);
        }
    }

    const int g = lane >> 2, tig = lane & 3;
    if (MODE == 0) {
        const int nblock = n0 + wn * 64;                    // one (sec, head)
        const int sec = nblock >> 10;
        const int h = (nblock & 1023) >> 6;
        if (sec == 0) {                                     // q -> fp16 h/l, scaled
#pragma unroll
            for (int mi = 0; mi < 4; mi++) {
                const int m1 = m0 + wm * 64 + mi * 16 + g;
                const int b = m1 >> 11, t = m1 & 2047;
                const size_t rb = (size_t)((b * Hn + h) * Tn + t) * Dn;
#pragma unroll
                for (int ni = 0; ni < 8; ni++) {
                    const int d = ni * 8 + 2 * tig;
#pragma unroll
                    for (int half = 0; half < 2; half++) {
                        const float v0 = acc[mi][ni][2 * half] * 0.125f;
                        const float v1 = acc[mi][ni][2 * half + 1] * 0.125f;
                        const float h0 = __half2float(__float2half(v0));
                        const float h1 = __half2float(__float2half(v1));
                        const size_t o = rb + (size_t)half * 8 * Dn + d;
                        *(unsigned*)&g_qf[o] = packh2(h0, h1);
                        *(unsigned*)&g_ql[o] = packh2(v0 - h0, v1 - h1);
                    }
                }
            }
        } else {                                            // k or v -> fp16 single
            unsigned short* dst = (sec == 1) ? g_kf : g_vf;
#pragma unroll
            for (int mi = 0; mi < 4; mi++) {
                const int m1 = m0 + wm * 64 + mi * 16 + g;
                const int b = m1 >> 11, t = m1 & 2047;
                const size_t rb = (size_t)((b * Hn + h) * Tn + t) * Dn;
#pragma unroll
                for (int ni = 0; ni < 8; ni++) {
                    const int d = ni * 8 + 2 * tig;
#pragma unroll
                    for (int half = 0; half < 2; half++) {
                        const size_t o = rb + (size_t)half * 8 * Dn + d;
                        *(unsigned*)&dst[o] =
                            packh2(acc[mi][ni][2 * half], acc[mi][ni][2 * half + 1]);
                    }
                }
            }
        }
    } else {
#pragma unroll
        for (int mi = 0; mi < 4; mi++) {
            const int m1 = m0 + wm * 64 + mi * 16 + g;
#pragma unroll
            for (int ni = 0; ni < 8; ni++) {
                const int n = n0 + wn * 64 + ni * 8 + 2 * tig;
                const float2 bb = *(const float2*)(bias + n);
                float2 lo = {acc[mi][ni][0] + bb.x, acc[mi][ni][1] + bb.y};
                float2 hi = {acc[mi][ni][2] + bb.x, acc[mi][ni][3] + bb.y};
                *(float2*)(out + (size_t)m1 * Cn + n) = lo;
                *(float2*)(out + (size_t)(m1 + 8) * Cn + n) = hi;
            }
        }
    }
}

// ---------------- TMA flash attention: 128-key KV tiles, one softmax per tile ----
// Grid (16, B*H), 256 thr / 8 warps, 128-row Q tile, 128-row KV tiles, 3-stage ring.
__global__ __launch_bounds__(256) void attn_tma(
    const __grid_constant__ CUtensorMap tQf, const __grid_constant__ CUtensorMap tQl,
    const __grid_constant__ CUtensorMap tKf, const __grid_constant__ CUtensorMap tVf)
{
    extern __shared__ __align__(16) unsigned char smraw[];
    const unsigned sb = (smem_u32(smraw) + 1023u) & ~1023u;
    const unsigned kvb = sb + 32768u;                       // 3 KV stages x 32768
    const unsigned ctrl = kvb + 3u * KVSTG;  // qbar, full[0..2] @+8.., empty[0..2] @+32..

    const int tid = threadIdx.x, lane = tid & 31, wid = tid >> 5;
    const int qt = (int)gridDim.x - 1 - (int)blockIdx.x;    // heavy tiles first
    const int bh = blockIdx.y;
    const int g = lane >> 2, tig = lane & 3;
    const int grow0 = bh * Tn;
    const int nkt = qt + 1;                                 // 128-key tiles

    if (tid == 0) {
        mbar_init(ctrl, 1);
        mbar_init(ctrl + 8, 1);  mbar_init(ctrl + 16, 1); mbar_init(ctrl + 24, 1);
        mbar_init(ctrl + 32, 8); mbar_init(ctrl + 40, 8); mbar_init(ctrl + 48, 8);
    }
    __syncthreads();

    auto issue_kv = [&](int s) {   // tid 0 only
        const unsigned base = kvb + (unsigned)(s % 3) * KVSTG;
        const unsigned mb = ctrl + 8u + (unsigned)(s % 3) * 8u;
        mbar_expect(mb, KVSTG);
        const int y = grow0 + s * 128;
        tma2d(base,           &tKf, 0, y, mb);              // 128x64 fp16 = 16KB
        tma2d(base + 16384u,  &tVf, 0, y, mb);
    };
    if (tid == 0) {
        mbar_expect(ctrl, 32768u);
        tma2d(sb,           &tQf, 0, grow0 + qt * 128, ctrl);
        tma2d(sb + 16384u,  &tQl, 0, grow0 + qt * 128, ctrl);
        issue_kv(0);
        if (nkt > 1) issue_kv(1);
        if (nkt > 2) issue_kv(2);
    }

    // Q fragments -> registers (warp w owns rows w*16..+15)
    mbar_wait(ctrl, 0u);
    const int qrow = wid * 16 + (lane & 15);
    const unsigned qswz = (unsigned)((qrow & 7) << 4);
    unsigned aqf[4][4], aql[4][4];
#pragma unroll
    for (int ks = 0; ks < 4; ks++) {
        const unsigned ac = (unsigned)((lane >> 4) * 16 + ks * 32) ^ qswz;
        ldsm4(aqf[ks], sb + (unsigned)(qrow * 128) + ac);
        ldsm4(aql[ks], sb + 16384u + (unsigned)(qrow * 128) + ac);
    }

    const int brow = (lane & 7) + ((lane >> 4) << 3);
    const unsigned bcolb = (unsigned)(((lane >> 3) & 1) * 16);
    const unsigned bswz = (unsigned)((brow & 7) << 4);
    const int vrow = (((lane >> 3) & 1) << 3) + (lane & 7);
    const unsigned vd2 = (unsigned)((lane >> 4) * 16);
    const unsigned vswz = (unsigned)((vrow & 7) << 4);

    float O[8][4];
#pragma unroll
    for (int i = 0; i < 8; i++)
#pragma unroll
        for (int q = 0; q < 4; q++) O[i][q] = 0.0f;
    float m0r = -1e30f, m1r = -1e30f, l0 = 0.0f, l1 = 0.0f;
    const int qrow_g = qt * 128 + wid * 16 + g;

    for (int kt = 0; kt < nkt; kt++) {
        const unsigned slot = (unsigned)(kt % 3);
        const unsigned stb = kvb + slot * KVSTG;
        mbar_wait(ctrl + 8u + slot * 8u, (unsigned)((kt / 3) & 1));

        // ---- S[128q x 128k] = Q K^T (2-term fp16) ----
        float sc[16][4];
#pragma unroll
        for (int i = 0; i < 16; i++)
#pragma unroll
            for (int q = 0; q < 4; q++) sc[i][q] = 0.0f;
#pragma unroll
        for (int ks = 0; ks < 4; ks++) {
            const unsigned bc = (bcolb + ks * 32) ^ bswz;
#pragma unroll
            for (int nb = 0; nb < 8; nb++) {
                unsigned bkf[4];
                ldsm4(bkf, stb + (unsigned)((nb * 16 + brow) * 128) + bc);
                mma16816h(sc[2 * nb],     aqf[ks], &bkf[0]);
                mma16816h(sc[2 * nb + 1], aqf[ks], &bkf[2]);
                mma16816h(sc[2 * nb],     aql[ks], &bkf[0]);
                mma16816h(sc[2 * nb + 1], aql[ks], &bkf[2]);
            }
        }

        if (kt == qt) {                          // diagonal tile -> causal mask
            const int kb = kt * 128 + 2 * tig;
#pragma unroll
            for (int ni = 0; ni < 16; ni++) {
                const int key = kb + ni * 8;
                if (key > qrow_g)         sc[ni][0] = -1e30f;
                if (key + 1 > qrow_g)     sc[ni][1] = -1e30f;
                if (key > qrow_g + 8)     sc[ni][2] = -1e30f;
                if (key + 1 > qrow_g + 8) sc[ni][3] = -1e30f;
            }
        }

        // ---- online softmax (once per 128 keys) ----
        float mx0 = -1e30f, mx1 = -1e30f;
#pragma unroll
        for (int ni = 0; ni < 16; ni++) {
            mx0 = fmaxf(mx0, fmaxf(sc[ni][0], sc[ni][1]));
            mx1 = fmaxf(mx1, fmaxf(sc[ni][2], sc[ni][3]));
        }
        mx0 = fmaxf(mx0, __shfl_xor_sync(0xFFFFFFFF, mx0, 1));
        mx0 = fmaxf(mx0, __shfl_xor_sync(0xFFFFFFFF, mx0, 2));
        mx1 = fmaxf(mx1, __shfl_xor_sync(0xFFFFFFFF, mx1, 1));
        mx1 = fmaxf(mx1, __shfl_xor_sync(0xFFFFFFFF, mx1, 2));
        const float nm0 = fmaxf(m0r, mx0), nm1 = fmaxf(m1r, mx1);
        const float cr0 = fexp(m0r - nm0), cr1 = fexp(m1r - nm1);
        m0r = nm0; m1r = nm1;
        l0 *= cr0; l1 *= cr1;
#pragma unroll
        for (int ni = 0; ni < 8; ni++) {
            O[ni][0] *= cr0; O[ni][1] *= cr0;
            O[ni][2] *= cr1; O[ni][3] *= cr1;
        }
        float ps0 = 0.0f, ps1 = 0.0f;
#pragma unroll
        for (int ni = 0; ni < 16; ni++) {
            sc[ni][0] = fexp(sc[ni][0] - nm0);
            sc[ni][1] = fexp(sc[ni][1] - nm0);
            sc[ni][2] = fexp(sc[ni][2] - nm1);
            sc[ni][3] = fexp(sc[ni][3] - nm1);
            ps0 += sc[ni][0] + sc[ni][1];
            ps1 += sc[ni][2] + sc[ni][3];
        }
        l0 += ps0; l1 += ps1;

        // ---- O += P V (fp16), P packed on the fly ----
#pragma unroll
        for (int j = 0; j < 8; j++) {
            unsigned apf[4];
            apf[0] = packh2(sc[2 * j][0], sc[2 * j][1]);
            apf[1] = packh2(sc[2 * j][2], sc[2 * j][3]);
            apf[2] = packh2(sc[2 * j + 1][0], sc[2 * j + 1][1]);
            apf[3] = packh2(sc[2 * j + 1][2], sc[2 * j + 1][3]);
#pragma unroll
            for (int db = 0; db < 4; db++) {
                unsigned vf[4];
                const unsigned off = (unsigned)((j * 16 + vrow) * 128) + ((db * 32u + vd2) ^ vswz);
                ldsm4t(vf, stb + 16384u + off);
                mma16816h(O[2 * db],     apf, &vf[0]);
                mma16816h(O[2 * db + 1], apf, &vf[2]);
            }
        }

        // ---- release slot ----
        if (lane == 0) mbar_arrive(ctrl + 32u + slot * 8u);
        if (tid == 0 && kt + 3 < nkt) {
            mbar_wait(ctrl + 32u + slot * 8u, (unsigned)((kt / 3) & 1));
            issue_kv(kt + 3);
        }
    }

    // ---- epilogue: ao -> fp16 single ----
    l0 += __shfl_xor_sync(0xFFFFFFFF, l0, 1);
    l0 += __shfl_xor_sync(0xFFFFFFFF, l0, 2);
    l1 += __shfl_xor_sync(0xFFFFFFFF, l1, 1);
    l1 += __shfl_xor_sync(0xFFFFFFFF, l1, 2);
    const float inv0 = 1.0f / l0, inv1 = 1.0f / l1;

    const int b = bh >> 4, h = bh & 15;
    const size_t r0 = (size_t)(b * Tn + qrow_g) * Cn;
    const size_t r1 = (size_t)(b * Tn + qrow_g + 8) * Cn;
#pragma unroll
    for (int ni = 0; ni < 8; ni++) {
        const int k = h * Dn + ni * 8 + 2 * tig;
        *(unsigned*)&g_aof[r0 + k] = packh2(O[ni][0] * inv0, O[ni][1] * inv0);
        *(unsigned*)&g_aof[r1 + k] = packh2(O[ni][2] * inv1, O[ni][3] * inv1);
    }
}

// ---------------- host ----------------
typedef CUresult (CUDAAPI* EncodeFn)(
    CUtensorMap*, CUtensorMapDataType, cuuint32_t, void*,
    const cuuint64_t*, const cuuint64_t*, const cuuint32_t*, const cuuint32_t*,
    CUtensorMapInterleave, CUtensorMapSwizzle, CUtensorMapL2promotion,
    CUtensorMapFloatOOBfill);

static void mk_map(EncodeFn enc, CUtensorMap* m, void* base, CUtensorMapDataType dt,
                   unsigned long long rows, unsigned long long cols,
                   unsigned boxc, unsigned boxr)
{
    cuuint64_t dims[2] = {cols, rows};
    cuuint64_t strides[1] = {cols * 2};
    cuuint32_t box[2] = {boxc, boxr};
    cuuint32_t es[2] = {1, 1};
    enc(m, dt, 2, base, dims, strides, box, es,
        CU_TENSOR_MAP_INTERLEAVE_NONE, CU_TENSOR_MAP_SWIZZLE_128B,
        CU_TENSOR_MAP_L2_PROMOTION_L2_128B, CU_TENSOR_MAP_FLOAT_OOB_FILL_NONE);
}

extern "C" void kernel_launch(void* const* d_in, const int* in_sizes, int n_in,
                              void* d_out, int out_size)
{
    const float* x     = (const float*)d_in[0];
    const float* w_qkv = (const float*)d_in[1];
    const float* w_out = (const float*)d_in[2];
    const float* b_out = (const float*)d_in[3];
    float* out = (float*)d_out;

    void *pXf, *pW1, *pW3, *pAo, *pQf, *pQl, *pKf, *pVf;
    cudaGetSymbolAddress(&pXf, g_xf);
    cudaGetSymbolAddress(&pW1, g_w1f);
    cudaGetSymbolAddress(&pW3, g_w3f);
    cudaGetSymbolAddress(&pAo, g_aof);
    cudaGetSymbolAddress(&pQf, g_qf);   cudaGetSymbolAddress(&pQl, g_ql);
    cudaGetSymbolAddress(&pKf, g_kf);   cudaGetSymbolAddress(&pVf, g_vf);

    EncodeFn enc = nullptr;
    cudaDriverEntryPointQueryResult qr;
    cudaGetDriverEntryPointByVersion("cuTensorMapEncodeTiled", (void**)&enc,
                                     12000, cudaEnableDefault, &qr);

    const auto F16 = CU_TENSOR_MAP_DATA_TYPE_FLOAT16;
    const unsigned long long MR = (unsigned long long)Bn * Tn;        // 8192
    const unsigned long long KVR = (unsigned long long)Bn * Hn * Tn;  // 131072
    CUtensorMap mXf, mW1, mW3, mAo, mQf, mQl, mKf, mVf;
    mk_map(enc, &mXf, pXf, F16, MR, 1024, 64, 256);
    mk_map(enc, &mW1, pW1, F16, 3072, 1024, 64, 128);
    mk_map(enc, &mW3, pW3, F16, 1024, 1024, 64, 128);
    mk_map(enc, &mAo, pAo, F16, MR, 1024, 64, 256);
    mk_map(enc, &mQf, pQf, F16, KVR, 64, 64, 128);
    mk_map(enc, &mQl, pQl, F16, KVR, 64, 64, 128);
    mk_map(enc, &mKf, pKf, F16, KVR, 64, 64, 128);
    mk_map(enc, &mVf, pVf, F16, KVR, 64, 64, 128);

    cudaFuncSetAttribute(gemm_tma<0>, cudaFuncAttributeMaxDynamicSharedMemorySize, GEMM_SMEM);
    cudaFuncSetAttribute(gemm_tma<1>, cudaFuncAttributeMaxDynamicSharedMemorySize, GEMM_SMEM);
    cudaFuncSetAttribute(attn_tma, cudaFuncAttributeMaxDynamicSharedMemorySize, ATTN_SMEM);

    tof16_all<<<6291456 / 256, 256>>>(x, w_qkv, w_out);
    gemm_tma<0><<<dim3(24, 32), 256, GEMM_SMEM>>>(mXf, mW1, nullptr, nullptr);
    attn_tma<<<dim3(Tn / 128, Bn * Hn), 256, ATTN_SMEM>>>(mQf, mQl, mKf, mVf);
    gemm_tma<1><<<dim3(8, 32), 256, GEMM_SMEM>>>(mAo, mW3, b_out, out);
}

// round 13
// speedup vs baseline: 13.7632x; 1.1783x over previous
#include <cuda.h>
#include <cuda_runtime.h>
#include <cuda_bf16.h>
#include <cuda_fp16.h>

namespace {
constexpr int Bn = 4, Tn = 2048, Cn = 1024, Hn = 16, Dn = 64;
constexpr unsigned GSTG = 49152;                                   // A 32K + B 16K
constexpr unsigned GEMM_SMEM = 4 * GSTG + 1024 + 64;               // 4-stage ring
constexpr unsigned KVSTG = 32768;                                  // K 16K + V 16K (128 keys)
constexpr unsigned ATTN_SMEM = 32768 + 3 * KVSTG + 1024 + 64;      // Q(2x16K) + 3 KV stages
}

// ---------------- scratch (device globals; no allocs allowed) ----------------
__device__ __align__(16) unsigned short g_xf[(size_t)Bn * Tn * Cn];     // fp16 x
__device__ __align__(16) unsigned short g_w1f[(size_t)3 * Cn * Cn];     // fp16 w_qkv
__device__ __align__(16) unsigned short g_w3f[(size_t)Cn * Cn];         // fp16 w_out
__device__ __align__(16) unsigned short g_aof[(size_t)Bn * Tn * Cn];    // fp16 attn out
__device__ __align__(16) unsigned short g_qf[(size_t)Bn * Hn * Tn * Dn]; // fp16 q high (pre-scaled by 0.125*log2e)
__device__ __align__(16) unsigned short g_ql[(size_t)Bn * Hn * Tn * Dn]; // fp16 q low
__device__ __align__(16) unsigned short g_kf[(size_t)Bn * Hn * Tn * Dn]; // fp16 k
__device__ __align__(16) unsigned short g_vf[(size_t)Bn * Hn * Tn * Dn]; // fp16 v

// ---------------- device helpers ----------------
__device__ __forceinline__ unsigned smem_u32(const void* p) {
    unsigned a;
    asm("{ .reg .u64 t; cvta.to.shared.u64 t, %1; cvt.u32.u64 %0, t; }" : "=r"(a) : "l"(p));
    return a;
}
__device__ __forceinline__ void mbar_init(unsigned addr, unsigned cnt) {
    asm volatile("mbarrier.init.shared.b64 [%0], %1;" :: "r"(addr), "r"(cnt) : "memory");
}
__device__ __forceinline__ void mbar_arrive(unsigned addr) {
    asm volatile("mbarrier.arrive.shared.b64 _, [%0];" :: "r"(addr) : "memory");
}
__device__ __forceinline__ void mbar_expect(unsigned addr, unsigned bytes) {
    asm volatile("mbarrier.arrive.expect_tx.shared.b64 _, [%0], %1;"
                 :: "r"(addr), "r"(bytes) : "memory");
}
__device__ __forceinline__ void mbar_wait(unsigned addr, unsigned parity) {
    asm volatile(
        "{\n\t.reg .pred P;\n\t"
        "WL_%=:\n\t"
        "mbarrier.try_wait.parity.acquire.cta.shared::cta.b64 P, [%0], %1, 0x989680;\n\t"
        "@P bra.uni WD_%=;\n\t"
        "bra.uni WL_%=;\n\t"
        "WD_%=:\n\t}"
        :: "r"(addr), "r"(parity) : "memory");
}
__device__ __forceinline__ void tma2d(unsigned smem, const CUtensorMap* m,
                                      int x, int y, unsigned mbar) {
    asm volatile(
        "cp.async.bulk.tensor.2d.shared::cta.global.tile.mbarrier::complete_tx::bytes "
        "[%0], [%1, {%2, %3}], [%4];"
        :: "r"(smem), "l"(m), "r"(x), "r"(y), "r"(mbar) : "memory");
}
__device__ __forceinline__ void ldsm4(unsigned* r, unsigned addr) {
    asm volatile("ldmatrix.sync.aligned.m8n8.x4.shared.b16 {%0,%1,%2,%3}, [%4];"
        : "=r"(r[0]), "=r"(r[1]), "=r"(r[2]), "=r"(r[3]) : "r"(addr));
}
__device__ __forceinline__ void ldsm4t(unsigned* r, unsigned addr) {
    asm volatile("ldmatrix.sync.aligned.m8n8.x4.trans.shared.b16 {%0,%1,%2,%3}, [%4];"
        : "=r"(r[0]), "=r"(r[1]), "=r"(r[2]), "=r"(r[3]) : "r"(addr));
}
__device__ __forceinline__ void mma16816h(float* c, const unsigned* a, const unsigned* b) {
    asm volatile("mma.sync.aligned.m16n8k16.row.col.f32.f16.f16.f32 "
        "{%0,%1,%2,%3}, {%4,%5,%6,%7}, {%8,%9}, {%0,%1,%2,%3};"
        : "+f"(c[0]), "+f"(c[1]), "+f"(c[2]), "+f"(c[3])
        : "r"(a[0]), "r"(a[1]), "r"(a[2]), "r"(a[3]), "r"(b[0]), "r"(b[1]));
}
__device__ __forceinline__ unsigned packh2(float lo, float hi) {
    unsigned u;
    asm("{ .reg .b16 l, h; cvt.rn.f16.f32 l, %1; cvt.rn.f16.f32 h, %2; "
        "mov.b32 %0, {l, h}; }" : "=r"(u) : "f"(lo), "f"(hi));
    return u;
}
// Single-instruction MUFU exp2 (scores are in log2 domain; q pre-scaled by log2e)
__device__ __forceinline__ float ex2(float x) {
    float r;
    asm("ex2.approx.ftz.f32 %0, %1;" : "=f"(r) : "f"(x));
    return r;
}

// ---------------- fp32 -> fp16 convert (x, w_qkv, w_out in ONE launch) ----------------
__global__ __launch_bounds__(256) void tof16_all(const float* __restrict__ x,
                                                 const float* __restrict__ w1,
                                                 const float* __restrict__ w3)
{
    const size_t p = (size_t)blockIdx.x * 256 + threadIdx.x;
    const float* src;
    unsigned short* dst;
    size_t off;
    if (p < 4194304u) { src = x; dst = g_xf; off = p; }
    else if (p < 5767168u) { src = w1; dst = g_w1f; off = p - 4194304u; }
    else { src = w3; dst = g_w3f; off = p - 5767168u; }
    const float2 v = *(const float2*)(src + off * 2);
    *(unsigned*)(dst + off * 2) = packh2(v.x, v.y);
}

// ---------------- TMA fp16 HMMA GEMM, 256x128 tile, 4-stage ring, no block sync ----
// MODE 0: A=xf, B=w1f -> q split fp16 (scaled 0.125*log2e) + k,v fp16. MODE 1: out+bias.
template <int MODE>
__global__ __launch_bounds__(256) void gemm_tma(
    const __grid_constant__ CUtensorMap tA, const __grid_constant__ CUtensorMap tB,
    const float* __restrict__ bias, float* __restrict__ out)
{
    extern __shared__ __align__(16) unsigned char smraw[];
    const unsigned sb = (smem_u32(smraw) + 1023u) & ~1023u;
    const unsigned ctrl = sb + 4u * GSTG;   // full[0..3] @ +0..24, empty[0..3] @ +32..56

    const int tid = threadIdx.x, lane = tid & 31, wid = tid >> 5;
    const int wm = wid & 3, wn = wid >> 2;                  // 4(m) x 2(n)
    const int m0 = blockIdx.y * 256, n0 = blockIdx.x * 128;

    if (tid == 0) {
#pragma unroll
        for (int i = 0; i < 4; i++) { mbar_init(ctrl + i * 8u, 1); mbar_init(ctrl + 32u + i * 8u, 8); }
    }
    __syncthreads();

    auto issue = [&](int s) {   // tid 0 only
        const unsigned base = sb + (unsigned)(s & 3) * GSTG;
        const unsigned mb = ctrl + (unsigned)(s & 3) * 8u;
        mbar_expect(mb, GSTG);
        const int kc = s * 64;
        tma2d(base,           &tA, kc, m0, mb);             // 256x64 fp16 = 32KB
        tma2d(base + 32768u,  &tB, kc, n0, mb);             // 128x64 fp16 = 16KB
    };
    if (tid == 0) { issue(0); issue(1); issue(2); issue(3); }

    const int arow = wm * 64 + (lane & 15);
    const unsigned acolb = (unsigned)((lane >> 4) * 16);
    const unsigned aswz = (unsigned)((arow & 7) << 4);
    const int brow = wn * 64 + (lane & 7) + ((lane >> 4) << 3);
    const unsigned bbase0 = (unsigned)(brow * 128);
    const unsigned bcolb = (unsigned)(((lane >> 3) & 1) * 16);
    const unsigned bswz = (unsigned)((brow & 7) << 4);

    float acc[4][8][4];
#pragma unroll
    for (int i = 0; i < 4; i++)
#pragma unroll
        for (int j = 0; j < 8; j++)
#pragma unroll
            for (int q = 0; q < 4; q++) acc[i][j][q] = 0.0f;

    for (int s = 0; s < 16; s++) {                          // K = 1024 / 64
        const unsigned slot = (unsigned)(s & 3);
        const unsigned stb = sb + slot * GSTG;
        mbar_wait(ctrl + slot * 8u, (unsigned)((s >> 2) & 1));
#pragma unroll
        for (int ks = 0; ks < 4; ks++) {
            unsigned af[4][4], bf[4][4];
            const unsigned ac = (acolb + ks * 32) ^ aswz;
#pragma unroll
            for (int mi = 0; mi < 4; mi++)
                ldsm4(af[mi], stb + (unsigned)((arow + mi * 16) * 128) + ac);
            const unsigned bc = (bcolb + ks * 32) ^ bswz;
#pragma unroll
            for (int nb = 0; nb < 4; nb++)
                ldsm4(bf[nb], stb + 32768u + bbase0 + nb * 2048u + bc);
#pragma unroll
            for (int mi = 0; mi < 4; mi++)
#pragma unroll
                for (int nb = 0; nb < 4; nb++) {
                    mma16816h(acc[mi][2 * nb],     af[mi], &bf[nb][0]);
                    mma16816h(acc[mi][2 * nb + 1], af[mi], &bf[nb][2]);
                }
        }
        if (lane == 0) mbar_arrive(ctrl + 32u + slot * 8u);
        if (tid == 0 && s + 4 < 16) {
            mbar_wait(ctrl + 32u + slot * 8u, (unsigned)((s >> 2) & 1));
            issue(s + 4);
        }
    }

    const int g = lane >> 2, tig = lane & 3;
    if (MODE == 0) {
        const int nblock = n0 + wn * 64;                    // one (sec, head)
        const int sec = nblock >> 10;
        const int h = (nblock & 1023) >> 6;
        if (sec == 0) {                   // q -> fp16 h/l, scaled by 0.125*log2e
            const float SC = 0.125f * 1.4426950408889634f;
#pragma unroll
            for (int mi = 0; mi < 4; mi++) {
                const int m1 = m0 + wm * 64 + mi * 16 + g;
                const int b = m1 >> 11, t = m1 & 2047;
                const size_t rb = (size_t)((b * Hn + h) * Tn + t) * Dn;
#pragma unroll
                for (int ni = 0; ni < 8; ni++) {
                    const int d = ni * 8 + 2 * tig;
#pragma unroll
                    for (int half = 0; half < 2; half++) {
                        const float v0 = acc[mi][ni][2 * half] * SC;
                        const float v1 = acc[mi][ni][2 * half + 1] * SC;
                        const float h0 = __half2float(__float2half(v0));
                        const float h1 = __half2float(__float2half(v1));
                        const size_t o = rb + (size_t)half * 8 * Dn + d;
                        *(unsigned*)&g_qf[o] = packh2(h0, h1);
                        *(unsigned*)&g_ql[o] = packh2(v0 - h0, v1 - h1);
                    }
                }
            }
        } else {                                            // k or v -> fp16 single
            unsigned short* dst = (sec == 1) ? g_kf : g_vf;
#pragma unroll
            for (int mi = 0; mi < 4; mi++) {
                const int m1 = m0 + wm * 64 + mi * 16 + g;
                const int b = m1 >> 11, t = m1 & 2047;
                const size_t rb = (size_t)((b * Hn + h) * Tn + t) * Dn;
#pragma unroll
                for (int ni = 0; ni < 8; ni++) {
                    const int d = ni * 8 + 2 * tig;
#pragma unroll
                    for (int half = 0; half < 2; half++) {
                        const size_t o = rb + (size_t)half * 8 * Dn + d;
                        *(unsigned*)&dst[o] =
                            packh2(acc[mi][ni][2 * half], acc[mi][ni][2 * half + 1]);
                    }
                }
            }
        }
    } else {
#pragma unroll
        for (int mi = 0; mi < 4; mi++) {
            const int m1 = m0 + wm * 64 + mi * 16 + g;
#pragma unroll
            for (int ni = 0; ni < 8; ni++) {
                const int n = n0 + wn * 64 + ni * 8 + 2 * tig;
                const float2 bb = *(const float2*)(bias + n);
                float2 lo = {acc[mi][ni][0] + bb.x, acc[mi][ni][1] + bb.y};
                float2 hi = {acc[mi][ni][2] + bb.x, acc[mi][ni][3] + bb.y};
                *(float2*)(out + (size_t)m1 * Cn + n) = lo;
                *(float2*)(out + (size_t)(m1 + 8) * Cn + n) = hi;
            }
        }
    }
}

// ---------------- TMA flash attention: log2-domain softmax via MUFU EX2 ----------------
// Grid (16, B*H), 256 thr / 8 warps, 128-row Q tile, 128-row KV tiles, 3-stage ring.
__global__ __launch_bounds__(256) void attn_tma(
    const __grid_constant__ CUtensorMap tQf, const __grid_constant__ CUtensorMap tQl,
    const __grid_constant__ CUtensorMap tKf, const __grid_constant__ CUtensorMap tVf)
{
    extern __shared__ __align__(16) unsigned char smraw[];
    const unsigned sb = (smem_u32(smraw) + 1023u) & ~1023u;
    const unsigned kvb = sb + 32768u;                       // 3 KV stages x 32768
    const unsigned ctrl = kvb + 3u * KVSTG;  // qbar, full[0..2] @+8.., empty[0..2] @+32..

    const int tid = threadIdx.x, lane = tid & 31, wid = tid >> 5;
    const int qt = (int)gridDim.x - 1 - (int)blockIdx.x;    // heavy tiles first
    const int bh = blockIdx.y;
    const int g = lane >> 2, tig = lane & 3;
    const int grow0 = bh * Tn;
    const int nkt = qt + 1;                                 // 128-key tiles

    if (tid == 0) {
        mbar_init(ctrl, 1);
        mbar_init(ctrl + 8, 1);  mbar_init(ctrl + 16, 1); mbar_init(ctrl + 24, 1);
        mbar_init(ctrl + 32, 8); mbar_init(ctrl + 40, 8); mbar_init(ctrl + 48, 8);
    }
    __syncthreads();

    auto issue_kv = [&](int s) {   // tid 0 only
        const unsigned base = kvb + (unsigned)(s % 3) * KVSTG;
        const unsigned mb = ctrl + 8u + (unsigned)(s % 3) * 8u;
        mbar_expect(mb, KVSTG);
        const int y = grow0 + s * 128;
        tma2d(base,           &tKf, 0, y, mb);              // 128x64 fp16 = 16KB
        tma2d(base + 16384u,  &tVf, 0, y, mb);
    };
    if (tid == 0) {
        mbar_expect(ctrl, 32768u);
        tma2d(sb,           &tQf, 0, grow0 + qt * 128, ctrl);
        tma2d(sb + 16384u,  &tQl, 0, grow0 + qt * 128, ctrl);
        issue_kv(0);
        if (nkt > 1) issue_kv(1);
        if (nkt > 2) issue_kv(2);
    }

    // Q fragments -> registers (warp w owns rows w*16..+15)
    mbar_wait(ctrl, 0u);
    const int qrow = wid * 16 + (lane & 15);
    const unsigned qswz = (unsigned)((qrow & 7) << 4);
    unsigned aqf[4][4], aql[4][4];
#pragma unroll
    for (int ks = 0; ks < 4; ks++) {
        const unsigned ac = (unsigned)((lane >> 4) * 16 + ks * 32) ^ qswz;
        ldsm4(aqf[ks], sb + (unsigned)(qrow * 128) + ac);
        ldsm4(aql[ks], sb + 16384u + (unsigned)(qrow * 128) + ac);
    }

    const int brow = (lane & 7) + ((lane >> 4) << 3);
    const unsigned bcolb = (unsigned)(((lane >> 3) & 1) * 16);
    const unsigned bswz = (unsigned)((brow & 7) << 4);
    const int vrow = (((lane >> 3) & 1) << 3) + (lane & 7);
    const unsigned vd2 = (unsigned)((lane >> 4) * 16);
    const unsigned vswz = (unsigned)((vrow & 7) << 4);

    float O[8][4];
#pragma unroll
    for (int i = 0; i < 8; i++)
#pragma unroll
        for (int q = 0; q < 4; q++) O[i][q] = 0.0f;
    float m0r = -1e30f, m1r = -1e30f, l0 = 0.0f, l1 = 0.0f;
    const int qrow_g = qt * 128 + wid * 16 + g;

    for (int kt = 0; kt < nkt; kt++) {
        const unsigned slot = (unsigned)(kt % 3);
        const unsigned stb = kvb + slot * KVSTG;
        mbar_wait(ctrl + 8u + slot * 8u, (unsigned)((kt / 3) & 1));

        // ---- S[128q x 128k] = Q K^T (2-term fp16, log2-domain) ----
        float sc[16][4];
#pragma unroll
        for (int i = 0; i < 16; i++)
#pragma unroll
            for (int q = 0; q < 4; q++) sc[i][q] = 0.0f;
#pragma unroll
        for (int ks = 0; ks < 4; ks++) {
            const unsigned bc = (bcolb + ks * 32) ^ bswz;
#pragma unroll
            for (int nb = 0; nb < 8; nb++) {
                unsigned bkf[4];
                ldsm4(bkf, stb + (unsigned)((nb * 16 + brow) * 128) + bc);
                mma16816h(sc[2 * nb],     aqf[ks], &bkf[0]);
                mma16816h(sc[2 * nb + 1], aqf[ks], &bkf[2]);
                mma16816h(sc[2 * nb],     aql[ks], &bkf[0]);
                mma16816h(sc[2 * nb + 1], aql[ks], &bkf[2]);
            }
        }

        if (kt == qt) {                          // diagonal tile -> causal mask
            const int kb = kt * 128 + 2 * tig;
#pragma unroll
            for (int ni = 0; ni < 16; ni++) {
                const int key = kb + ni * 8;
                if (key > qrow_g)         sc[ni][0] = -1e30f;
                if (key + 1 > qrow_g)     sc[ni][1] = -1e30f;
                if (key > qrow_g + 8)     sc[ni][2] = -1e30f;
                if (key + 1 > qrow_g + 8) sc[ni][3] = -1e30f;
            }
        }

        // ---- online softmax (log2 domain, MUFU EX2) ----
        float mx0 = -1e30f, mx1 = -1e30f;
#pragma unroll
        for (int ni = 0; ni < 16; ni++) {
            mx0 = fmaxf(mx0, fmaxf(sc[ni][0], sc[ni][1]));
            mx1 = fmaxf(mx1, fmaxf(sc[ni][2], sc[ni][3]));
        }
        mx0 = fmaxf(mx0, __shfl_xor_sync(0xFFFFFFFF, mx0, 1));
        mx0 = fmaxf(mx0, __shfl_xor_sync(0xFFFFFFFF, mx0, 2));
        mx1 = fmaxf(mx1, __shfl_xor_sync(0xFFFFFFFF, mx1, 1));
        mx1 = fmaxf(mx1, __shfl_xor_sync(0xFFFFFFFF, mx1, 2));
        const float nm0 = fmaxf(m0r, mx0), nm1 = fmaxf(m1r, mx1);
        const float cr0 = ex2(m0r - nm0), cr1 = ex2(m1r - nm1);
        m0r = nm0; m1r = nm1;
        l0 *= cr0; l1 *= cr1;
#pragma unroll
        for (int ni = 0; ni < 8; ni++) {
            O[ni][0] *= cr0; O[ni][1] *= cr0;
            O[ni][2] *= cr1; O[ni][3] *= cr1;
        }
        float ps0 = 0.0f, ps1 = 0.0f;
#pragma unroll
        for (int ni = 0; ni < 16; ni++) {
            sc[ni][0] = ex2(sc[ni][0] - nm0);
            sc[ni][1] = ex2(sc[ni][1] - nm0);
            sc[ni][2] = ex2(sc[ni][2] - nm1);
            sc[ni][3] = ex2(sc[ni][3] - nm1);
            ps0 += sc[ni][0] + sc[ni][1];
            ps1 += sc[ni][2] + sc[ni][3];
        }
        l0 += ps0; l1 += ps1;

        // ---- O += P V (fp16), P packed on the fly ----
#pragma unroll
        for (int j = 0; j < 8; j++) {
            unsigned apf[4];
            apf[0] = packh2(sc[2 * j][0], sc[2 * j][1]);
            apf[1] = packh2(sc[2 * j][2], sc[2 * j][3]);
            apf[2] = packh2(sc[2 * j + 1][0], sc[2 * j + 1][1]);
            apf[3] = packh2(sc[2 * j + 1][2], sc[2 * j + 1][3]);
#pragma unroll
            for (int db = 0; db < 4; db++) {
                unsigned vf[4];
                const unsigned off = (unsigned)((j * 16 + vrow) * 128) + ((db * 32u + vd2) ^ vswz);
                ldsm4t(vf, stb + 16384u + off);
                mma16816h(O[2 * db],     apf, &vf[0]);
                mma16816h(O[2 * db + 1], apf, &vf[2]);
            }
        }

        // ---- release slot ----
        if (lane == 0) mbar_arrive(ctrl + 32u + slot * 8u);
        if (tid == 0 && kt + 3 < nkt) {
            mbar_wait(ctrl + 32u + slot * 8u, (unsigned)((kt / 3) & 1));
            issue_kv(kt + 3);
        }
    }

    // ---- epilogue: ao -> fp16 single ----
    l0 += __shfl_xor_sync(0xFFFFFFFF, l0, 1);
    l0 += __shfl_xor_sync(0xFFFFFFFF, l0, 2);
    l1 += __shfl_xor_sync(0xFFFFFFFF, l1, 1);
    l1 += __shfl_xor_sync(0xFFFFFFFF, l1, 2);
    const float inv0 = 1.0f / l0, inv1 = 1.0f / l1;

    const int b = bh >> 4, h = bh & 15;
    const size_t r0 = (size_t)(b * Tn + qrow_g) * Cn;
    const size_t r1 = (size_t)(b * Tn + qrow_g + 8) * Cn;
#pragma unroll
    for (int ni = 0; ni < 8; ni++) {
        const int k = h * Dn + ni * 8 + 2 * tig;
        *(unsigned*)&g_aof[r0 + k] = packh2(O[ni][0] * inv0, O[ni][1] * inv0);
        *(unsigned*)&g_aof[r1 + k] = packh2(O[ni][2] * inv1, O[ni][3] * inv1);
    }
}

// ---------------- host ----------------
typedef CUresult (CUDAAPI* EncodeFn)(
    CUtensorMap*, CUtensorMapDataType, cuuint32_t, void*,
    const cuuint64_t*, const cuuint64_t*, const cuuint32_t*, const cuuint32_t*,
    CUtensorMapInterleave, CUtensorMapSwizzle, CUtensorMapL2promotion,
    CUtensorMapFloatOOBfill);

static void mk_map(EncodeFn enc, CUtensorMap* m, void* base, CUtensorMapDataType dt,
                   unsigned long long rows, unsigned long long cols,
                   unsigned boxc, unsigned boxr)
{
    cuuint64_t dims[2] = {cols, rows};
    cuuint64_t strides[1] = {cols * 2};
    cuuint32_t box[2] = {boxc, boxr};
    cuuint32_t es[2] = {1, 1};
    enc(m, dt, 2, base, dims, strides, box, es,
        CU_TENSOR_MAP_INTERLEAVE_NONE, CU_TENSOR_MAP_SWIZZLE_128B,
        CU_TENSOR_MAP_L2_PROMOTION_L2_128B, CU_TENSOR_MAP_FLOAT_OOB_FILL_NONE);
}

extern "C" void kernel_launch(void* const* d_in, const int* in_sizes, int n_in,
                              void* d_out, int out_size)
{
    const float* x     = (const float*)d_in[0];
    const float* w_qkv = (const float*)d_in[1];
    const float* w_out = (const float*)d_in[2];
    const float* b_out = (const float*)d_in[3];
    float* out = (float*)d_out;

    void *pXf, *pW1, *pW3, *pAo, *pQf, *pQl, *pKf, *pVf;
    cudaGetSymbolAddress(&pXf, g_xf);
    cudaGetSymbolAddress(&pW1, g_w1f);
    cudaGetSymbolAddress(&pW3, g_w3f);
    cudaGetSymbolAddress(&pAo, g_aof);
    cudaGetSymbolAddress(&pQf, g_qf);   cudaGetSymbolAddress(&pQl, g_ql);
    cudaGetSymbolAddress(&pKf, g_kf);   cudaGetSymbolAddress(&pVf, g_vf);

    EncodeFn enc = nullptr;
    cudaDriverEntryPointQueryResult qr;
    cudaGetDriverEntryPointByVersion("cuTensorMapEncodeTiled", (void**)&enc,
                                     12000, cudaEnableDefault, &qr);

    const auto F16 = CU_TENSOR_MAP_DATA_TYPE_FLOAT16;
    const unsigned long long MR = (unsigned long long)Bn * Tn;        // 8192
    const unsigned long long KVR = (unsigned long long)Bn * Hn * Tn;  // 131072
    CUtensorMap mXf, mW1, mW3, mAo, mQf, mQl, mKf, mVf;
    mk_map(enc, &mXf, pXf, F16, MR, 1024, 64, 256);
    mk_map(enc, &mW1, pW1, F16, 3072, 1024, 64, 128);
    mk_map(enc, &mW3, pW3, F16, 1024, 1024, 64, 128);
    mk_map(enc, &mAo, pAo, F16, MR, 1024, 64, 256);
    mk_map(enc, &mQf, pQf, F16, KVR, 64, 64, 128);
    mk_map(enc, &mQl, pQl, F16, KVR, 64, 64, 128);
    mk_map(enc, &mKf, pKf, F16, KVR, 64, 64, 128);
    mk_map(enc, &mVf, pVf, F16, KVR, 64, 64, 128);

    cudaFuncSetAttribute(gemm_tma<0>, cudaFuncAttributeMaxDynamicSharedMemorySize, GEMM_SMEM);
    cudaFuncSetAttribute(gemm_tma<1>, cudaFuncAttributeMaxDynamicSharedMemorySize, GEMM_SMEM);
    cudaFuncSetAttribute(attn_tma, cudaFuncAttributeMaxDynamicSharedMemorySize, ATTN_SMEM);

    tof16_all<<<6291456 / 256, 256>>>(x, w_qkv, w_out);
    gemm_tma<0><<<dim3(24, 32), 256, GEMM_SMEM>>>(mXf, mW1, nullptr, nullptr);
    attn_tma<<<dim3(Tn / 128, Bn * Hn), 256, ATTN_SMEM>>>(mQf, mQl, mKf, mVf);
    gemm_tma<1><<<dim3(8, 32), 256, GEMM_SMEM>>>(mAo, mW3, b_out, out);
}

// round 14
// speedup vs baseline: 15.5152x; 1.1273x over previous
#include <cuda.h>
#include <cuda_runtime.h>
#include <cuda_bf16.h>
#include <cuda_fp16.h>

namespace {
constexpr int Bn = 4, Tn = 2048, Cn = 1024, Hn = 16, Dn = 64;
constexpr unsigned GSTG = 49152;                                   // A 32K + B 16K
constexpr unsigned GEMM_SMEM = 4 * GSTG + 1024 + 64;               // 4-stage ring
constexpr unsigned KVSTG = 32768;                                  // K 16K + V 16K (128 keys)
constexpr unsigned ATTN_SMEM = 16384 + 3 * KVSTG + 1024 + 64;      // Q(16K) + 3 KV stages
}

// ---------------- scratch (device globals; no allocs allowed) ----------------
__device__ __align__(16) unsigned short g_xf[(size_t)Bn * Tn * Cn];     // fp16 x
__device__ __align__(16) unsigned short g_w1f[(size_t)3 * Cn * Cn];     // fp16 w_qkv
__device__ __align__(16) unsigned short g_w3f[(size_t)Cn * Cn];         // fp16 w_out
__device__ __align__(16) unsigned short g_aof[(size_t)Bn * Tn * Cn];    // fp16 attn out
__device__ __align__(16) unsigned short g_qf[(size_t)Bn * Hn * Tn * Dn]; // fp16 q (pre-scaled 0.125*log2e)
__device__ __align__(16) unsigned short g_kf[(size_t)Bn * Hn * Tn * Dn]; // fp16 k
__device__ __align__(16) unsigned short g_vf[(size_t)Bn * Hn * Tn * Dn]; // fp16 v

// ---------------- device helpers ----------------
__device__ __forceinline__ unsigned smem_u32(const void* p) {
    unsigned a;
    asm("{ .reg .u64 t; cvta.to.shared.u64 t, %1; cvt.u32.u64 %0, t; }" : "=r"(a) : "l"(p));
    return a;
}
__device__ __forceinline__ void mbar_init(unsigned addr, unsigned cnt) {
    asm volatile("mbarrier.init.shared.b64 [%0], %1;" :: "r"(addr), "r"(cnt) : "memory");
}
__device__ __forceinline__ void mbar_arrive(unsigned addr) {
    asm volatile("mbarrier.arrive.shared.b64 _, [%0];" :: "r"(addr) : "memory");
}
__device__ __forceinline__ void mbar_expect(unsigned addr, unsigned bytes) {
    asm volatile("mbarrier.arrive.expect_tx.shared.b64 _, [%0], %1;"
                 :: "r"(addr), "r"(bytes) : "memory");
}
__device__ __forceinline__ void mbar_wait(unsigned addr, unsigned parity) {
    asm volatile(
        "{\n\t.reg .pred P;\n\t"
        "WL_%=:\n\t"
        "mbarrier.try_wait.parity.acquire.cta.shared::cta.b64 P, [%0], %1, 0x989680;\n\t"
        "@P bra.uni WD_%=;\n\t"
        "bra.uni WL_%=;\n\t"
        "WD_%=:\n\t}"
        :: "r"(addr), "r"(parity) : "memory");
}
__device__ __forceinline__ void tma2d(unsigned smem, const CUtensorMap* m,
                                      int x, int y, unsigned mbar) {
    asm volatile(
        "cp.async.bulk.tensor.2d.shared::cta.global.tile.mbarrier::complete_tx::bytes "
        "[%0], [%1, {%2, %3}], [%4];"
        :: "r"(smem), "l"(m), "r"(x), "r"(y), "r"(mbar) : "memory");
}
__device__ __forceinline__ void ldsm4(unsigned* r, unsigned addr) {
    asm volatile("ldmatrix.sync.aligned.m8n8.x4.shared.b16 {%0,%1,%2,%3}, [%4];"
        : "=r"(r[0]), "=r"(r[1]), "=r"(r[2]), "=r"(r[3]) : "r"(addr));
}
__device__ __forceinline__ void ldsm4t(unsigned* r, unsigned addr) {
    asm volatile("ldmatrix.sync.aligned.m8n8.x4.trans.shared.b16 {%0,%1,%2,%3}, [%4];"
        : "=r"(r[0]), "=r"(r[1]), "=r"(r[2]), "=r"(r[3]) : "r"(addr));
}
__device__ __forceinline__ void mma16816h(float* c, const unsigned* a, const unsigned* b) {
    asm volatile("mma.sync.aligned.m16n8k16.row.col.f32.f16.f16.f32 "
        "{%0,%1,%2,%3}, {%4,%5,%6,%7}, {%8,%9}, {%0,%1,%2,%3};"
        : "+f"(c[0]), "+f"(c[1]), "+f"(c[2]), "+f"(c[3])
        : "r"(a[0]), "r"(a[1]), "r"(a[2]), "r"(a[3]), "r"(b[0]), "r"(b[1]));
}
__device__ __forceinline__ unsigned packh2(float lo, float hi) {
    unsigned u;
    asm("{ .reg .b16 l, h; cvt.rn.f16.f32 l, %1; cvt.rn.f16.f32 h, %2; "
        "mov.b32 %0, {l, h}; }" : "=r"(u) : "f"(lo), "f"(hi));
    return u;
}
__device__ __forceinline__ float ex2(float x) {
    float r;
    asm("ex2.approx.ftz.f32 %0, %1;" : "=f"(r) : "f"(x));
    return r;
}

// ---------------- fp32 -> fp16 convert (x, w_qkv, w_out in ONE launch) ----------------
__global__ __launch_bounds__(256) void tof16_all(const float* __restrict__ x,
                                                 const float* __restrict__ w1,
                                                 const float* __restrict__ w3)
{
    const size_t p = (size_t)blockIdx.x * 256 + threadIdx.x;
    const float* src;
    unsigned short* dst;
    size_t off;
    if (p < 4194304u) { src = x; dst = g_xf; off = p; }
    else if (p < 5767168u) { src = w1; dst = g_w1f; off = p - 4194304u; }
    else { src = w3; dst = g_w3f; off = p - 5767168u; }
    const float2 v = *(const float2*)(src + off * 2);
    *(unsigned*)(dst + off * 2) = packh2(v.x, v.y);
}

// ---------------- TMA fp16 HMMA GEMM, 256x128 tile, 4-stage ring, no block sync ----
// MODE 0: A=xf, B=w1f -> q fp16 (scaled 0.125*log2e), k, v fp16. MODE 1: out+bias.
template <int MODE>
__global__ __launch_bounds__(256) void gemm_tma(
    const __grid_constant__ CUtensorMap tA, const __grid_constant__ CUtensorMap tB,
    const float* __restrict__ bias, float* __restrict__ out)
{
    extern __shared__ __align__(16) unsigned char smraw[];
    const unsigned sb = (smem_u32(smraw) + 1023u) & ~1023u;
    const unsigned ctrl = sb + 4u * GSTG;   // full[0..3] @ +0..24, empty[0..3] @ +32..56

    const int tid = threadIdx.x, lane = tid & 31, wid = tid >> 5;
    const int wm = wid & 3, wn = wid >> 2;                  // 4(m) x 2(n)
    const int m0 = blockIdx.y * 256, n0 = blockIdx.x * 128;

    if (tid == 0) {
#pragma unroll
        for (int i = 0; i < 4; i++) { mbar_init(ctrl + i * 8u, 1); mbar_init(ctrl + 32u + i * 8u, 8); }
    }
    __syncthreads();

    auto issue = [&](int s) {   // tid 0 only
        const unsigned base = sb + (unsigned)(s & 3) * GSTG;
        const unsigned mb = ctrl + (unsigned)(s & 3) * 8u;
        mbar_expect(mb, GSTG);
        const int kc = s * 64;
        tma2d(base,           &tA, kc, m0, mb);             // 256x64 fp16 = 32KB
        tma2d(base + 32768u,  &tB, kc, n0, mb);             // 128x64 fp16 = 16KB
    };
    if (tid == 0) { issue(0); issue(1); issue(2); issue(3); }

    const int arow = wm * 64 + (lane & 15);
    const unsigned acolb = (unsigned)((lane >> 4) * 16);
    const unsigned aswz = (unsigned)((arow & 7) << 4);
    const int brow = wn * 64 + (lane & 7) + ((lane >> 4) << 3);
    const unsigned bbase0 = (unsigned)(brow * 128);
    const unsigned bcolb = (unsigned)(((lane >> 3) & 1) * 16);
    const unsigned bswz = (unsigned)((brow & 7) << 4);

    float acc[4][8][4];
#pragma unroll
    for (int i = 0; i < 4; i++)
#pragma unroll
        for (int j = 0; j < 8; j++)
#pragma unroll
            for (int q = 0; q < 4; q++) acc[i][j][q] = 0.0f;

    for (int s = 0; s < 16; s++) {                          // K = 1024 / 64
        const unsigned slot = (unsigned)(s & 3);
        const unsigned stb = sb + slot * GSTG;
        mbar_wait(ctrl + slot * 8u, (unsigned)((s >> 2) & 1));
#pragma unroll
        for (int ks = 0; ks < 4; ks++) {
            unsigned af[4][4], bf[4][4];
            const unsigned ac = (acolb + ks * 32) ^ aswz;
#pragma unroll
            for (int mi = 0; mi < 4; mi++)
                ldsm4(af[mi], stb + (unsigned)((arow + mi * 16) * 128) + ac);
            const unsigned bc = (bcolb + ks * 32) ^ bswz;
#pragma unroll
            for (int nb = 0; nb < 4; nb++)
                ldsm4(bf[nb], stb + 32768u + bbase0 + nb * 2048u + bc);
#pragma unroll
            for (int mi = 0; mi < 4; mi++)
#pragma unroll
                for (int nb = 0; nb < 4; nb++) {
                    mma16816h(acc[mi][2 * nb],     af[mi], &bf[nb][0]);
                    mma16816h(acc[mi][2 * nb + 1], af[mi], &bf[nb][2]);
                }
        }
        if (lane == 0) mbar_arrive(ctrl + 32u + slot * 8u);
        if (tid == 0 && s + 4 < 16) {
            mbar_wait(ctrl + 32u + slot * 8u, (unsigned)((s >> 2) & 1));
            issue(s + 4);
        }
    }

    const int g = lane >> 2, tig = lane & 3;
    if (MODE == 0) {
        const int nblock = n0 + wn * 64;                    // one (sec, head)
        const int sec = nblock >> 10;
        const int h = (nblock & 1023) >> 6;
        const float SC = (sec == 0) ? 0.125f * 1.4426950408889634f : 1.0f;
        unsigned short* dst = (sec == 0) ? g_qf : (sec == 1) ? g_kf : g_vf;
#pragma unroll
        for (int mi = 0; mi < 4; mi++) {
            const int m1 = m0 + wm * 64 + mi * 16 + g;
            const int b = m1 >> 11, t = m1 & 2047;
            const size_t rb = (size_t)((b * Hn + h) * Tn + t) * Dn;
#pragma unroll
            for (int ni = 0; ni < 8; ni++) {
                const int d = ni * 8 + 2 * tig;
#pragma unroll
                for (int half = 0; half < 2; half++) {
                    const size_t o = rb + (size_t)half * 8 * Dn + d;
                    *(unsigned*)&dst[o] =
                        packh2(acc[mi][ni][2 * half] * SC, acc[mi][ni][2 * half + 1] * SC);
                }
            }
        }
    } else {
#pragma unroll
        for (int mi = 0; mi < 4; mi++) {
            const int m1 = m0 + wm * 64 + mi * 16 + g;
#pragma unroll
            for (int ni = 0; ni < 8; ni++) {
                const int n = n0 + wn * 64 + ni * 8 + 2 * tig;
                const float2 bb = *(const float2*)(bias + n);
                float2 lo = {acc[mi][ni][0] + bb.x, acc[mi][ni][1] + bb.y};
                float2 hi = {acc[mi][ni][2] + bb.x, acc[mi][ni][3] + bb.y};
                *(float2*)(out + (size_t)m1 * Cn + n) = lo;
                *(float2*)(out + (size_t)(m1 + 8) * Cn + n) = hi;
            }
        }
    }
}

// ---------------- TMA flash attention: 1-term fp16 QK, log2 softmax, fp16 PV ----------
// Grid (16, B*H), 256 thr / 8 warps, 128-row Q tile, 128-row KV tiles, 3-stage ring.
__global__ __launch_bounds__(256) void attn_tma(
    const __grid_constant__ CUtensorMap tQf,
    const __grid_constant__ CUtensorMap tKf, const __grid_constant__ CUtensorMap tVf)
{
    extern __shared__ __align__(16) unsigned char smraw[];
    const unsigned sb = (smem_u32(smraw) + 1023u) & ~1023u;
    const unsigned kvb = sb + 16384u;                       // 3 KV stages x 32768
    const unsigned ctrl = kvb + 3u * KVSTG;  // qbar, full[0..2] @+8.., empty[0..2] @+32..

    const int tid = threadIdx.x, lane = tid & 31, wid = tid >> 5;
    const int qt = (int)gridDim.x - 1 - (int)blockIdx.x;    // heavy tiles first
    const int bh = blockIdx.y;
    const int g = lane >> 2, tig = lane & 3;
    const int grow0 = bh * Tn;
    const int nkt = qt + 1;                                 // 128-key tiles

    if (tid == 0) {
        mbar_init(ctrl, 1);
        mbar_init(ctrl + 8, 1);  mbar_init(ctrl + 16, 1); mbar_init(ctrl + 24, 1);
        mbar_init(ctrl + 32, 8); mbar_init(ctrl + 40, 8); mbar_init(ctrl + 48, 8);
    }
    __syncthreads();

    auto issue_kv = [&](int s) {   // tid 0 only
        const unsigned base = kvb + (unsigned)(s % 3) * KVSTG;
        const unsigned mb = ctrl + 8u + (unsigned)(s % 3) * 8u;
        mbar_expect(mb, KVSTG);
        const int y = grow0 + s * 128;
        tma2d(base,           &tKf, 0, y, mb);              // 128x64 fp16 = 16KB
        tma2d(base + 16384u,  &tVf, 0, y, mb);
    };
    if (tid == 0) {
        mbar_expect(ctrl, 16384u);
        tma2d(sb, &tQf, 0, grow0 + qt * 128, ctrl);
        issue_kv(0);
        if (nkt > 1) issue_kv(1);
        if (nkt > 2) issue_kv(2);
    }

    // Q fragments -> registers (warp w owns rows w*16..+15)
    mbar_wait(ctrl, 0u);
    const int qrow = wid * 16 + (lane & 15);
    const unsigned qswz = (unsigned)((qrow & 7) << 4);
    unsigned aqf[4][4];
#pragma unroll
    for (int ks = 0; ks < 4; ks++) {
        const unsigned ac = (unsigned)((lane >> 4) * 16 + ks * 32) ^ qswz;
        ldsm4(aqf[ks], sb + (unsigned)(qrow * 128) + ac);
    }

    const int brow = (lane & 7) + ((lane >> 4) << 3);
    const unsigned bcolb = (unsigned)(((lane >> 3) & 1) * 16);
    const unsigned bswz = (unsigned)((brow & 7) << 4);
    const int vrow = (((lane >> 3) & 1) << 3) + (lane & 7);
    const unsigned vd2 = (unsigned)((lane >> 4) * 16);
    const unsigned vswz = (unsigned)((vrow & 7) << 4);

    float O[8][4];
#pragma unroll
    for (int i = 0; i < 8; i++)
#pragma unroll
        for (int q = 0; q < 4; q++) O[i][q] = 0.0f;
    float m0r = -1e30f, m1r = -1e30f, l0 = 0.0f, l1 = 0.0f;
    const int qrow_g = qt * 128 + wid * 16 + g;

    for (int kt = 0; kt < nkt; kt++) {
        const unsigned slot = (unsigned)(kt % 3);
        const unsigned stb = kvb + slot * KVSTG;
        mbar_wait(ctrl + 8u + slot * 8u, (unsigned)((kt / 3) & 1));

        // ---- S[128q x 128k] = Q K^T (1-term fp16, log2-domain) ----
        float sc[16][4];
#pragma unroll
        for (int i = 0; i < 16; i++)
#pragma unroll
            for (int q = 0; q < 4; q++) sc[i][q] = 0.0f;
#pragma unroll
        for (int ks = 0; ks < 4; ks++) {
            const unsigned bc = (bcolb + ks * 32) ^ bswz;
#pragma unroll
            for (int nb = 0; nb < 8; nb++) {
                unsigned bkf[4];
                ldsm4(bkf, stb + (unsigned)((nb * 16 + brow) * 128) + bc);
                mma16816h(sc[2 * nb],     aqf[ks], &bkf[0]);
                mma16816h(sc[2 * nb + 1], aqf[ks], &bkf[2]);
            }
        }

        if (kt == qt) {                          // diagonal tile -> causal mask
            const int kb = kt * 128 + 2 * tig;
#pragma unroll
            for (int ni = 0; ni < 16; ni++) {
                const int key = kb + ni * 8;
                if (key > qrow_g)         sc[ni][0] = -1e30f;
                if (key + 1 > qrow_g)     sc[ni][1] = -1e30f;
                if (key > qrow_g + 8)     sc[ni][2] = -1e30f;
                if (key + 1 > qrow_g + 8) sc[ni][3] = -1e30f;
            }
        }

        // ---- online softmax (log2 domain, MUFU EX2) ----
        float mx0 = -1e30f, mx1 = -1e30f;
#pragma unroll
        for (int ni = 0; ni < 16; ni++) {
            mx0 = fmaxf(mx0, fmaxf(sc[ni][0], sc[ni][1]));
            mx1 = fmaxf(mx1, fmaxf(sc[ni][2], sc[ni][3]));
        }
        mx0 = fmaxf(mx0, __shfl_xor_sync(0xFFFFFFFF, mx0, 1));
        mx0 = fmaxf(mx0, __shfl_xor_sync(0xFFFFFFFF, mx0, 2));
        mx1 = fmaxf(mx1, __shfl_xor_sync(0xFFFFFFFF, mx1, 1));
        mx1 = fmaxf(mx1, __shfl_xor_sync(0xFFFFFFFF, mx1, 2));
        const float nm0 = fmaxf(m0r, mx0), nm1 = fmaxf(m1r, mx1);
        const float cr0 = ex2(m0r - nm0), cr1 = ex2(m1r - nm1);
        m0r = nm0; m1r = nm1;
        l0 *= cr0; l1 *= cr1;
#pragma unroll
        for (int ni = 0; ni < 8; ni++) {
            O[ni][0] *= cr0; O[ni][1] *= cr0;
            O[ni][2] *= cr1; O[ni][3] *= cr1;
        }
        float ps0 = 0.0f, ps1 = 0.0f;
#pragma unroll
        for (int ni = 0; ni < 16; ni++) {
            sc[ni][0] = ex2(sc[ni][0] - nm0);
            sc[ni][1] = ex2(sc[ni][1] - nm0);
            sc[ni][2] = ex2(sc[ni][2] - nm1);
            sc[ni][3] = ex2(sc[ni][3] - nm1);
            ps0 += sc[ni][0] + sc[ni][1];
            ps1 += sc[ni][2] + sc[ni][3];
        }
        l0 += ps0; l1 += ps1;

        // ---- O += P V (fp16), P packed on the fly ----
#pragma unroll
        for (int j = 0; j < 8; j++) {
            unsigned apf[4];
            apf[0] = packh2(sc[2 * j][0], sc[2 * j][1]);
            apf[1] = packh2(sc[2 * j][2], sc[2 * j][3]);
            apf[2] = packh2(sc[2 * j + 1][0], sc[2 * j + 1][1]);
            apf[3] = packh2(sc[2 * j + 1][2], sc[2 * j + 1][3]);
#pragma unroll
            for (int db = 0; db < 4; db++) {
                unsigned vf[4];
                const unsigned off = (unsigned)((j * 16 + vrow) * 128) + ((db * 32u + vd2) ^ vswz);
                ldsm4t(vf, stb + 16384u + off);
                mma16816h(O[2 * db],     apf, &vf[0]);
                mma16816h(O[2 * db + 1], apf, &vf[2]);
            }
        }

        // ---- release slot ----
        if (lane == 0) mbar_arrive(ctrl + 32u + slot * 8u);
        if (tid == 0 && kt + 3 < nkt) {
            mbar_wait(ctrl + 32u + slot * 8u, (unsigned)((kt / 3) & 1));
            issue_kv(kt + 3);
        }
    }

    // ---- epilogue: ao -> fp16 single ----
    l0 += __shfl_xor_sync(0xFFFFFFFF, l0, 1);
    l0 += __shfl_xor_sync(0xFFFFFFFF, l0, 2);
    l1 += __shfl_xor_sync(0xFFFFFFFF, l1, 1);
    l1 += __shfl_xor_sync(0xFFFFFFFF, l1, 2);
    const float inv0 = 1.0f / l0, inv1 = 1.0f / l1;

    const int b = bh >> 4, h = bh & 15;
    const size_t r0 = (size_t)(b * Tn + qrow_g) * Cn;
    const size_t r1 = (size_t)(b * Tn + qrow_g + 8) * Cn;
#pragma unroll
    for (int ni = 0; ni < 8; ni++) {
        const int k = h * Dn + ni * 8 + 2 * tig;
        *(unsigned*)&g_aof[r0 + k] = packh2(O[ni][0] * inv0, O[ni][1] * inv0);
        *(unsigned*)&g_aof[r1 + k] = packh2(O[ni][2] * inv1, O[ni][3] * inv1);
    }
}

// ---------------- host ----------------
typedef CUresult (CUDAAPI* EncodeFn)(
    CUtensorMap*, CUtensorMapDataType, cuuint32_t, void*,
    const cuuint64_t*, const cuuint64_t*, const cuuint32_t*, const cuuint32_t*,
    CUtensorMapInterleave, CUtensorMapSwizzle, CUtensorMapL2promotion,
    CUtensorMapFloatOOBfill);

static void mk_map(EncodeFn enc, CUtensorMap* m, void* base, CUtensorMapDataType dt,
                   unsigned long long rows, unsigned long long cols,
                   unsigned boxc, unsigned boxr)
{
    cuuint64_t dims[2] = {cols, rows};
    cuuint64_t strides[1] = {cols * 2};
    cuuint32_t box[2] = {boxc, boxr};
    cuuint32_t es[2] = {1, 1};
    enc(m, dt, 2, base, dims, strides, box, es,
        CU_TENSOR_MAP_INTERLEAVE_NONE, CU_TENSOR_MAP_SWIZZLE_128B,
        CU_TENSOR_MAP_L2_PROMOTION_L2_128B, CU_TENSOR_MAP_FLOAT_OOB_FILL_NONE);
}

extern "C" void kernel_launch(void* const* d_in, const int* in_sizes, int n_in,
                              void* d_out, int out_size)
{
    const float* x     = (const float*)d_in[0];
    const float* w_qkv = (const float*)d_in[1];
    const float* w_out = (const float*)d_in[2];
    const float* b_out = (const float*)d_in[3];
    float* out = (float*)d_out;

    void *pXf, *pW1, *pW3, *pAo, *pQf, *pKf, *pVf;
    cudaGetSymbolAddress(&pXf, g_xf);
    cudaGetSymbolAddress(&pW1, g_w1f);
    cudaGetSymbolAddress(&pW3, g_w3f);
    cudaGetSymbolAddress(&pAo, g_aof);
    cudaGetSymbolAddress(&pQf, g_qf);
    cudaGetSymbolAddress(&pKf, g_kf);   cudaGetSymbolAddress(&pVf, g_vf);

    EncodeFn enc = nullptr;
    cudaDriverEntryPointQueryResult qr;
    cudaGetDriverEntryPointByVersion("cuTensorMapEncodeTiled", (void**)&enc,
                                     12000, cudaEnableDefault, &qr);

    const auto F16 = CU_TENSOR_MAP_DATA_TYPE_FLOAT16;
    const unsigned long long MR = (unsigned long long)Bn * Tn;        // 8192
    const unsigned long long KVR = (unsigned long long)Bn * Hn * Tn;  // 131072
    CUtensorMap mXf, mW1, mW3, mAo, mQf, mKf, mVf;
    mk_map(enc, &mXf, pXf, F16, MR, 1024, 64, 256);
    mk_map(enc, &mW1, pW1, F16, 3072, 1024, 64, 128);
    mk_map(enc, &mW3, pW3, F16, 1024, 1024, 64, 128);
    mk_map(enc, &mAo, pAo, F16, MR, 1024, 64, 256);
    mk_map(enc, &mQf, pQf, F16, KVR, 64, 64, 128);
    mk_map(enc, &mKf, pKf, F16, KVR, 64, 64, 128);
    mk_map(enc, &mVf, pVf, F16, KVR, 64, 64, 128);

    cudaFuncSetAttribute(gemm_tma<0>, cudaFuncAttributeMaxDynamicSharedMemorySize, GEMM_SMEM);
    cudaFuncSetAttribute(gemm_tma<1>, cudaFuncAttributeMaxDynamicSharedMemorySize, GEMM_SMEM);
    cudaFuncSetAttribute(attn_tma, cudaFuncAttributeMaxDynamicSharedMemorySize, ATTN_SMEM);

    tof16_all<<<6291456 / 256, 256>>>(x, w_qkv, w_out);
    gemm_tma<0><<<dim3(24, 32), 256, GEMM_SMEM>>>(mXf, mW1, nullptr, nullptr);
    attn_tma<<<dim3(Tn / 128, Bn * Hn), 256, ATTN_SMEM>>>(mQf, mKf, mVf);
    gemm_tma<1><<<dim3(8, 32), 256, GEMM_SMEM>>>(mAo, mW3, b_out, out);
}